// round 9
// baseline (speedup 1.0000x reference)
#include <cuda_runtime.h>
#include <cuda_bf16.h>
#include <cuda_fp16.h>
#include <cstdint>
#include <cstddef>
#include <math.h>

// Problem constants
#define B_   2
#define T_   4
#define NQ_  576
#define NK_  576
#define D_   1024
#define H_   16
#define DH_  64
#define TOK  (B_*T_*NQ_)
#define NEGBIG (-1.7014118e38f)
#define LOG2E 1.4426950408889634f

#define GK 1024
#define GN 1024

// Scratch (device globals; no dynamic allocation allowed)
__device__ int   g_mask_mode[2];
__device__ __nv_bfloat16 g_E[8 * NQ_ * NK_];
__device__ float2 g_rtq[TOK * 32];    // cos/sin table for q coords
__device__ float2 g_rtk[TOK * 32];    // cos/sin table for k coords

// fp16 operands
__device__ __half g_qhi[TOK * D_],  g_qlo[TOK * D_];
__device__ __half g_kvhi[TOK * D_], g_kvlo[TOK * D_];
__device__ __half g_yhi[TOK * D_],  g_ylo[TOK * D_];
__device__ __half g_Wqh[D_ * D_], g_Wkh[D_ * D_], g_Wvh[D_ * D_], g_Woh[D_ * D_];
__device__ __half g_V16[TOK * D_];

// attention operands (fp16): Q hi/lo (rope'd), K single (rope'd), V^T single
__device__ __half g_aQh[TOK * D_], g_aQl[TOK * D_];
__device__ __half g_aKr[TOK * D_];
__device__ __half g_vtr[128 * 64 * NK_];

// ---------------------------------------------------------------------------
// Family-portable PTX helpers
// ---------------------------------------------------------------------------
__device__ __forceinline__ uint32_t smem_u32(const void* p) {
    uint32_t a;
    asm("{ .reg .u64 t; cvta.to.shared.u64 t, %1; cvt.u32.u64 %0, t; }"
        : "=r"(a) : "l"(p));
    return a;
}
__device__ __forceinline__ void cp16(uint32_t s, const void* g) {
    asm volatile("cp.async.cg.shared.global [%0], [%1], 16;"
                 :: "r"(s), "l"(g) : "memory");
}
__device__ __forceinline__ void cp_commit() {
    asm volatile("cp.async.commit_group;" ::: "memory");
}
__device__ __forceinline__ void cp_wait1() {
    asm volatile("cp.async.wait_group 1;" ::: "memory");
}
__device__ __forceinline__ void cp_wait0() {
    asm volatile("cp.async.wait_group 0;" ::: "memory");
}
__device__ __forceinline__ void ldm_x4(uint32_t* r, uint32_t addr) {
    asm volatile("ldmatrix.sync.aligned.m8n8.x4.shared.b16 {%0,%1,%2,%3}, [%4];"
                 : "=r"(r[0]), "=r"(r[1]), "=r"(r[2]), "=r"(r[3]) : "r"(addr));
}
__device__ __forceinline__ void mma_f16(float* d, const uint32_t* a, const uint32_t* b) {
    asm volatile(
        "mma.sync.aligned.m16n8k16.row.col.f32.f16.f16.f32 "
        "{%0,%1,%2,%3}, {%4,%5,%6,%7}, {%8,%9}, {%0,%1,%2,%3};"
        : "+f"(d[0]), "+f"(d[1]), "+f"(d[2]), "+f"(d[3])
        : "r"(a[0]), "r"(a[1]), "r"(a[2]), "r"(a[3]), "r"(b[0]), "r"(b[1]));
}
__device__ __forceinline__ float ex2(float x) {
    float y;
    asm("ex2.approx.f32 %0, %1;" : "=f"(y) : "f"(x));
    return y;
}

// ---------------------------------------------------------------------------
// fp32 -> fp16 hi/lo split (activations)
// ---------------------------------------------------------------------------
__global__ void split_h_kernel(const float* __restrict__ x,
                               __half* __restrict__ hi,
                               __half* __restrict__ lo, int n4)
{
    int i = blockIdx.x * blockDim.x + threadIdx.x;
    if (i >= n4) return;
    float4 v = ((const float4*)x)[i];
    __half h0 = __float2half_rn(v.x);
    __half h1 = __float2half_rn(v.y);
    __half h2 = __float2half_rn(v.z);
    __half h3 = __float2half_rn(v.w);
    __half l0 = __float2half_rn(v.x - __half2float(h0));
    __half l1 = __float2half_rn(v.y - __half2float(h1));
    __half l2 = __float2half_rn(v.z - __half2float(h2));
    __half l3 = __float2half_rn(v.w - __half2float(h3));
    ((__half2*)hi)[2*i]   = __halves2half2(h0, h1);
    ((__half2*)hi)[2*i+1] = __halves2half2(h2, h3);
    ((__half2*)lo)[2*i]   = __halves2half2(l0, l1);
    ((__half2*)lo)[2*i+1] = __halves2half2(l2, l3);
}

// fp32 -> fp16 single rounding (weights)
__global__ void round_h_kernel(const float* __restrict__ x,
                               __half* __restrict__ h, int n4)
{
    int i = blockIdx.x * blockDim.x + threadIdx.x;
    if (i >= n4) return;
    float4 v = ((const float4*)x)[i];
    ((__half2*)h)[2*i]   = __floats2half2_rn(v.x, v.y);
    ((__half2*)h)[2*i+1] = __floats2half2_rn(v.z, v.w);
}

// ---------------------------------------------------------------------------
// RoPE cos/sin table: tab[tok][j] = (cos, sin) of 0.5*pi*coord[axis(j)]*freq
// ---------------------------------------------------------------------------
__global__ void ropetab_kernel(const float* __restrict__ coords,
                               const float* __restrict__ f0,
                               const float* __restrict__ f1,
                               const float* __restrict__ f2,
                               float2* __restrict__ tab)
{
    const int tok = blockIdx.x, tid = threadIdx.x;   // 32 threads
    float coord, fr;
    if (tid < 12)      { coord = coords[tok * 3 + 0]; fr = f0[tid]; }
    else if (tid < 22) { coord = coords[tok * 3 + 1]; fr = f1[tid - 12]; }
    else               { coord = coords[tok * 3 + 2]; fr = f2[tid - 22]; }
    float arg = 1.5707963267948966f * coord * fr;
    float s, c;
    sincosf(arg, &s, &c);
    tab[tok * 32 + tid] = make_float2(c, s);
}

// ---------------------------------------------------------------------------
// V transpose (fp16 in, fp16 out)
// ---------------------------------------------------------------------------
__global__ void vtsplit_kernel(const __half* __restrict__ V,
                               __half* __restrict__ vr)
{
    __shared__ __half t[32][33];
    const int k0 = blockIdx.x * 32, d0 = blockIdx.y * 32, f = blockIdx.z;
    const int tx = threadIdx.x & 31, ty = threadIdx.x >> 5;
    #pragma unroll
    for (int i = 0; i < 4; i++) {
        int key = k0 + ty + i * 8;
        t[ty + i * 8][tx] = V[(size_t)(f * NQ_ + key) * D_ + d0 + tx];
    }
    __syncthreads();
    #pragma unroll
    for (int i = 0; i < 4; i++) {
        int dd = ty + i * 8;
        int d = d0 + dd, h = d >> 6, dl = d & 63;
        size_t oi = ((size_t)(f * 16 + h) * 64 + dl) * NK_ + k0 + tx;
        vr[oi] = t[tx][dd];
    }
}

// ---------------------------------------------------------------------------
// Mask dtype detection
// ---------------------------------------------------------------------------
__global__ void detect_mask_kernel(const unsigned* __restrict__ qm,
                                   const unsigned* __restrict__ km, int nints)
{
    __shared__ int s_i, s_f;
    for (int b = 0; b < 2; b++) {
        if (threadIdx.x == 0) { s_i = 1; s_f = 1; }
        __syncthreads();
        const unsigned* p = b ? km : qm;
        int li = 1, lf = 1;
        for (int i = threadIdx.x; i < nints; i += blockDim.x) {
            unsigned v = p[i];
            if (v > 1u) li = 0;
            if (v != 0u && v != 0x3f800000u) lf = 0;
        }
        if (!li) atomicAnd(&s_i, 0);
        if (!lf) atomicAnd(&s_f, 0);
        __syncthreads();
        if (threadIdx.x == 0)
            g_mask_mode[b] = s_i ? 1 : (s_f ? 2 : 0);
        __syncthreads();
    }
}

__device__ __forceinline__ bool mask_at(const void* p, int i, int mode) {
    if (mode == 1) return ((const int*)p)[i] != 0;
    if (mode == 2) return ((const float*)p)[i] != 0.f;
    return ((const unsigned char*)p)[i] != 0;
}

// ---------------------------------------------------------------------------
// Fused bias precompute (raw masks, bf16 output)
// ---------------------------------------------------------------------------
__global__ void __launch_bounds__(576)
bias_kernel(const float* __restrict__ cq, const float* __restrict__ ck,
            const void* __restrict__ qmr, const void* __restrict__ kmr,
            __nv_bfloat16* __restrict__ E)
{
    __shared__ float ky[NK_], kx[NK_];
    __shared__ unsigned char kbad[NK_];
    __shared__ float qy8[8], qx8[8];
    __shared__ unsigned char qbad[8];
    const int f = blockIdx.y, k = threadIdx.x;
    const int ki = f * NK_ + k;
    const int mq = g_mask_mode[0], mk = g_mask_mode[1];
    ky[k]  = ck[ki * 3 + 1];
    kx[k]  = ck[ki * 3 + 2];
    kbad[k] = mask_at(kmr, ki, mk) ? 1 : 0;
    if (threadIdx.x < 8) {
        int q = blockIdx.x * 8 + threadIdx.x;
        int qi = f * NQ_ + q;
        qy8[threadIdx.x] = cq[qi * 3 + 1];
        qx8[threadIdx.x] = cq[qi * 3 + 2];
        qbad[threadIdx.x] = mask_at(qmr, qi, mq) ? 1 : 0;
    }
    __syncthreads();
    #pragma unroll
    for (int r = 0; r < 8; r++) {
        int q = blockIdx.x * 8 + r;
        float dy = qy8[r] - ky[k];
        float dx = qx8[r] - kx[k];
        float dist = sqrtf(dy * dy + dx * dx);
        bool bad = qbad[r] || kbad[k] || (dist > 0.5f);
        E[(size_t)(f * NQ_ + q) * NK_ + k] =
            __float2bfloat16(bad ? -3.0e38f : __expf(-10.f * dist));
    }
}

// ---------------------------------------------------------------------------
// HMMA GEMM, fp16 2-term split, fused epilogues.
// MODE 0: fp32 out (+bias)        [Wo]
// MODE 1: rope + fp16 hi/lo out   [Q]
// MODE 2: rope + fp16 out         [K]
// MODE 3: fp16 out                [V]
// ---------------------------------------------------------------------------
#define TILE_B 10240
#define STAGE  (3 * TILE_B)
#define NCH    32

template<int MODE>
__global__ void __launch_bounds__(128, 2)
gemm_mma(const __half* __restrict__ Ah, const __half* __restrict__ Al,
         const __half* __restrict__ Bh, const float* __restrict__ bias,
         float* __restrict__ C, __half* __restrict__ O1, __half* __restrict__ O2,
         const float2* __restrict__ rtab)
{
    extern __shared__ char dsm[];
    const uint32_t sbase = smem_u32(dsm);

    const int tid  = threadIdx.x;
    const int wid  = tid >> 5;
    const int lane = tid & 31;
    const int m0 = blockIdx.y * 128;
    const int n0 = blockIdx.x * 128;
    const int wm = (wid & 1) * 64;
    const int wn = (wid >> 1) * 64;

    float acc[4][8][4];
    #pragma unroll
    for (int mt = 0; mt < 4; mt++)
        #pragma unroll
        for (int nt = 0; nt < 8; nt++)
            #pragma unroll
            for (int r = 0; r < 4; r++) acc[mt][nt][r] = 0.f;

    int l_tl[12], l_row[12], l_c[12];
    #pragma unroll
    for (int j = 0; j < 12; j++) {
        int i = tid + j * 128;
        l_tl[j]  = i >> 9;
        l_row[j] = (i & 511) >> 2;
        l_c[j]   = i & 3;
    }

    auto issue_load = [&](int ch, int buf) {
        const int k0 = ch * 32;
        #pragma unroll
        for (int j = 0; j < 12; j++) {
            const __half* g;
            if (l_tl[j] == 2)      g = Bh + (size_t)(n0 + l_row[j]) * GK + k0 + l_c[j] * 8;
            else if (l_tl[j] == 1) g = Al + (size_t)(m0 + l_row[j]) * GK + k0 + l_c[j] * 8;
            else                   g = Ah + (size_t)(m0 + l_row[j]) * GK + k0 + l_c[j] * 8;
            uint32_t s = sbase + buf * STAGE + l_tl[j] * TILE_B
                       + l_row[j] * 80 + l_c[j] * 16;
            cp16(s, g);
        }
        cp_commit();
    };

    issue_load(0, 0);
    issue_load(1, 1);

    for (int ch = 0; ch < NCH; ch++) {
        if (ch == NCH - 1) cp_wait0(); else cp_wait1();
        __syncthreads();
        if (ch + 2 < NCH) issue_load(ch + 2, (ch + 2) % 3);

        const uint32_t hbase = sbase + (ch % 3) * STAGE;
        const uint32_t lbase = hbase + TILE_B;
        const uint32_t bbase = hbase + 2 * TILE_B;

        #pragma unroll
        for (int ks = 0; ks < 2; ks++) {
            uint32_t b[8][2];
            #pragma unroll
            for (int np = 0; np < 4; np++) {
                uint32_t addr = bbase
                    + (wn + np * 16 + (lane & 7) + ((lane >> 4) & 1) * 8) * 80
                    + ((lane >> 3) & 1) * 16 + ks * 32;
                uint32_t r[4];
                ldm_x4(r, addr);
                b[np * 2][0] = r[0];     b[np * 2][1] = r[1];
                b[np * 2 + 1][0] = r[2]; b[np * 2 + 1][1] = r[3];
            }
            uint32_t a[4][4];
            #pragma unroll
            for (int mt = 0; mt < 4; mt++) {
                uint32_t addr = hbase + (wm + mt * 16 + (lane & 15)) * 80
                              + (lane >> 4) * 16 + ks * 32;
                ldm_x4(a[mt], addr);
            }
            #pragma unroll
            for (int mt = 0; mt < 4; mt++)
                #pragma unroll
                for (int nt = 0; nt < 8; nt++)
                    mma_f16(acc[mt][nt], a[mt], b[nt]);
            #pragma unroll
            for (int mt = 0; mt < 4; mt++) {
                uint32_t addr = lbase + (wm + mt * 16 + (lane & 15)) * 80
                              + (lane >> 4) * 16 + ks * 32;
                ldm_x4(a[mt], addr);
            }
            #pragma unroll
            for (int mt = 0; mt < 4; mt++)
                #pragma unroll
                for (int nt = 0; nt < 8; nt++)
                    mma_f16(acc[mt][nt], a[mt], b[nt]);
        }
    }

    // Stage rope table for this m-tile into (now free) smem.
    float2* st = (float2*)dsm;
    if (MODE == 1 || MODE == 2) {
        __syncthreads();
        for (int i = tid; i < 128 * 32; i += 128)
            st[i] = rtab[(size_t)(m0 + (i >> 5)) * 32 + (i & 31)];
        __syncthreads();
    }

    const int cb_loc = wn + (lane & 3) * 2;
    const int cbase = n0 + cb_loc;
    float bv[8][2];
    #pragma unroll
    for (int nt = 0; nt < 8; nt++) {
        bv[nt][0] = bias[cbase + nt * 8];
        bv[nt][1] = bias[cbase + nt * 8 + 1];
    }

    #pragma unroll
    for (int mt = 0; mt < 4; mt++) {
        int rl0 = wm + mt * 16 + (lane >> 2);
        #pragma unroll
        for (int nt = 0; nt < 8; nt++) {
            int col = cbase + nt * 8;
            float v0 = acc[mt][nt][0] + bv[nt][0];
            float v1 = acc[mt][nt][1] + bv[nt][1];
            float v2 = acc[mt][nt][2] + bv[nt][0];
            float v3 = acc[mt][nt][3] + bv[nt][1];
            if (MODE == 0) {
                *(float2*)&C[(size_t)(m0 + rl0) * GN + col]     = make_float2(v0, v1);
                *(float2*)&C[(size_t)(m0 + rl0 + 8) * GN + col] = make_float2(v2, v3);
            } else if (MODE == 3) {
                ((__half2*)O1)[((size_t)(m0 + rl0) * D_ + col) >> 1]     = __floats2half2_rn(v0, v1);
                ((__half2*)O1)[((size_t)(m0 + rl0 + 8) * D_ + col) >> 1] = __floats2half2_rn(v2, v3);
            } else {
                int j = ((cb_loc + nt * 8) & 63) >> 1;
                float2 cs0 = st[rl0 * 32 + j];
                float2 cs1 = st[(rl0 + 8) * 32 + j];
                float y0 = v0 * cs0.x - v1 * cs0.y;
                float y1 = v1 * cs0.x + v0 * cs0.y;
                float y2 = v2 * cs1.x - v3 * cs1.y;
                float y3 = v3 * cs1.x + v2 * cs1.y;
                size_t e0 = ((size_t)(m0 + rl0) * D_ + col) >> 1;
                size_t e1 = ((size_t)(m0 + rl0 + 8) * D_ + col) >> 1;
                __half2 h0 = __floats2half2_rn(y0, y1);
                __half2 h1 = __floats2half2_rn(y2, y3);
                ((__half2*)O1)[e0] = h0;
                ((__half2*)O1)[e1] = h1;
                if (MODE == 1) {
                    ((__half2*)O2)[e0] = __floats2half2_rn(
                        y0 - __half2float(__low2half(h0)), y1 - __half2float(__high2half(h0)));
                    ((__half2*)O2)[e1] = __floats2half2_rn(
                        y2 - __half2float(__low2half(h1)), y3 - __half2float(__high2half(h1)));
                }
            }
        }
    }
}

// ---------------------------------------------------------------------------
// HMMA flash attention, fp16 2-pass (unchanged from round 8)
// ---------------------------------------------------------------------------
#define ATT_SMEM 27648

__global__ void __launch_bounds__(128)
attn_mma(const __half* __restrict__ Qh, const __half* __restrict__ Ql,
         const __half* __restrict__ Kr, const __half* __restrict__ Vtr,
         const __nv_bfloat16* __restrict__ E, const float* __restrict__ alpha,
         __half* __restrict__ Yh, __half* __restrict__ Yl)
{
    extern __shared__ char sm[];
    uint32_t* sK = (uint32_t*)sm;
    uint32_t* sV = (uint32_t*)(sm + 9216);
    __nv_bfloat16* sE = (__nv_bfloat16*)(sm + 18432);

    const int tid = threadIdx.x;
    const int w = tid >> 5, lane = tid & 31;
    const int c = lane & 3, rg = lane >> 2;
    const int qb = blockIdx.x, fh = blockIdx.y;
    const int f = fh >> 4, h = fh & 15;
    const int tok0 = f * NQ_;
    const int q0 = qb * 64;
    const float alph = alpha[h];
    const int rl = 16 * w + rg;

    for (int i = tid; i < 512; i += 128) {
        int row = i >> 3, c16 = i & 7;
        size_t go = (size_t)(tok0 + q0 + row) * D_ + h * 64 + c16 * 8;
        *(uint4*)(sK + row * 36 + c16 * 4) = *(const uint4*)(Qh + go);
        *(uint4*)(sV + row * 36 + c16 * 4) = *(const uint4*)(Ql + go);
    }
    __syncthreads();
    uint32_t qhF[4][4], qlF[4][4];
    #pragma unroll
    for (int s = 0; s < 4; s++) {
        qhF[s][0] = sK[rl * 36 + 8 * s + c];
        qhF[s][1] = sK[(rl + 8) * 36 + 8 * s + c];
        qhF[s][2] = sK[rl * 36 + 8 * s + c + 4];
        qhF[s][3] = sK[(rl + 8) * 36 + 8 * s + c + 4];
        qlF[s][0] = sV[rl * 36 + 8 * s + c];
        qlF[s][1] = sV[(rl + 8) * 36 + 8 * s + c];
        qlF[s][2] = sV[rl * 36 + 8 * s + c + 4];
        qlF[s][3] = sV[(rl + 8) * 36 + 8 * s + c + 4];
    }
    __syncthreads();

    float o[8][4];
    #pragma unroll
    for (int n = 0; n < 8; n++)
        #pragma unroll
        for (int r = 0; r < 4; r++) o[n][r] = 0.f;
    float m0r = -3.0e38f, m1r = -3.0e38f, l0r = 0.f, l1r = 0.f;

    for (int kt = 0; kt < 9; kt++) {
        const int k0 = kt * 64;
        for (int i = tid; i < 512; i += 128) {
            int row = i >> 3, c16 = i & 7;
            size_t go = (size_t)(tok0 + k0 + row) * D_ + h * 64 + c16 * 8;
            *(uint4*)(sK + row * 36 + c16 * 4) = *(const uint4*)(Kr + go);
            size_t vo = (size_t)fh * (64 * NK_) + (size_t)row * NK_ + k0 + c16 * 8;
            *(uint4*)(sV + row * 36 + c16 * 4) = *(const uint4*)(Vtr + vo);
        }
        for (int i = tid; i < 512; i += 128) {
            int row = i >> 3, c8 = i & 7;
            *(uint4*)(sE + row * 72 + c8 * 8) =
                *(const uint4*)(E + (size_t)(tok0 + q0 + row) * NK_ + k0 + c8 * 8);
        }
        __syncthreads();

        float s[8][4];
        #pragma unroll
        for (int n = 0; n < 8; n++)
            #pragma unroll
            for (int r = 0; r < 4; r++) s[n][r] = 0.f;
        #pragma unroll
        for (int st = 0; st < 4; st++) {
            #pragma unroll
            for (int n = 0; n < 8; n++) {
                int bi = (8 * n + rg) * 36 + 8 * st + c;
                uint32_t bh[2] = { sK[bi], sK[bi + 4] };
                mma_f16(s[n], qhF[st], bh);
                mma_f16(s[n], qlF[st], bh);
            }
        }

        float mn0 = m0r, mn1 = m1r;
        #pragma unroll
        for (int n = 0; n < 8; n++) {
            float2 e0 = __bfloat1622float2(
                *(__nv_bfloat162*)(sE + rl * 72 + 8 * n + 2 * c));
            float2 e1 = __bfloat1622float2(
                *(__nv_bfloat162*)(sE + (rl + 8) * 72 + 8 * n + 2 * c));
            s[n][0] = (e0.x < 0.f) ? NEGBIG : fmaf(s[n][0], 0.125f, alph * e0.x);
            s[n][1] = (e0.y < 0.f) ? NEGBIG : fmaf(s[n][1], 0.125f, alph * e0.y);
            s[n][2] = (e1.x < 0.f) ? NEGBIG : fmaf(s[n][2], 0.125f, alph * e1.x);
            s[n][3] = (e1.y < 0.f) ? NEGBIG : fmaf(s[n][3], 0.125f, alph * e1.y);
            mn0 = fmaxf(mn0, fmaxf(s[n][0], s[n][1]));
            mn1 = fmaxf(mn1, fmaxf(s[n][2], s[n][3]));
        }
        mn0 = fmaxf(mn0, __shfl_xor_sync(0xffffffffu, mn0, 1));
        mn0 = fmaxf(mn0, __shfl_xor_sync(0xffffffffu, mn0, 2));
        mn1 = fmaxf(mn1, __shfl_xor_sync(0xffffffffu, mn1, 1));
        mn1 = fmaxf(mn1, __shfl_xor_sync(0xffffffffu, mn1, 2));
        float f0 = ex2((m0r - mn0) * LOG2E);
        float f1 = ex2((m1r - mn1) * LOG2E);
        m0r = mn0; m1r = mn1;

        float rs0 = 0.f, rs1 = 0.f;
        uint32_t phL[8], phH[8], plL[8], plH[8];
        #pragma unroll
        for (int n = 0; n < 8; n++) {
            float p0 = ex2((s[n][0] - mn0) * LOG2E);
            float p1 = ex2((s[n][1] - mn0) * LOG2E);
            float p2 = ex2((s[n][2] - mn1) * LOG2E);
            float p3 = ex2((s[n][3] - mn1) * LOG2E);
            rs0 += p0 + p1;
            rs1 += p2 + p3;
            o[n][0] *= f0; o[n][1] *= f0; o[n][2] *= f1; o[n][3] *= f1;
            __half2 bL = __floats2half2_rn(p0, p1);
            phL[n] = *(uint32_t*)&bL;
            __half2 rL = __floats2half2_rn(p0 - __half2float(__low2half(bL)),
                                           p1 - __half2float(__high2half(bL)));
            plL[n] = *(uint32_t*)&rL;
            __half2 bH = __floats2half2_rn(p2, p3);
            phH[n] = *(uint32_t*)&bH;
            __half2 rH = __floats2half2_rn(p2 - __half2float(__low2half(bH)),
                                           p3 - __half2float(__high2half(bH)));
            plH[n] = *(uint32_t*)&rH;
        }
        rs0 += __shfl_xor_sync(0xffffffffu, rs0, 1);
        rs0 += __shfl_xor_sync(0xffffffffu, rs0, 2);
        rs1 += __shfl_xor_sync(0xffffffffu, rs1, 1);
        rs1 += __shfl_xor_sync(0xffffffffu, rs1, 2);
        l0r = l0r * f0 + rs0;
        l1r = l1r * f1 + rs1;

        #pragma unroll
        for (int st = 0; st < 4; st++) {
            uint32_t ah[4] = { phL[2 * st], phH[2 * st], phL[2 * st + 1], phH[2 * st + 1] };
            uint32_t al[4] = { plL[2 * st], plH[2 * st], plL[2 * st + 1], plH[2 * st + 1] };
            #pragma unroll
            for (int n = 0; n < 8; n++) {
                int bi = (8 * n + rg) * 36 + 8 * st + c;
                uint32_t vh[2] = { sV[bi], sV[bi + 4] };
                mma_f16(o[n], ah, vh);
                mma_f16(o[n], al, vh);
            }
        }
        __syncthreads();
    }

    float i0 = 1.f / l0r, i1 = 1.f / l1r;
    #pragma unroll
    for (int n = 0; n < 8; n++) {
        size_t e0 = ((size_t)(tok0 + q0 + rl) * D_ + h * 64 + 8 * n + 2 * c) >> 1;
        size_t e1 = ((size_t)(tok0 + q0 + rl + 8) * D_ + h * 64 + 8 * n + 2 * c) >> 1;
        float2 w0 = { o[n][0] * i0, o[n][1] * i0 };
        float2 w1 = { o[n][2] * i1, o[n][3] * i1 };
        __half2 h0 = __floats2half2_rn(w0.x, w0.y);
        __half2 l0v = __floats2half2_rn(w0.x - __half2float(__low2half(h0)),
                                        w0.y - __half2float(__high2half(h0)));
        __half2 h1 = __floats2half2_rn(w1.x, w1.y);
        __half2 l1v = __floats2half2_rn(w1.x - __half2float(__low2half(h1)),
                                        w1.y - __half2float(__high2half(h1)));
        ((__half2*)Yh)[e0] = h0;
        ((__half2*)Yl)[e0] = l0v;
        ((__half2*)Yh)[e1] = h1;
        ((__half2*)Yl)[e1] = l1v;
    }
}

// ---------------------------------------------------------------------------
extern "C" void kernel_launch(void* const* d_in, const int* in_sizes, int n_in,
                              void* d_out, int out_size)
{
    (void)in_sizes; (void)n_in; (void)out_size;

    const float*   q_tokens  = (const float*)d_in[0];
    const float*   kv_tokens = (const float*)d_in[1];
    const float*   coords_q  = (const float*)d_in[2];
    const float*   coords_k  = (const float*)d_in[3];
    const void*    q_pad     = d_in[4];
    const void*    kv_pad    = d_in[5];
    const float*   Wq = (const float*)d_in[6];
    const float*   bq = (const float*)d_in[7];
    const float*   Wk = (const float*)d_in[8];
    const float*   bk = (const float*)d_in[9];
    const float*   Wv = (const float*)d_in[10];
    const float*   bv = (const float*)d_in[11];
    const float*   Wo = (const float*)d_in[12];
    const float*   bo = (const float*)d_in[13];
    const float*   alpha = (const float*)d_in[14];
    const float*   f0 = (const float*)d_in[15];
    const float*   f1 = (const float*)d_in[16];
    const float*   f2 = (const float*)d_in[17];
    float* out = (float*)d_out;

    __nv_bfloat16 *Eb;
    float2 *rtq, *rtk;
    cudaGetSymbolAddress((void**)&Eb, g_E);
    cudaGetSymbolAddress((void**)&rtq, g_rtq);
    cudaGetSymbolAddress((void**)&rtk, g_rtk);

    __half *qhi, *qlo, *kvhi, *kvlo, *yhi, *ylo, *Wqh, *Wkh, *Wvh, *Woh, *V16;
    __half *aQh, *aQl, *aKr, *vtr;
    cudaGetSymbolAddress((void**)&qhi,  g_qhi);  cudaGetSymbolAddress((void**)&qlo,  g_qlo);
    cudaGetSymbolAddress((void**)&kvhi, g_kvhi); cudaGetSymbolAddress((void**)&kvlo, g_kvlo);
    cudaGetSymbolAddress((void**)&yhi,  g_yhi);  cudaGetSymbolAddress((void**)&ylo,  g_ylo);
    cudaGetSymbolAddress((void**)&Wqh, g_Wqh);   cudaGetSymbolAddress((void**)&Wkh, g_Wkh);
    cudaGetSymbolAddress((void**)&Wvh, g_Wvh);   cudaGetSymbolAddress((void**)&Woh, g_Woh);
    cudaGetSymbolAddress((void**)&V16, g_V16);
    cudaGetSymbolAddress((void**)&aQh, g_aQh);   cudaGetSymbolAddress((void**)&aQl, g_aQl);
    cudaGetSymbolAddress((void**)&aKr, g_aKr);   cudaGetSymbolAddress((void**)&vtr, g_vtr);

    const int gemm_smem = 3 * STAGE;  // 92160
    cudaFuncSetAttribute(gemm_mma<0>, cudaFuncAttributeMaxDynamicSharedMemorySize, gemm_smem);
    cudaFuncSetAttribute(gemm_mma<1>, cudaFuncAttributeMaxDynamicSharedMemorySize, gemm_smem);
    cudaFuncSetAttribute(gemm_mma<2>, cudaFuncAttributeMaxDynamicSharedMemorySize, gemm_smem);
    cudaFuncSetAttribute(gemm_mma<3>, cudaFuncAttributeMaxDynamicSharedMemorySize, gemm_smem);
    cudaFuncSetAttribute(attn_mma, cudaFuncAttributeMaxDynamicSharedMemorySize, ATT_SMEM);

    // masks + fused bias + rope tables
    detect_mask_kernel<<<1, 256>>>((const unsigned*)q_pad, (const unsigned*)kv_pad,
                                   TOK / 4);
    bias_kernel<<<dim3(NQ_ / 8, 8), NK_>>>(coords_q, coords_k, q_pad, kv_pad, Eb);
    ropetab_kernel<<<TOK, 32>>>(coords_q, f0, f1, f2, rtq);
    ropetab_kernel<<<TOK, 32>>>(coords_k, f0, f1, f2, rtk);

    // fp16 splits: activations hi/lo, weights single-rounded
    const int ntok4 = TOK * D_ / 4, nw4 = D_ * D_ / 4;
    split_h_kernel<<<(ntok4 + 255) / 256, 256>>>(q_tokens,  qhi,  qlo,  ntok4);
    split_h_kernel<<<(ntok4 + 255) / 256, 256>>>(kv_tokens, kvhi, kvlo, ntok4);
    round_h_kernel<<<(nw4 + 255) / 256, 256>>>(Wq, Wqh, nw4);
    round_h_kernel<<<(nw4 + 255) / 256, 256>>>(Wk, Wkh, nw4);
    round_h_kernel<<<(nw4 + 255) / 256, 256>>>(Wv, Wvh, nw4);
    round_h_kernel<<<(nw4 + 255) / 256, 256>>>(Wo, Woh, nw4);

    dim3 gg(GN / 128, TOK / 128);
    // Q: rope + fp16 hi/lo;  K: rope + fp16;  V: fp16
    gemm_mma<1><<<gg, 128, gemm_smem>>>(qhi,  qlo,  Wqh, bq, nullptr, aQh, aQl, rtq);
    gemm_mma<2><<<gg, 128, gemm_smem>>>(kvhi, kvlo, Wkh, bk, nullptr, aKr, nullptr, rtk);
    gemm_mma<3><<<gg, 128, gemm_smem>>>(kvhi, kvlo, Wvh, bv, nullptr, V16, nullptr, nullptr);

    vtsplit_kernel<<<dim3(NK_ / 32, D_ / 32, 8), 256>>>(V16, vtr);

    attn_mma<<<dim3(9, 128), 128, ATT_SMEM>>>(aQh, aQl, aKr, vtr,
                                              Eb, alpha, yhi, ylo);

    gemm_mma<0><<<gg, 128, gemm_smem>>>(yhi, ylo, Woh, bo, out, nullptr, nullptr, nullptr);
}

// round 10
// speedup vs baseline: 1.1702x; 1.1702x over previous
#include <cuda_runtime.h>
#include <cuda_bf16.h>
#include <cuda_fp16.h>
#include <cstdint>
#include <cstddef>
#include <math.h>

// Problem constants
#define B_   2
#define T_   4
#define NQ_  576
#define NK_  576
#define D_   1024
#define H_   16
#define DH_  64
#define TOK  (B_*T_*NQ_)
#define NEGBIG (-1.7014118e38f)
#define LOG2E 1.4426950408889634f

#define GK 1024
#define GN 1024

// Scratch (device globals; no dynamic allocation allowed)
__device__ int   g_mask_mode[2];
__device__ __nv_bfloat16 g_E[8 * NQ_ * NK_];
__device__ float2 g_rtq[TOK * 32];
__device__ float2 g_rtk[TOK * 32];

// fp16 operands
__device__ __half g_qhi[TOK * D_],  g_qlo[TOK * D_];
__device__ __half g_kvhi[TOK * D_], g_kvlo[TOK * D_];
__device__ __half g_yhi[TOK * D_];
__device__ __half g_Wqh[D_ * D_], g_Wkh[D_ * D_], g_Wvh[D_ * D_], g_Woh[D_ * D_];
__device__ __half g_V16[TOK * D_];

// attention operands (fp16): Q hi/lo (rope'd), K single (rope'd), V^T single
__device__ __half g_aQh[TOK * D_], g_aQl[TOK * D_];
__device__ __half g_aKr[TOK * D_];
__device__ __half g_vtr[128 * 64 * NK_];

// ---------------------------------------------------------------------------
// Family-portable PTX helpers
// ---------------------------------------------------------------------------
__device__ __forceinline__ uint32_t smem_u32(const void* p) {
    uint32_t a;
    asm("{ .reg .u64 t; cvta.to.shared.u64 t, %1; cvt.u32.u64 %0, t; }"
        : "=r"(a) : "l"(p));
    return a;
}
__device__ __forceinline__ void cp16(uint32_t s, const void* g) {
    asm volatile("cp.async.cg.shared.global [%0], [%1], 16;"
                 :: "r"(s), "l"(g) : "memory");
}
__device__ __forceinline__ void cp_commit() {
    asm volatile("cp.async.commit_group;" ::: "memory");
}
__device__ __forceinline__ void cp_wait1() {
    asm volatile("cp.async.wait_group 1;" ::: "memory");
}
__device__ __forceinline__ void cp_wait0() {
    asm volatile("cp.async.wait_group 0;" ::: "memory");
}
__device__ __forceinline__ void ldm_x4(uint32_t* r, uint32_t addr) {
    asm volatile("ldmatrix.sync.aligned.m8n8.x4.shared.b16 {%0,%1,%2,%3}, [%4];"
                 : "=r"(r[0]), "=r"(r[1]), "=r"(r[2]), "=r"(r[3]) : "r"(addr));
}
__device__ __forceinline__ void mma_f16(float* d, const uint32_t* a, const uint32_t* b) {
    asm volatile(
        "mma.sync.aligned.m16n8k16.row.col.f32.f16.f16.f32 "
        "{%0,%1,%2,%3}, {%4,%5,%6,%7}, {%8,%9}, {%0,%1,%2,%3};"
        : "+f"(d[0]), "+f"(d[1]), "+f"(d[2]), "+f"(d[3])
        : "r"(a[0]), "r"(a[1]), "r"(a[2]), "r"(a[3]), "r"(b[0]), "r"(b[1]));
}
__device__ __forceinline__ float ex2(float x) {
    float y;
    asm("ex2.approx.f32 %0, %1;" : "=f"(y) : "f"(x));
    return y;
}

// ---------------------------------------------------------------------------
// fp32 -> fp16 hi/lo split (activations)
// ---------------------------------------------------------------------------
__global__ void split_h_kernel(const float* __restrict__ x,
                               __half* __restrict__ hi,
                               __half* __restrict__ lo, int n4)
{
    int i = blockIdx.x * blockDim.x + threadIdx.x;
    if (i >= n4) return;
    float4 v = ((const float4*)x)[i];
    __half h0 = __float2half_rn(v.x);
    __half h1 = __float2half_rn(v.y);
    __half h2 = __float2half_rn(v.z);
    __half h3 = __float2half_rn(v.w);
    __half l0 = __float2half_rn(v.x - __half2float(h0));
    __half l1 = __float2half_rn(v.y - __half2float(h1));
    __half l2 = __float2half_rn(v.z - __half2float(h2));
    __half l3 = __float2half_rn(v.w - __half2float(h3));
    ((__half2*)hi)[2*i]   = __halves2half2(h0, h1);
    ((__half2*)hi)[2*i+1] = __halves2half2(h2, h3);
    ((__half2*)lo)[2*i]   = __halves2half2(l0, l1);
    ((__half2*)lo)[2*i+1] = __halves2half2(l2, l3);
}

// fp32 -> fp16 single rounding (weights)
__global__ void round_h_kernel(const float* __restrict__ x,
                               __half* __restrict__ h, int n4)
{
    int i = blockIdx.x * blockDim.x + threadIdx.x;
    if (i >= n4) return;
    float4 v = ((const float4*)x)[i];
    ((__half2*)h)[2*i]   = __floats2half2_rn(v.x, v.y);
    ((__half2*)h)[2*i+1] = __floats2half2_rn(v.z, v.w);
}

// ---------------------------------------------------------------------------
// RoPE cos/sin table
// ---------------------------------------------------------------------------
__global__ void ropetab_kernel(const float* __restrict__ coords,
                               const float* __restrict__ f0,
                               const float* __restrict__ f1,
                               const float* __restrict__ f2,
                               float2* __restrict__ tab)
{
    const int tok = blockIdx.x, tid = threadIdx.x;
    float coord, fr;
    if (tid < 12)      { coord = coords[tok * 3 + 0]; fr = f0[tid]; }
    else if (tid < 22) { coord = coords[tok * 3 + 1]; fr = f1[tid - 12]; }
    else               { coord = coords[tok * 3 + 2]; fr = f2[tid - 22]; }
    float arg = 1.5707963267948966f * coord * fr;
    float s, c;
    sincosf(arg, &s, &c);
    tab[tok * 32 + tid] = make_float2(c, s);
}

// ---------------------------------------------------------------------------
// V transpose (fp16 in, fp16 out)
// ---------------------------------------------------------------------------
__global__ void vtsplit_kernel(const __half* __restrict__ V,
                               __half* __restrict__ vr)
{
    __shared__ __half t[32][33];
    const int k0 = blockIdx.x * 32, d0 = blockIdx.y * 32, f = blockIdx.z;
    const int tx = threadIdx.x & 31, ty = threadIdx.x >> 5;
    #pragma unroll
    for (int i = 0; i < 4; i++) {
        int key = k0 + ty + i * 8;
        t[ty + i * 8][tx] = V[(size_t)(f * NQ_ + key) * D_ + d0 + tx];
    }
    __syncthreads();
    #pragma unroll
    for (int i = 0; i < 4; i++) {
        int dd = ty + i * 8;
        int d = d0 + dd, h = d >> 6, dl = d & 63;
        size_t oi = ((size_t)(f * 16 + h) * 64 + dl) * NK_ + k0 + tx;
        vr[oi] = t[tx][dd];
    }
}

// ---------------------------------------------------------------------------
// Mask dtype detection
// ---------------------------------------------------------------------------
__global__ void detect_mask_kernel(const unsigned* __restrict__ qm,
                                   const unsigned* __restrict__ km, int nints)
{
    __shared__ int s_i, s_f;
    for (int b = 0; b < 2; b++) {
        if (threadIdx.x == 0) { s_i = 1; s_f = 1; }
        __syncthreads();
        const unsigned* p = b ? km : qm;
        int li = 1, lf = 1;
        for (int i = threadIdx.x; i < nints; i += blockDim.x) {
            unsigned v = p[i];
            if (v > 1u) li = 0;
            if (v != 0u && v != 0x3f800000u) lf = 0;
        }
        if (!li) atomicAnd(&s_i, 0);
        if (!lf) atomicAnd(&s_f, 0);
        __syncthreads();
        if (threadIdx.x == 0)
            g_mask_mode[b] = s_i ? 1 : (s_f ? 2 : 0);
        __syncthreads();
    }
}

__device__ __forceinline__ bool mask_at(const void* p, int i, int mode) {
    if (mode == 1) return ((const int*)p)[i] != 0;
    if (mode == 2) return ((const float*)p)[i] != 0.f;
    return ((const unsigned char*)p)[i] != 0;
}

// ---------------------------------------------------------------------------
// Fused bias precompute (raw masks, bf16 output)
// ---------------------------------------------------------------------------
__global__ void __launch_bounds__(576)
bias_kernel(const float* __restrict__ cq, const float* __restrict__ ck,
            const void* __restrict__ qmr, const void* __restrict__ kmr,
            __nv_bfloat16* __restrict__ E)
{
    __shared__ float ky[NK_], kx[NK_];
    __shared__ unsigned char kbad[NK_];
    __shared__ float qy8[8], qx8[8];
    __shared__ unsigned char qbad[8];
    const int f = blockIdx.y, k = threadIdx.x;
    const int ki = f * NK_ + k;
    const int mq = g_mask_mode[0], mk = g_mask_mode[1];
    ky[k]  = ck[ki * 3 + 1];
    kx[k]  = ck[ki * 3 + 2];
    kbad[k] = mask_at(kmr, ki, mk) ? 1 : 0;
    if (threadIdx.x < 8) {
        int q = blockIdx.x * 8 + threadIdx.x;
        int qi = f * NQ_ + q;
        qy8[threadIdx.x] = cq[qi * 3 + 1];
        qx8[threadIdx.x] = cq[qi * 3 + 2];
        qbad[threadIdx.x] = mask_at(qmr, qi, mq) ? 1 : 0;
    }
    __syncthreads();
    #pragma unroll
    for (int r = 0; r < 8; r++) {
        int q = blockIdx.x * 8 + r;
        float dy = qy8[r] - ky[k];
        float dx = qx8[r] - kx[k];
        float dist = sqrtf(dy * dy + dx * dx);
        bool bad = qbad[r] || kbad[k] || (dist > 0.5f);
        E[(size_t)(f * NQ_ + q) * NK_ + k] =
            __float2bfloat16(bad ? -3.0e38f : __expf(-10.f * dist));
    }
}

// ---------------------------------------------------------------------------
// HMMA GEMM, templated on epilogue MODE and split passes NPASS.
// MODE 0: fp32 out (+bias)        [Wo]
// MODE 1: rope + fp16 hi/lo out   [Q]
// MODE 2: rope + fp16 out         [K]
// MODE 3: fp16 out                [V]
// NPASS 2: C = (Ahi+Alo) B^T ;  NPASS 1: C = Ahi B^T
// ---------------------------------------------------------------------------
#define TILE_B 10240
#define NCH    32

template<int MODE, int NPASS>
__global__ void __launch_bounds__(128, 2)
gemm_mma(const __half* __restrict__ Ah, const __half* __restrict__ Al,
         const __half* __restrict__ Bh, const float* __restrict__ bias,
         float* __restrict__ C, __half* __restrict__ O1, __half* __restrict__ O2,
         const float2* __restrict__ rtab)
{
    constexpr int NTILES = NPASS + 1;
    constexpr int STG = NTILES * TILE_B;
    constexpr int NSLOT = NTILES * 4;

    extern __shared__ char dsm[];
    const uint32_t sbase = smem_u32(dsm);

    const int tid  = threadIdx.x;
    const int wid  = tid >> 5;
    const int lane = tid & 31;
    const int m0 = blockIdx.y * 128;
    const int n0 = blockIdx.x * 128;
    const int wm = (wid & 1) * 64;
    const int wn = (wid >> 1) * 64;

    float acc[4][8][4];
    #pragma unroll
    for (int mt = 0; mt < 4; mt++)
        #pragma unroll
        for (int nt = 0; nt < 8; nt++)
            #pragma unroll
            for (int r = 0; r < 4; r++) acc[mt][nt][r] = 0.f;

    int l_tl[NSLOT], l_row[NSLOT], l_c[NSLOT];
    #pragma unroll
    for (int j = 0; j < NSLOT; j++) {
        int i = tid + j * 128;
        l_tl[j]  = i >> 9;
        l_row[j] = (i & 511) >> 2;
        l_c[j]   = i & 3;
    }

    auto issue_load = [&](int ch, int buf) {
        const int k0 = ch * 32;
        #pragma unroll
        for (int j = 0; j < NSLOT; j++) {
            const __half* g;
            if (l_tl[j] == NTILES - 1)
                g = Bh + (size_t)(n0 + l_row[j]) * GK + k0 + l_c[j] * 8;
            else if (NPASS == 2 && l_tl[j] == 1)
                g = Al + (size_t)(m0 + l_row[j]) * GK + k0 + l_c[j] * 8;
            else
                g = Ah + (size_t)(m0 + l_row[j]) * GK + k0 + l_c[j] * 8;
            uint32_t s = sbase + buf * STG + l_tl[j] * TILE_B
                       + l_row[j] * 80 + l_c[j] * 16;
            cp16(s, g);
        }
        cp_commit();
    };

    issue_load(0, 0);
    issue_load(1, 1);

    for (int ch = 0; ch < NCH; ch++) {
        if (ch == NCH - 1) cp_wait0(); else cp_wait1();
        __syncthreads();
        if (ch + 2 < NCH) issue_load(ch + 2, (ch + 2) % 3);

        const uint32_t hbase = sbase + (ch % 3) * STG;
        const uint32_t bbase = hbase + (NTILES - 1) * TILE_B;

        #pragma unroll
        for (int ks = 0; ks < 2; ks++) {
            uint32_t b[8][2];
            #pragma unroll
            for (int np = 0; np < 4; np++) {
                uint32_t addr = bbase
                    + (wn + np * 16 + (lane & 7) + ((lane >> 4) & 1) * 8) * 80
                    + ((lane >> 3) & 1) * 16 + ks * 32;
                uint32_t r[4];
                ldm_x4(r, addr);
                b[np * 2][0] = r[0];     b[np * 2][1] = r[1];
                b[np * 2 + 1][0] = r[2]; b[np * 2 + 1][1] = r[3];
            }
            uint32_t a[4][4];
            #pragma unroll
            for (int mt = 0; mt < 4; mt++) {
                uint32_t addr = hbase + (wm + mt * 16 + (lane & 15)) * 80
                              + (lane >> 4) * 16 + ks * 32;
                ldm_x4(a[mt], addr);
            }
            #pragma unroll
            for (int mt = 0; mt < 4; mt++)
                #pragma unroll
                for (int nt = 0; nt < 8; nt++)
                    mma_f16(acc[mt][nt], a[mt], b[nt]);
            if (NPASS == 2) {
                #pragma unroll
                for (int mt = 0; mt < 4; mt++) {
                    uint32_t addr = hbase + TILE_B
                                  + (wm + mt * 16 + (lane & 15)) * 80
                                  + (lane >> 4) * 16 + ks * 32;
                    ldm_x4(a[mt], addr);
                }
                #pragma unroll
                for (int mt = 0; mt < 4; mt++)
                    #pragma unroll
                    for (int nt = 0; nt < 8; nt++)
                        mma_f16(acc[mt][nt], a[mt], b[nt]);
            }
        }
    }

    // Stage rope table for this m-tile into (now free) smem.
    float2* st = (float2*)dsm;
    if (MODE == 1 || MODE == 2) {
        __syncthreads();
        for (int i = tid; i < 128 * 32; i += 128)
            st[i] = rtab[(size_t)(m0 + (i >> 5)) * 32 + (i & 31)];
        __syncthreads();
    }

    const int cb_loc = wn + (lane & 3) * 2;
    const int cbase = n0 + cb_loc;
    float bv[8][2];
    #pragma unroll
    for (int nt = 0; nt < 8; nt++) {
        bv[nt][0] = bias[cbase + nt * 8];
        bv[nt][1] = bias[cbase + nt * 8 + 1];
    }

    #pragma unroll
    for (int mt = 0; mt < 4; mt++) {
        int rl0 = wm + mt * 16 + (lane >> 2);
        #pragma unroll
        for (int nt = 0; nt < 8; nt++) {
            int col = cbase + nt * 8;
            float v0 = acc[mt][nt][0] + bv[nt][0];
            float v1 = acc[mt][nt][1] + bv[nt][1];
            float v2 = acc[mt][nt][2] + bv[nt][0];
            float v3 = acc[mt][nt][3] + bv[nt][1];
            if (MODE == 0) {
                *(float2*)&C[(size_t)(m0 + rl0) * GN + col]     = make_float2(v0, v1);
                *(float2*)&C[(size_t)(m0 + rl0 + 8) * GN + col] = make_float2(v2, v3);
            } else if (MODE == 3) {
                ((__half2*)O1)[((size_t)(m0 + rl0) * D_ + col) >> 1]     = __floats2half2_rn(v0, v1);
                ((__half2*)O1)[((size_t)(m0 + rl0 + 8) * D_ + col) >> 1] = __floats2half2_rn(v2, v3);
            } else {
                int j = ((cb_loc + nt * 8) & 63) >> 1;
                float2 cs0 = st[rl0 * 32 + j];
                float2 cs1 = st[(rl0 + 8) * 32 + j];
                float y0 = v0 * cs0.x - v1 * cs0.y;
                float y1 = v1 * cs0.x + v0 * cs0.y;
                float y2 = v2 * cs1.x - v3 * cs1.y;
                float y3 = v3 * cs1.x + v2 * cs1.y;
                size_t e0 = ((size_t)(m0 + rl0) * D_ + col) >> 1;
                size_t e1 = ((size_t)(m0 + rl0 + 8) * D_ + col) >> 1;
                __half2 h0 = __floats2half2_rn(y0, y1);
                __half2 h1 = __floats2half2_rn(y2, y3);
                ((__half2*)O1)[e0] = h0;
                ((__half2*)O1)[e1] = h1;
                if (MODE == 1) {
                    ((__half2*)O2)[e0] = __floats2half2_rn(
                        y0 - __half2float(__low2half(h0)), y1 - __half2float(__high2half(h0)));
                    ((__half2*)O2)[e1] = __floats2half2_rn(
                        y2 - __half2float(__low2half(h1)), y3 - __half2float(__high2half(h1)));
                }
            }
        }
    }
}

// ---------------------------------------------------------------------------
// HMMA flash attention, fp16 2-pass; epilogue writes single fp16 Y (Wo is
// single-pass now).
// ---------------------------------------------------------------------------
#define ATT_SMEM 27648

__global__ void __launch_bounds__(128)
attn_mma(const __half* __restrict__ Qh, const __half* __restrict__ Ql,
         const __half* __restrict__ Kr, const __half* __restrict__ Vtr,
         const __nv_bfloat16* __restrict__ E, const float* __restrict__ alpha,
         __half* __restrict__ Yh)
{
    extern __shared__ char sm[];
    uint32_t* sK = (uint32_t*)sm;
    uint32_t* sV = (uint32_t*)(sm + 9216);
    __nv_bfloat16* sE = (__nv_bfloat16*)(sm + 18432);

    const int tid = threadIdx.x;
    const int w = tid >> 5, lane = tid & 31;
    const int c = lane & 3, rg = lane >> 2;
    const int qb = blockIdx.x, fh = blockIdx.y;
    const int f = fh >> 4, h = fh & 15;
    const int tok0 = f * NQ_;
    const int q0 = qb * 64;
    const float alph = alpha[h];
    const int rl = 16 * w + rg;

    for (int i = tid; i < 512; i += 128) {
        int row = i >> 3, c16 = i & 7;
        size_t go = (size_t)(tok0 + q0 + row) * D_ + h * 64 + c16 * 8;
        *(uint4*)(sK + row * 36 + c16 * 4) = *(const uint4*)(Qh + go);
        *(uint4*)(sV + row * 36 + c16 * 4) = *(const uint4*)(Ql + go);
    }
    __syncthreads();
    uint32_t qhF[4][4], qlF[4][4];
    #pragma unroll
    for (int s = 0; s < 4; s++) {
        qhF[s][0] = sK[rl * 36 + 8 * s + c];
        qhF[s][1] = sK[(rl + 8) * 36 + 8 * s + c];
        qhF[s][2] = sK[rl * 36 + 8 * s + c + 4];
        qhF[s][3] = sK[(rl + 8) * 36 + 8 * s + c + 4];
        qlF[s][0] = sV[rl * 36 + 8 * s + c];
        qlF[s][1] = sV[(rl + 8) * 36 + 8 * s + c];
        qlF[s][2] = sV[rl * 36 + 8 * s + c + 4];
        qlF[s][3] = sV[(rl + 8) * 36 + 8 * s + c + 4];
    }
    __syncthreads();

    float o[8][4];
    #pragma unroll
    for (int n = 0; n < 8; n++)
        #pragma unroll
        for (int r = 0; r < 4; r++) o[n][r] = 0.f;
    float m0r = -3.0e38f, m1r = -3.0e38f, l0r = 0.f, l1r = 0.f;

    for (int kt = 0; kt < 9; kt++) {
        const int k0 = kt * 64;
        for (int i = tid; i < 512; i += 128) {
            int row = i >> 3, c16 = i & 7;
            size_t go = (size_t)(tok0 + k0 + row) * D_ + h * 64 + c16 * 8;
            *(uint4*)(sK + row * 36 + c16 * 4) = *(const uint4*)(Kr + go);
            size_t vo = (size_t)fh * (64 * NK_) + (size_t)row * NK_ + k0 + c16 * 8;
            *(uint4*)(sV + row * 36 + c16 * 4) = *(const uint4*)(Vtr + vo);
        }
        for (int i = tid; i < 512; i += 128) {
            int row = i >> 3, c8 = i & 7;
            *(uint4*)(sE + row * 72 + c8 * 8) =
                *(const uint4*)(E + (size_t)(tok0 + q0 + row) * NK_ + k0 + c8 * 8);
        }
        __syncthreads();

        float s[8][4];
        #pragma unroll
        for (int n = 0; n < 8; n++)
            #pragma unroll
            for (int r = 0; r < 4; r++) s[n][r] = 0.f;
        #pragma unroll
        for (int st = 0; st < 4; st++) {
            #pragma unroll
            for (int n = 0; n < 8; n++) {
                int bi = (8 * n + rg) * 36 + 8 * st + c;
                uint32_t bh[2] = { sK[bi], sK[bi + 4] };
                mma_f16(s[n], qhF[st], bh);
                mma_f16(s[n], qlF[st], bh);
            }
        }

        float mn0 = m0r, mn1 = m1r;
        #pragma unroll
        for (int n = 0; n < 8; n++) {
            float2 e0 = __bfloat1622float2(
                *(__nv_bfloat162*)(sE + rl * 72 + 8 * n + 2 * c));
            float2 e1 = __bfloat1622float2(
                *(__nv_bfloat162*)(sE + (rl + 8) * 72 + 8 * n + 2 * c));
            s[n][0] = (e0.x < 0.f) ? NEGBIG : fmaf(s[n][0], 0.125f, alph * e0.x);
            s[n][1] = (e0.y < 0.f) ? NEGBIG : fmaf(s[n][1], 0.125f, alph * e0.y);
            s[n][2] = (e1.x < 0.f) ? NEGBIG : fmaf(s[n][2], 0.125f, alph * e1.x);
            s[n][3] = (e1.y < 0.f) ? NEGBIG : fmaf(s[n][3], 0.125f, alph * e1.y);
            mn0 = fmaxf(mn0, fmaxf(s[n][0], s[n][1]));
            mn1 = fmaxf(mn1, fmaxf(s[n][2], s[n][3]));
        }
        mn0 = fmaxf(mn0, __shfl_xor_sync(0xffffffffu, mn0, 1));
        mn0 = fmaxf(mn0, __shfl_xor_sync(0xffffffffu, mn0, 2));
        mn1 = fmaxf(mn1, __shfl_xor_sync(0xffffffffu, mn1, 1));
        mn1 = fmaxf(mn1, __shfl_xor_sync(0xffffffffu, mn1, 2));
        float f0 = ex2((m0r - mn0) * LOG2E);
        float f1 = ex2((m1r - mn1) * LOG2E);
        m0r = mn0; m1r = mn1;

        float rs0 = 0.f, rs1 = 0.f;
        uint32_t phL[8], phH[8], plL[8], plH[8];
        #pragma unroll
        for (int n = 0; n < 8; n++) {
            float p0 = ex2((s[n][0] - mn0) * LOG2E);
            float p1 = ex2((s[n][1] - mn0) * LOG2E);
            float p2 = ex2((s[n][2] - mn1) * LOG2E);
            float p3 = ex2((s[n][3] - mn1) * LOG2E);
            rs0 += p0 + p1;
            rs1 += p2 + p3;
            o[n][0] *= f0; o[n][1] *= f0; o[n][2] *= f1; o[n][3] *= f1;
            __half2 bL = __floats2half2_rn(p0, p1);
            phL[n] = *(uint32_t*)&bL;
            __half2 rL = __floats2half2_rn(p0 - __half2float(__low2half(bL)),
                                           p1 - __half2float(__high2half(bL)));
            plL[n] = *(uint32_t*)&rL;
            __half2 bH = __floats2half2_rn(p2, p3);
            phH[n] = *(uint32_t*)&bH;
            __half2 rH = __floats2half2_rn(p2 - __half2float(__low2half(bH)),
                                           p3 - __half2float(__high2half(bH)));
            plH[n] = *(uint32_t*)&rH;
        }
        rs0 += __shfl_xor_sync(0xffffffffu, rs0, 1);
        rs0 += __shfl_xor_sync(0xffffffffu, rs0, 2);
        rs1 += __shfl_xor_sync(0xffffffffu, rs1, 1);
        rs1 += __shfl_xor_sync(0xffffffffu, rs1, 2);
        l0r = l0r * f0 + rs0;
        l1r = l1r * f1 + rs1;

        #pragma unroll
        for (int st = 0; st < 4; st++) {
            uint32_t ah[4] = { phL[2 * st], phH[2 * st], phL[2 * st + 1], phH[2 * st + 1] };
            uint32_t al[4] = { plL[2 * st], plH[2 * st], plL[2 * st + 1], plH[2 * st + 1] };
            #pragma unroll
            for (int n = 0; n < 8; n++) {
                int bi = (8 * n + rg) * 36 + 8 * st + c;
                uint32_t vh[2] = { sV[bi], sV[bi + 4] };
                mma_f16(o[n], ah, vh);
                mma_f16(o[n], al, vh);
            }
        }
        __syncthreads();
    }

    float i0 = 1.f / l0r, i1 = 1.f / l1r;
    #pragma unroll
    for (int n = 0; n < 8; n++) {
        size_t e0 = ((size_t)(tok0 + q0 + rl) * D_ + h * 64 + 8 * n + 2 * c) >> 1;
        size_t e1 = ((size_t)(tok0 + q0 + rl + 8) * D_ + h * 64 + 8 * n + 2 * c) >> 1;
        ((__half2*)Yh)[e0] = __floats2half2_rn(o[n][0] * i0, o[n][1] * i0);
        ((__half2*)Yh)[e1] = __floats2half2_rn(o[n][2] * i1, o[n][3] * i1);
    }
}

// ---------------------------------------------------------------------------
extern "C" void kernel_launch(void* const* d_in, const int* in_sizes, int n_in,
                              void* d_out, int out_size)
{
    (void)in_sizes; (void)n_in; (void)out_size;

    const float*   q_tokens  = (const float*)d_in[0];
    const float*   kv_tokens = (const float*)d_in[1];
    const float*   coords_q  = (const float*)d_in[2];
    const float*   coords_k  = (const float*)d_in[3];
    const void*    q_pad     = d_in[4];
    const void*    kv_pad    = d_in[5];
    const float*   Wq = (const float*)d_in[6];
    const float*   bq = (const float*)d_in[7];
    const float*   Wk = (const float*)d_in[8];
    const float*   bk = (const float*)d_in[9];
    const float*   Wv = (const float*)d_in[10];
    const float*   bv = (const float*)d_in[11];
    const float*   Wo = (const float*)d_in[12];
    const float*   bo = (const float*)d_in[13];
    const float*   alpha = (const float*)d_in[14];
    const float*   f0 = (const float*)d_in[15];
    const float*   f1 = (const float*)d_in[16];
    const float*   f2 = (const float*)d_in[17];
    float* out = (float*)d_out;

    __nv_bfloat16 *Eb;
    float2 *rtq, *rtk;
    cudaGetSymbolAddress((void**)&Eb, g_E);
    cudaGetSymbolAddress((void**)&rtq, g_rtq);
    cudaGetSymbolAddress((void**)&rtk, g_rtk);

    __half *qhi, *qlo, *kvhi, *kvlo, *yhi, *Wqh, *Wkh, *Wvh, *Woh, *V16;
    __half *aQh, *aQl, *aKr, *vtr;
    cudaGetSymbolAddress((void**)&qhi,  g_qhi);  cudaGetSymbolAddress((void**)&qlo,  g_qlo);
    cudaGetSymbolAddress((void**)&kvhi, g_kvhi); cudaGetSymbolAddress((void**)&kvlo, g_kvlo);
    cudaGetSymbolAddress((void**)&yhi,  g_yhi);
    cudaGetSymbolAddress((void**)&Wqh, g_Wqh);   cudaGetSymbolAddress((void**)&Wkh, g_Wkh);
    cudaGetSymbolAddress((void**)&Wvh, g_Wvh);   cudaGetSymbolAddress((void**)&Woh, g_Woh);
    cudaGetSymbolAddress((void**)&V16, g_V16);
    cudaGetSymbolAddress((void**)&aQh, g_aQh);   cudaGetSymbolAddress((void**)&aQl, g_aQl);
    cudaGetSymbolAddress((void**)&aKr, g_aKr);   cudaGetSymbolAddress((void**)&vtr, g_vtr);

    const int smem2 = 3 * 3 * TILE_B;  // 92160 (2-pass: 3 tiles per stage)
    const int smem1 = 3 * 2 * TILE_B;  // 61440 (1-pass: 2 tiles per stage)
    cudaFuncSetAttribute(gemm_mma<1,2>, cudaFuncAttributeMaxDynamicSharedMemorySize, smem2);
    cudaFuncSetAttribute(gemm_mma<2,2>, cudaFuncAttributeMaxDynamicSharedMemorySize, smem2);
    cudaFuncSetAttribute(gemm_mma<3,1>, cudaFuncAttributeMaxDynamicSharedMemorySize, smem1);
    cudaFuncSetAttribute(gemm_mma<0,1>, cudaFuncAttributeMaxDynamicSharedMemorySize, smem1);
    cudaFuncSetAttribute(attn_mma, cudaFuncAttributeMaxDynamicSharedMemorySize, ATT_SMEM);

    // masks + fused bias + rope tables
    detect_mask_kernel<<<1, 256>>>((const unsigned*)q_pad, (const unsigned*)kv_pad,
                                   TOK / 4);
    bias_kernel<<<dim3(NQ_ / 8, 8), NK_>>>(coords_q, coords_k, q_pad, kv_pad, Eb);
    ropetab_kernel<<<TOK, 32>>>(coords_q, f0, f1, f2, rtq);
    ropetab_kernel<<<TOK, 32>>>(coords_k, f0, f1, f2, rtk);

    // fp16 splits: activations hi/lo, weights single-rounded
    const int ntok4 = TOK * D_ / 4, nw4 = D_ * D_ / 4;
    split_h_kernel<<<(ntok4 + 255) / 256, 256>>>(q_tokens,  qhi,  qlo,  ntok4);
    split_h_kernel<<<(ntok4 + 255) / 256, 256>>>(kv_tokens, kvhi, kvlo, ntok4);
    round_h_kernel<<<(nw4 + 255) / 256, 256>>>(Wq, Wqh, nw4);
    round_h_kernel<<<(nw4 + 255) / 256, 256>>>(Wk, Wkh, nw4);
    round_h_kernel<<<(nw4 + 255) / 256, 256>>>(Wv, Wvh, nw4);
    round_h_kernel<<<(nw4 + 255) / 256, 256>>>(Wo, Woh, nw4);

    dim3 gg(GN / 128, TOK / 128);
    // Q: 2-pass + rope + fp16 hi/lo;  K: 2-pass + rope + fp16;  V: 1-pass fp16
    gemm_mma<1,2><<<gg, 128, smem2>>>(qhi,  qlo,  Wqh, bq, nullptr, aQh, aQl, rtq);
    gemm_mma<2,2><<<gg, 128, smem2>>>(kvhi, kvlo, Wkh, bk, nullptr, aKr, nullptr, rtk);
    gemm_mma<3,1><<<gg, 128, smem1>>>(kvhi, nullptr, Wvh, bv, nullptr, V16, nullptr, nullptr);

    vtsplit_kernel<<<dim3(NK_ / 32, D_ / 32, 8), 256>>>(V16, vtr);

    attn_mma<<<dim3(9, 128), 128, ATT_SMEM>>>(aQh, aQl, aKr, vtr, Eb, alpha, yhi);

    // Wo: 1-pass, fp32 out
    gemm_mma<0,1><<<gg, 128, smem1>>>(yhi, nullptr, Woh, bo, out, nullptr, nullptr, nullptr);
}

// round 11
// speedup vs baseline: 1.6151x; 1.3802x over previous
#include <cuda_runtime.h>
#include <cuda_bf16.h>
#include <cuda_fp16.h>
#include <cstdint>
#include <cstddef>
#include <math.h>

// Problem constants
#define B_   2
#define T_   4
#define NQ_  576
#define NK_  576
#define D_   1024
#define H_   16
#define DH_  64
#define TOK  (B_*T_*NQ_)
#define NEGBIG (-1.7014118e38f)
#define LOG2E 1.4426950408889634f

#define GK 1024
#define GN 1024

// Scratch (device globals; no dynamic allocation allowed)
__device__ int   g_mask_mode[2];
__device__ __nv_bfloat16 g_E[8 * NQ_ * NK_];
__device__ float2 g_rtq[TOK * 32];
__device__ float2 g_rtk[TOK * 32];

// fp16 operands (all single-rounded now)
__device__ __half g_q16[TOK * D_];
__device__ __half g_kv16[TOK * D_];
__device__ __half g_yhi[TOK * D_];
__device__ __half g_Wqh[D_ * D_], g_Wkh[D_ * D_], g_Wvh[D_ * D_], g_Woh[D_ * D_];
__device__ __half g_V16[TOK * D_];

// attention operands (fp16): Q single (rope'd), K single (rope'd), V^T single
__device__ __half g_aQh[TOK * D_];
__device__ __half g_aKr[TOK * D_];
__device__ __half g_vtr[128 * 64 * NK_];

// ---------------------------------------------------------------------------
// Family-portable PTX helpers
// ---------------------------------------------------------------------------
__device__ __forceinline__ uint32_t smem_u32(const void* p) {
    uint32_t a;
    asm("{ .reg .u64 t; cvta.to.shared.u64 t, %1; cvt.u32.u64 %0, t; }"
        : "=r"(a) : "l"(p));
    return a;
}
__device__ __forceinline__ void cp16(uint32_t s, const void* g) {
    asm volatile("cp.async.cg.shared.global [%0], [%1], 16;"
                 :: "r"(s), "l"(g) : "memory");
}
__device__ __forceinline__ void cp_commit() {
    asm volatile("cp.async.commit_group;" ::: "memory");
}
__device__ __forceinline__ void cp_wait1() {
    asm volatile("cp.async.wait_group 1;" ::: "memory");
}
__device__ __forceinline__ void cp_wait0() {
    asm volatile("cp.async.wait_group 0;" ::: "memory");
}
__device__ __forceinline__ void ldm_x4(uint32_t* r, uint32_t addr) {
    asm volatile("ldmatrix.sync.aligned.m8n8.x4.shared.b16 {%0,%1,%2,%3}, [%4];"
                 : "=r"(r[0]), "=r"(r[1]), "=r"(r[2]), "=r"(r[3]) : "r"(addr));
}
__device__ __forceinline__ void mma_f16(float* d, const uint32_t* a, const uint32_t* b) {
    asm volatile(
        "mma.sync.aligned.m16n8k16.row.col.f32.f16.f16.f32 "
        "{%0,%1,%2,%3}, {%4,%5,%6,%7}, {%8,%9}, {%0,%1,%2,%3};"
        : "+f"(d[0]), "+f"(d[1]), "+f"(d[2]), "+f"(d[3])
        : "r"(a[0]), "r"(a[1]), "r"(a[2]), "r"(a[3]), "r"(b[0]), "r"(b[1]));
}
__device__ __forceinline__ float ex2(float x) {
    float y;
    asm("ex2.approx.f32 %0, %1;" : "=f"(y) : "f"(x));
    return y;
}

// fp32 -> fp16 single rounding
__global__ void round_h_kernel(const float* __restrict__ x,
                               __half* __restrict__ h, int n4)
{
    int i = blockIdx.x * blockDim.x + threadIdx.x;
    if (i >= n4) return;
    float4 v = ((const float4*)x)[i];
    ((__half2*)h)[2*i]   = __floats2half2_rn(v.x, v.y);
    ((__half2*)h)[2*i+1] = __floats2half2_rn(v.z, v.w);
}

// ---------------------------------------------------------------------------
// RoPE cos/sin table
// ---------------------------------------------------------------------------
__global__ void ropetab_kernel(const float* __restrict__ coords,
                               const float* __restrict__ f0,
                               const float* __restrict__ f1,
                               const float* __restrict__ f2,
                               float2* __restrict__ tab)
{
    const int tok = blockIdx.x, tid = threadIdx.x;
    float coord, fr;
    if (tid < 12)      { coord = coords[tok * 3 + 0]; fr = f0[tid]; }
    else if (tid < 22) { coord = coords[tok * 3 + 1]; fr = f1[tid - 12]; }
    else               { coord = coords[tok * 3 + 2]; fr = f2[tid - 22]; }
    float arg = 1.5707963267948966f * coord * fr;
    float s, c;
    sincosf(arg, &s, &c);
    tab[tok * 32 + tid] = make_float2(c, s);
}

// ---------------------------------------------------------------------------
// V transpose (fp16 in, fp16 out)
// ---------------------------------------------------------------------------
__global__ void vtsplit_kernel(const __half* __restrict__ V,
                               __half* __restrict__ vr)
{
    __shared__ __half t[32][33];
    const int k0 = blockIdx.x * 32, d0 = blockIdx.y * 32, f = blockIdx.z;
    const int tx = threadIdx.x & 31, ty = threadIdx.x >> 5;
    #pragma unroll
    for (int i = 0; i < 4; i++) {
        int key = k0 + ty + i * 8;
        t[ty + i * 8][tx] = V[(size_t)(f * NQ_ + key) * D_ + d0 + tx];
    }
    __syncthreads();
    #pragma unroll
    for (int i = 0; i < 4; i++) {
        int dd = ty + i * 8;
        int d = d0 + dd, h = d >> 6, dl = d & 63;
        size_t oi = ((size_t)(f * 16 + h) * 64 + dl) * NK_ + k0 + tx;
        vr[oi] = t[tx][dd];
    }
}

// ---------------------------------------------------------------------------
// Mask dtype detection
// ---------------------------------------------------------------------------
__global__ void detect_mask_kernel(const unsigned* __restrict__ qm,
                                   const unsigned* __restrict__ km, int nints)
{
    __shared__ int s_i, s_f;
    for (int b = 0; b < 2; b++) {
        if (threadIdx.x == 0) { s_i = 1; s_f = 1; }
        __syncthreads();
        const unsigned* p = b ? km : qm;
        int li = 1, lf = 1;
        for (int i = threadIdx.x; i < nints; i += blockDim.x) {
            unsigned v = p[i];
            if (v > 1u) li = 0;
            if (v != 0u && v != 0x3f800000u) lf = 0;
        }
        if (!li) atomicAnd(&s_i, 0);
        if (!lf) atomicAnd(&s_f, 0);
        __syncthreads();
        if (threadIdx.x == 0)
            g_mask_mode[b] = s_i ? 1 : (s_f ? 2 : 0);
        __syncthreads();
    }
}

__device__ __forceinline__ bool mask_at(const void* p, int i, int mode) {
    if (mode == 1) return ((const int*)p)[i] != 0;
    if (mode == 2) return ((const float*)p)[i] != 0.f;
    return ((const unsigned char*)p)[i] != 0;
}

// ---------------------------------------------------------------------------
// Fused bias precompute (raw masks, bf16 output)
// ---------------------------------------------------------------------------
__global__ void __launch_bounds__(576)
bias_kernel(const float* __restrict__ cq, const float* __restrict__ ck,
            const void* __restrict__ qmr, const void* __restrict__ kmr,
            __nv_bfloat16* __restrict__ E)
{
    __shared__ float ky[NK_], kx[NK_];
    __shared__ unsigned char kbad[NK_];
    __shared__ float qy8[8], qx8[8];
    __shared__ unsigned char qbad[8];
    const int f = blockIdx.y, k = threadIdx.x;
    const int ki = f * NK_ + k;
    const int mq = g_mask_mode[0], mk = g_mask_mode[1];
    ky[k]  = ck[ki * 3 + 1];
    kx[k]  = ck[ki * 3 + 2];
    kbad[k] = mask_at(kmr, ki, mk) ? 1 : 0;
    if (threadIdx.x < 8) {
        int q = blockIdx.x * 8 + threadIdx.x;
        int qi = f * NQ_ + q;
        qy8[threadIdx.x] = cq[qi * 3 + 1];
        qx8[threadIdx.x] = cq[qi * 3 + 2];
        qbad[threadIdx.x] = mask_at(qmr, qi, mq) ? 1 : 0;
    }
    __syncthreads();
    #pragma unroll
    for (int r = 0; r < 8; r++) {
        int q = blockIdx.x * 8 + r;
        float dy = qy8[r] - ky[k];
        float dx = qx8[r] - kx[k];
        float dist = sqrtf(dy * dy + dx * dx);
        bool bad = qbad[r] || kbad[k] || (dist > 0.5f);
        E[(size_t)(f * NQ_ + q) * NK_ + k] =
            __float2bfloat16(bad ? -3.0e38f : __expf(-10.f * dist));
    }
}

// ---------------------------------------------------------------------------
// HMMA GEMM, 1-pass fp16: C = rn(A) rn(B)^T + bias, fused epilogues.
// MODE 0: fp32 out (+bias)   [Wo]
// MODE 2: rope + fp16 out    [Q, K]
// MODE 3: fp16 out           [V]
// ---------------------------------------------------------------------------
#define TILE_B 10240
#define STG    (2 * TILE_B)
#define NCH    32

template<int MODE>
__global__ void __launch_bounds__(128, 2)
gemm_mma(const __half* __restrict__ Ah, const __half* __restrict__ Bh,
         const float* __restrict__ bias,
         float* __restrict__ C, __half* __restrict__ O1,
         const float2* __restrict__ rtab)
{
    extern __shared__ char dsm[];
    const uint32_t sbase = smem_u32(dsm);

    const int tid  = threadIdx.x;
    const int wid  = tid >> 5;
    const int lane = tid & 31;
    const int m0 = blockIdx.y * 128;
    const int n0 = blockIdx.x * 128;
    const int wm = (wid & 1) * 64;
    const int wn = (wid >> 1) * 64;

    float acc[4][8][4];
    #pragma unroll
    for (int mt = 0; mt < 4; mt++)
        #pragma unroll
        for (int nt = 0; nt < 8; nt++)
            #pragma unroll
            for (int r = 0; r < 4; r++) acc[mt][nt][r] = 0.f;

    int l_tl[8], l_row[8], l_c[8];
    #pragma unroll
    for (int j = 0; j < 8; j++) {
        int i = tid + j * 128;
        l_tl[j]  = i >> 9;
        l_row[j] = (i & 511) >> 2;
        l_c[j]   = i & 3;
    }

    auto issue_load = [&](int ch, int buf) {
        const int k0 = ch * 32;
        #pragma unroll
        for (int j = 0; j < 8; j++) {
            const __half* g = l_tl[j]
                ? Bh + (size_t)(n0 + l_row[j]) * GK + k0 + l_c[j] * 8
                : Ah + (size_t)(m0 + l_row[j]) * GK + k0 + l_c[j] * 8;
            uint32_t s = sbase + buf * STG + l_tl[j] * TILE_B
                       + l_row[j] * 80 + l_c[j] * 16;
            cp16(s, g);
        }
        cp_commit();
    };

    issue_load(0, 0);
    issue_load(1, 1);

    for (int ch = 0; ch < NCH; ch++) {
        if (ch == NCH - 1) cp_wait0(); else cp_wait1();
        __syncthreads();
        if (ch + 2 < NCH) issue_load(ch + 2, (ch + 2) % 3);

        const uint32_t hbase = sbase + (ch % 3) * STG;
        const uint32_t bbase = hbase + TILE_B;

        #pragma unroll
        for (int ks = 0; ks < 2; ks++) {
            uint32_t b[8][2];
            #pragma unroll
            for (int np = 0; np < 4; np++) {
                uint32_t addr = bbase
                    + (wn + np * 16 + (lane & 7) + ((lane >> 4) & 1) * 8) * 80
                    + ((lane >> 3) & 1) * 16 + ks * 32;
                uint32_t r[4];
                ldm_x4(r, addr);
                b[np * 2][0] = r[0];     b[np * 2][1] = r[1];
                b[np * 2 + 1][0] = r[2]; b[np * 2 + 1][1] = r[3];
            }
            uint32_t a[4][4];
            #pragma unroll
            for (int mt = 0; mt < 4; mt++) {
                uint32_t addr = hbase + (wm + mt * 16 + (lane & 15)) * 80
                              + (lane >> 4) * 16 + ks * 32;
                ldm_x4(a[mt], addr);
            }
            #pragma unroll
            for (int mt = 0; mt < 4; mt++)
                #pragma unroll
                for (int nt = 0; nt < 8; nt++)
                    mma_f16(acc[mt][nt], a[mt], b[nt]);
        }
    }

    // Stage rope table for this m-tile into (now free) smem.
    float2* st = (float2*)dsm;
    if (MODE == 2) {
        __syncthreads();
        for (int i = tid; i < 128 * 32; i += 128)
            st[i] = rtab[(size_t)(m0 + (i >> 5)) * 32 + (i & 31)];
        __syncthreads();
    }

    const int cb_loc = wn + (lane & 3) * 2;
    const int cbase = n0 + cb_loc;
    float bv[8][2];
    #pragma unroll
    for (int nt = 0; nt < 8; nt++) {
        bv[nt][0] = bias[cbase + nt * 8];
        bv[nt][1] = bias[cbase + nt * 8 + 1];
    }

    #pragma unroll
    for (int mt = 0; mt < 4; mt++) {
        int rl0 = wm + mt * 16 + (lane >> 2);
        #pragma unroll
        for (int nt = 0; nt < 8; nt++) {
            int col = cbase + nt * 8;
            float v0 = acc[mt][nt][0] + bv[nt][0];
            float v1 = acc[mt][nt][1] + bv[nt][1];
            float v2 = acc[mt][nt][2] + bv[nt][0];
            float v3 = acc[mt][nt][3] + bv[nt][1];
            if (MODE == 0) {
                *(float2*)&C[(size_t)(m0 + rl0) * GN + col]     = make_float2(v0, v1);
                *(float2*)&C[(size_t)(m0 + rl0 + 8) * GN + col] = make_float2(v2, v3);
            } else if (MODE == 3) {
                ((__half2*)O1)[((size_t)(m0 + rl0) * D_ + col) >> 1]     = __floats2half2_rn(v0, v1);
                ((__half2*)O1)[((size_t)(m0 + rl0 + 8) * D_ + col) >> 1] = __floats2half2_rn(v2, v3);
            } else {
                int j = ((cb_loc + nt * 8) & 63) >> 1;
                float2 cs0 = st[rl0 * 32 + j];
                float2 cs1 = st[(rl0 + 8) * 32 + j];
                float y0 = v0 * cs0.x - v1 * cs0.y;
                float y1 = v1 * cs0.x + v0 * cs0.y;
                float y2 = v2 * cs1.x - v3 * cs1.y;
                float y3 = v3 * cs1.x + v2 * cs1.y;
                ((__half2*)O1)[((size_t)(m0 + rl0) * D_ + col) >> 1]     = __floats2half2_rn(y0, y1);
                ((__half2*)O1)[((size_t)(m0 + rl0 + 8) * D_ + col) >> 1] = __floats2half2_rn(y2, y3);
            }
        }
    }
}

// ---------------------------------------------------------------------------
// HMMA flash attention: S = Q K^T (1-pass), O = (Phi+Plo) V (2-pass P).
// ---------------------------------------------------------------------------
#define ATT_SMEM 27648

__global__ void __launch_bounds__(128)
attn_mma(const __half* __restrict__ Qh,
         const __half* __restrict__ Kr, const __half* __restrict__ Vtr,
         const __nv_bfloat16* __restrict__ E, const float* __restrict__ alpha,
         __half* __restrict__ Yh)
{
    extern __shared__ char sm[];
    uint32_t* sK = (uint32_t*)sm;
    uint32_t* sV = (uint32_t*)(sm + 9216);
    __nv_bfloat16* sE = (__nv_bfloat16*)(sm + 18432);

    const int tid = threadIdx.x;
    const int w = tid >> 5, lane = tid & 31;
    const int c = lane & 3, rg = lane >> 2;
    const int qb = blockIdx.x, fh = blockIdx.y;
    const int f = fh >> 4, h = fh & 15;
    const int tok0 = f * NQ_;
    const int q0 = qb * 64;
    const float alph = alpha[h];
    const int rl = 16 * w + rg;

    // stage Q through sK, extract resident A fragments
    for (int i = tid; i < 512; i += 128) {
        int row = i >> 3, c16 = i & 7;
        size_t go = (size_t)(tok0 + q0 + row) * D_ + h * 64 + c16 * 8;
        *(uint4*)(sK + row * 36 + c16 * 4) = *(const uint4*)(Qh + go);
    }
    __syncthreads();
    uint32_t qhF[4][4];
    #pragma unroll
    for (int s = 0; s < 4; s++) {
        qhF[s][0] = sK[rl * 36 + 8 * s + c];
        qhF[s][1] = sK[(rl + 8) * 36 + 8 * s + c];
        qhF[s][2] = sK[rl * 36 + 8 * s + c + 4];
        qhF[s][3] = sK[(rl + 8) * 36 + 8 * s + c + 4];
    }
    __syncthreads();

    float o[8][4];
    #pragma unroll
    for (int n = 0; n < 8; n++)
        #pragma unroll
        for (int r = 0; r < 4; r++) o[n][r] = 0.f;
    float m0r = -3.0e38f, m1r = -3.0e38f, l0r = 0.f, l1r = 0.f;

    for (int kt = 0; kt < 9; kt++) {
        const int k0 = kt * 64;
        for (int i = tid; i < 512; i += 128) {
            int row = i >> 3, c16 = i & 7;
            size_t go = (size_t)(tok0 + k0 + row) * D_ + h * 64 + c16 * 8;
            *(uint4*)(sK + row * 36 + c16 * 4) = *(const uint4*)(Kr + go);
            size_t vo = (size_t)fh * (64 * NK_) + (size_t)row * NK_ + k0 + c16 * 8;
            *(uint4*)(sV + row * 36 + c16 * 4) = *(const uint4*)(Vtr + vo);
        }
        for (int i = tid; i < 512; i += 128) {
            int row = i >> 3, c8 = i & 7;
            *(uint4*)(sE + row * 72 + c8 * 8) =
                *(const uint4*)(E + (size_t)(tok0 + q0 + row) * NK_ + k0 + c8 * 8);
        }
        __syncthreads();

        // S = Q K^T (1-pass)
        float s[8][4];
        #pragma unroll
        for (int n = 0; n < 8; n++)
            #pragma unroll
            for (int r = 0; r < 4; r++) s[n][r] = 0.f;
        #pragma unroll
        for (int st = 0; st < 4; st++) {
            #pragma unroll
            for (int n = 0; n < 8; n++) {
                int bi = (8 * n + rg) * 36 + 8 * st + c;
                uint32_t bh[2] = { sK[bi], sK[bi + 4] };
                mma_f16(s[n], qhF[st], bh);
            }
        }

        float mn0 = m0r, mn1 = m1r;
        #pragma unroll
        for (int n = 0; n < 8; n++) {
            float2 e0 = __bfloat1622float2(
                *(__nv_bfloat162*)(sE + rl * 72 + 8 * n + 2 * c));
            float2 e1 = __bfloat1622float2(
                *(__nv_bfloat162*)(sE + (rl + 8) * 72 + 8 * n + 2 * c));
            s[n][0] = (e0.x < 0.f) ? NEGBIG : fmaf(s[n][0], 0.125f, alph * e0.x);
            s[n][1] = (e0.y < 0.f) ? NEGBIG : fmaf(s[n][1], 0.125f, alph * e0.y);
            s[n][2] = (e1.x < 0.f) ? NEGBIG : fmaf(s[n][2], 0.125f, alph * e1.x);
            s[n][3] = (e1.y < 0.f) ? NEGBIG : fmaf(s[n][3], 0.125f, alph * e1.y);
            mn0 = fmaxf(mn0, fmaxf(s[n][0], s[n][1]));
            mn1 = fmaxf(mn1, fmaxf(s[n][2], s[n][3]));
        }
        mn0 = fmaxf(mn0, __shfl_xor_sync(0xffffffffu, mn0, 1));
        mn0 = fmaxf(mn0, __shfl_xor_sync(0xffffffffu, mn0, 2));
        mn1 = fmaxf(mn1, __shfl_xor_sync(0xffffffffu, mn1, 1));
        mn1 = fmaxf(mn1, __shfl_xor_sync(0xffffffffu, mn1, 2));
        float f0 = ex2((m0r - mn0) * LOG2E);
        float f1 = ex2((m1r - mn1) * LOG2E);
        m0r = mn0; m1r = mn1;

        float rs0 = 0.f, rs1 = 0.f;
        uint32_t phL[8], phH[8], plL[8], plH[8];
        #pragma unroll
        for (int n = 0; n < 8; n++) {
            float p0 = ex2((s[n][0] - mn0) * LOG2E);
            float p1 = ex2((s[n][1] - mn0) * LOG2E);
            float p2 = ex2((s[n][2] - mn1) * LOG2E);
            float p3 = ex2((s[n][3] - mn1) * LOG2E);
            rs0 += p0 + p1;
            rs1 += p2 + p3;
            o[n][0] *= f0; o[n][1] *= f0; o[n][2] *= f1; o[n][3] *= f1;
            __half2 bL = __floats2half2_rn(p0, p1);
            phL[n] = *(uint32_t*)&bL;
            __half2 rL = __floats2half2_rn(p0 - __half2float(__low2half(bL)),
                                           p1 - __half2float(__high2half(bL)));
            plL[n] = *(uint32_t*)&rL;
            __half2 bH = __floats2half2_rn(p2, p3);
            phH[n] = *(uint32_t*)&bH;
            __half2 rH = __floats2half2_rn(p2 - __half2float(__low2half(bH)),
                                           p3 - __half2float(__high2half(bH)));
            plH[n] = *(uint32_t*)&rH;
        }
        rs0 += __shfl_xor_sync(0xffffffffu, rs0, 1);
        rs0 += __shfl_xor_sync(0xffffffffu, rs0, 2);
        rs1 += __shfl_xor_sync(0xffffffffu, rs1, 1);
        rs1 += __shfl_xor_sync(0xffffffffu, rs1, 2);
        l0r = l0r * f0 + rs0;
        l1r = l1r * f1 + rs1;

        // O += (Phi + Plo) V
        #pragma unroll
        for (int st = 0; st < 4; st++) {
            uint32_t ah[4] = { phL[2 * st], phH[2 * st], phL[2 * st + 1], phH[2 * st + 1] };
            uint32_t al[4] = { plL[2 * st], plH[2 * st], plL[2 * st + 1], plH[2 * st + 1] };
            #pragma unroll
            for (int n = 0; n < 8; n++) {
                int bi = (8 * n + rg) * 36 + 8 * st + c;
                uint32_t vh[2] = { sV[bi], sV[bi + 4] };
                mma_f16(o[n], ah, vh);
                mma_f16(o[n], al, vh);
            }
        }
        __syncthreads();
    }

    float i0 = 1.f / l0r, i1 = 1.f / l1r;
    #pragma unroll
    for (int n = 0; n < 8; n++) {
        size_t e0 = ((size_t)(tok0 + q0 + rl) * D_ + h * 64 + 8 * n + 2 * c) >> 1;
        size_t e1 = ((size_t)(tok0 + q0 + rl + 8) * D_ + h * 64 + 8 * n + 2 * c) >> 1;
        ((__half2*)Yh)[e0] = __floats2half2_rn(o[n][0] * i0, o[n][1] * i0);
        ((__half2*)Yh)[e1] = __floats2half2_rn(o[n][2] * i1, o[n][3] * i1);
    }
}

// ---------------------------------------------------------------------------
extern "C" void kernel_launch(void* const* d_in, const int* in_sizes, int n_in,
                              void* d_out, int out_size)
{
    (void)in_sizes; (void)n_in; (void)out_size;

    const float*   q_tokens  = (const float*)d_in[0];
    const float*   kv_tokens = (const float*)d_in[1];
    const float*   coords_q  = (const float*)d_in[2];
    const float*   coords_k  = (const float*)d_in[3];
    const void*    q_pad     = d_in[4];
    const void*    kv_pad    = d_in[5];
    const float*   Wq = (const float*)d_in[6];
    const float*   bq = (const float*)d_in[7];
    const float*   Wk = (const float*)d_in[8];
    const float*   bk = (const float*)d_in[9];
    const float*   Wv = (const float*)d_in[10];
    const float*   bv = (const float*)d_in[11];
    const float*   Wo = (const float*)d_in[12];
    const float*   bo = (const float*)d_in[13];
    const float*   alpha = (const float*)d_in[14];
    const float*   f0 = (const float*)d_in[15];
    const float*   f1 = (const float*)d_in[16];
    const float*   f2 = (const float*)d_in[17];
    float* out = (float*)d_out;

    __nv_bfloat16 *Eb;
    float2 *rtq, *rtk;
    cudaGetSymbolAddress((void**)&Eb, g_E);
    cudaGetSymbolAddress((void**)&rtq, g_rtq);
    cudaGetSymbolAddress((void**)&rtk, g_rtk);

    __half *q16, *kv16, *yhi, *Wqh, *Wkh, *Wvh, *Woh, *V16;
    __half *aQh, *aKr, *vtr;
    cudaGetSymbolAddress((void**)&q16,  g_q16);
    cudaGetSymbolAddress((void**)&kv16, g_kv16);
    cudaGetSymbolAddress((void**)&yhi,  g_yhi);
    cudaGetSymbolAddress((void**)&Wqh, g_Wqh);   cudaGetSymbolAddress((void**)&Wkh, g_Wkh);
    cudaGetSymbolAddress((void**)&Wvh, g_Wvh);   cudaGetSymbolAddress((void**)&Woh, g_Woh);
    cudaGetSymbolAddress((void**)&V16, g_V16);
    cudaGetSymbolAddress((void**)&aQh, g_aQh);
    cudaGetSymbolAddress((void**)&aKr, g_aKr);   cudaGetSymbolAddress((void**)&vtr, g_vtr);

    const int gemm_smem = 3 * STG;  // 61440
    cudaFuncSetAttribute(gemm_mma<0>, cudaFuncAttributeMaxDynamicSharedMemorySize, gemm_smem);
    cudaFuncSetAttribute(gemm_mma<2>, cudaFuncAttributeMaxDynamicSharedMemorySize, gemm_smem);
    cudaFuncSetAttribute(gemm_mma<3>, cudaFuncAttributeMaxDynamicSharedMemorySize, gemm_smem);
    cudaFuncSetAttribute(attn_mma, cudaFuncAttributeMaxDynamicSharedMemorySize, ATT_SMEM);

    // masks + fused bias + rope tables
    detect_mask_kernel<<<1, 256>>>((const unsigned*)q_pad, (const unsigned*)kv_pad,
                                   TOK / 4);
    bias_kernel<<<dim3(NQ_ / 8, 8), NK_>>>(coords_q, coords_k, q_pad, kv_pad, Eb);
    ropetab_kernel<<<TOK, 32>>>(coords_q, f0, f1, f2, rtq);
    ropetab_kernel<<<TOK, 32>>>(coords_k, f0, f1, f2, rtk);

    // fp16 single roundings
    const int ntok4 = TOK * D_ / 4, nw4 = D_ * D_ / 4;
    round_h_kernel<<<(ntok4 + 255) / 256, 256>>>(q_tokens,  q16,  ntok4);
    round_h_kernel<<<(ntok4 + 255) / 256, 256>>>(kv_tokens, kv16, ntok4);
    round_h_kernel<<<(nw4 + 255) / 256, 256>>>(Wq, Wqh, nw4);
    round_h_kernel<<<(nw4 + 255) / 256, 256>>>(Wk, Wkh, nw4);
    round_h_kernel<<<(nw4 + 255) / 256, 256>>>(Wv, Wvh, nw4);
    round_h_kernel<<<(nw4 + 255) / 256, 256>>>(Wo, Woh, nw4);

    dim3 gg(GN / 128, TOK / 128);
    // All 1-pass: Q,K with rope+fp16 epilogue; V fp16; Wo fp32.
    gemm_mma<2><<<gg, 128, gemm_smem>>>(q16,  Wqh, bq, nullptr, aQh, rtq);
    gemm_mma<2><<<gg, 128, gemm_smem>>>(kv16, Wkh, bk, nullptr, aKr, rtk);
    gemm_mma<3><<<gg, 128, gemm_smem>>>(kv16, Wvh, bv, nullptr, V16, nullptr);

    vtsplit_kernel<<<dim3(NK_ / 32, D_ / 32, 8), 256>>>(V16, vtr);

    attn_mma<<<dim3(9, 128), 128, ATT_SMEM>>>(aQh, aKr, vtr, Eb, alpha, yhi);

    gemm_mma<0><<<gg, 128, gemm_smem>>>(yhi, Woh, bo, out, nullptr, nullptr);
}

// round 12
// speedup vs baseline: 1.6892x; 1.0459x over previous
#include <cuda_runtime.h>
#include <cuda_bf16.h>
#include <cuda_fp16.h>
#include <cstdint>
#include <cstddef>
#include <math.h>

// Problem constants
#define B_   2
#define T_   4
#define NQ_  576
#define NK_  576
#define D_   1024
#define H_   16
#define DH_  64
#define TOK  (B_*T_*NQ_)
#define NEGBIG (-1.7014118e38f)
#define LOG2E 1.4426950408889634f

#define GK 1024
#define GN 1024

// Scratch (device globals; no dynamic allocation allowed)
__device__ int   g_mask_mode[2];
__device__ __nv_bfloat16 g_E[8 * NQ_ * NK_];
__device__ float2 g_rt[2][TOK * 32];   // cos/sin tables: [0]=q, [1]=k

// fp16 operands (all single-rounded)
__device__ __half g_x16[2][TOK * D_];  // [0]=q_tokens, [1]=kv_tokens
__device__ __half g_yhi[TOK * D_];
__device__ __half g_W16[4][D_ * D_];   // Wq, Wk, Wv, Wo
__device__ __half g_V16[TOK * D_];

// attention operands (fp16): Q (rope'd), K (rope'd), V^T
__device__ __half g_aQh[TOK * D_];
__device__ __half g_aKr[TOK * D_];
__device__ __half g_vtr[128 * 64 * NK_];

// ---------------------------------------------------------------------------
// Family-portable PTX helpers
// ---------------------------------------------------------------------------
__device__ __forceinline__ uint32_t smem_u32(const void* p) {
    uint32_t a;
    asm("{ .reg .u64 t; cvta.to.shared.u64 t, %1; cvt.u32.u64 %0, t; }"
        : "=r"(a) : "l"(p));
    return a;
}
__device__ __forceinline__ void cp16(uint32_t s, const void* g) {
    asm volatile("cp.async.cg.shared.global [%0], [%1], 16;"
                 :: "r"(s), "l"(g) : "memory");
}
__device__ __forceinline__ void cp_commit() {
    asm volatile("cp.async.commit_group;" ::: "memory");
}
__device__ __forceinline__ void cp_wait1() {
    asm volatile("cp.async.wait_group 1;" ::: "memory");
}
__device__ __forceinline__ void cp_wait0() {
    asm volatile("cp.async.wait_group 0;" ::: "memory");
}
__device__ __forceinline__ void ldm_x4(uint32_t* r, uint32_t addr) {
    asm volatile("ldmatrix.sync.aligned.m8n8.x4.shared.b16 {%0,%1,%2,%3}, [%4];"
                 : "=r"(r[0]), "=r"(r[1]), "=r"(r[2]), "=r"(r[3]) : "r"(addr));
}
__device__ __forceinline__ void mma_f16(float* d, const uint32_t* a, const uint32_t* b) {
    asm volatile(
        "mma.sync.aligned.m16n8k16.row.col.f32.f16.f16.f32 "
        "{%0,%1,%2,%3}, {%4,%5,%6,%7}, {%8,%9}, {%0,%1,%2,%3};"
        : "+f"(d[0]), "+f"(d[1]), "+f"(d[2]), "+f"(d[3])
        : "r"(a[0]), "r"(a[1]), "r"(a[2]), "r"(a[3]), "r"(b[0]), "r"(b[1]));
}
__device__ __forceinline__ float ex2(float x) {
    float y;
    asm("ex2.approx.f32 %0, %1;" : "=f"(y) : "f"(x));
    return y;
}

// batched fp32 -> fp16 rounding: grid.y selects (src,dst) pair
__global__ void round_h_batch(const float* const* __restrict__ srcs,
                              __half* const* __restrict__ dsts, int n4)
{
    int i = blockIdx.x * blockDim.x + threadIdx.x;
    if (i >= n4) return;
    const float* x = srcs[blockIdx.y];
    __half* h = dsts[blockIdx.y];
    float4 v = ((const float4*)x)[i];
    ((__half2*)h)[2*i]   = __floats2half2_rn(v.x, v.y);
    ((__half2*)h)[2*i+1] = __floats2half2_rn(v.z, v.w);
}

__device__ const float* g_round_src[6];
__device__ __half*      g_round_dst[6];

__global__ void setptrs_kernel(const float* s0, const float* s1, const float* s2,
                               const float* s3, const float* s4, const float* s5)
{
    g_round_src[0] = s0; g_round_src[1] = s1; g_round_src[2] = s2;
    g_round_src[3] = s3; g_round_src[4] = s4; g_round_src[5] = s5;
    g_round_dst[0] = g_W16[0]; g_round_dst[1] = g_W16[1];
    g_round_dst[2] = g_W16[2]; g_round_dst[3] = g_W16[3];
    g_round_dst[4] = g_x16[0]; g_round_dst[5] = g_x16[1];
}

// ---------------------------------------------------------------------------
// RoPE cos/sin table (grid.y = 0:q, 1:k)
// ---------------------------------------------------------------------------
__global__ void ropetab_kernel(const float* __restrict__ cq,
                               const float* __restrict__ ck,
                               const float* __restrict__ f0,
                               const float* __restrict__ f1,
                               const float* __restrict__ f2,
                               float2* __restrict__ tq,
                               float2* __restrict__ tk)
{
    const int tok = blockIdx.x, tid = threadIdx.x;
    const float* coords = blockIdx.y ? ck : cq;
    float2* tab = blockIdx.y ? tk : tq;
    float coord, fr;
    if (tid < 12)      { coord = coords[tok * 3 + 0]; fr = f0[tid]; }
    else if (tid < 22) { coord = coords[tok * 3 + 1]; fr = f1[tid - 12]; }
    else               { coord = coords[tok * 3 + 2]; fr = f2[tid - 22]; }
    float arg = 1.5707963267948966f * coord * fr;
    float s, c;
    sincosf(arg, &s, &c);
    tab[tok * 32 + tid] = make_float2(c, s);
}

// ---------------------------------------------------------------------------
// V transpose (fp16 in, fp16 out)
// ---------------------------------------------------------------------------
__global__ void vtsplit_kernel(const __half* __restrict__ V,
                               __half* __restrict__ vr)
{
    __shared__ __half t[32][33];
    const int k0 = blockIdx.x * 32, d0 = blockIdx.y * 32, f = blockIdx.z;
    const int tx = threadIdx.x & 31, ty = threadIdx.x >> 5;
    #pragma unroll
    for (int i = 0; i < 4; i++) {
        int key = k0 + ty + i * 8;
        t[ty + i * 8][tx] = V[(size_t)(f * NQ_ + key) * D_ + d0 + tx];
    }
    __syncthreads();
    #pragma unroll
    for (int i = 0; i < 4; i++) {
        int dd = ty + i * 8;
        int d = d0 + dd, h = d >> 6, dl = d & 63;
        size_t oi = ((size_t)(f * 16 + h) * 64 + dl) * NK_ + k0 + tx;
        vr[oi] = t[tx][dd];
    }
}

// ---------------------------------------------------------------------------
// Mask dtype detection
// ---------------------------------------------------------------------------
__global__ void detect_mask_kernel(const unsigned* __restrict__ qm,
                                   const unsigned* __restrict__ km, int nints)
{
    __shared__ int s_i, s_f;
    for (int b = 0; b < 2; b++) {
        if (threadIdx.x == 0) { s_i = 1; s_f = 1; }
        __syncthreads();
        const unsigned* p = b ? km : qm;
        int li = 1, lf = 1;
        for (int i = threadIdx.x; i < nints; i += blockDim.x) {
            unsigned v = p[i];
            if (v > 1u) li = 0;
            if (v != 0u && v != 0x3f800000u) lf = 0;
        }
        if (!li) atomicAnd(&s_i, 0);
        if (!lf) atomicAnd(&s_f, 0);
        __syncthreads();
        if (threadIdx.x == 0)
            g_mask_mode[b] = s_i ? 1 : (s_f ? 2 : 0);
        __syncthreads();
    }
}

__device__ __forceinline__ bool mask_at(const void* p, int i, int mode) {
    if (mode == 1) return ((const int*)p)[i] != 0;
    if (mode == 2) return ((const float*)p)[i] != 0.f;
    return ((const unsigned char*)p)[i] != 0;
}

// ---------------------------------------------------------------------------
// Fused bias precompute (raw masks, bf16 output)
// ---------------------------------------------------------------------------
__global__ void __launch_bounds__(576)
bias_kernel(const float* __restrict__ cq, const float* __restrict__ ck,
            const void* __restrict__ qmr, const void* __restrict__ kmr,
            __nv_bfloat16* __restrict__ E)
{
    __shared__ float ky[NK_], kx[NK_];
    __shared__ unsigned char kbad[NK_];
    __shared__ float qy8[8], qx8[8];
    __shared__ unsigned char qbad[8];
    const int f = blockIdx.y, k = threadIdx.x;
    const int ki = f * NK_ + k;
    const int mq = g_mask_mode[0], mk = g_mask_mode[1];
    ky[k]  = ck[ki * 3 + 1];
    kx[k]  = ck[ki * 3 + 2];
    kbad[k] = mask_at(kmr, ki, mk) ? 1 : 0;
    if (threadIdx.x < 8) {
        int q = blockIdx.x * 8 + threadIdx.x;
        int qi = f * NQ_ + q;
        qy8[threadIdx.x] = cq[qi * 3 + 1];
        qx8[threadIdx.x] = cq[qi * 3 + 2];
        qbad[threadIdx.x] = mask_at(qmr, qi, mq) ? 1 : 0;
    }
    __syncthreads();
    #pragma unroll
    for (int r = 0; r < 8; r++) {
        int q = blockIdx.x * 8 + r;
        float dy = qy8[r] - ky[k];
        float dx = qx8[r] - kx[k];
        float dist = sqrtf(dy * dy + dx * dx);
        bool bad = qbad[r] || kbad[k] || (dist > 0.5f);
        E[(size_t)(f * NQ_ + q) * NK_ + k] =
            __float2bfloat16(bad ? -3.0e38f : __expf(-10.f * dist));
    }
}

// ---------------------------------------------------------------------------
// HMMA GEMM, 1-pass fp16: C = rn(A) rn(B)^T + bias, fused epilogues.
// MODE 0: fp32 out (+bias)   [Wo]
// MODE 2: rope + fp16 out    [Q, K]
// MODE 3: fp16 out           [V]
// ---------------------------------------------------------------------------
#define TILE_B 10240
#define STG    (2 * TILE_B)
#define NCH    32

template<int MODE>
__global__ void __launch_bounds__(128, 2)
gemm_mma(const __half* __restrict__ Ah, const __half* __restrict__ Bh,
         const float* __restrict__ bias,
         float* __restrict__ C, __half* __restrict__ O1,
         const float2* __restrict__ rtab)
{
    extern __shared__ char dsm[];
    const uint32_t sbase = smem_u32(dsm);

    const int tid  = threadIdx.x;
    const int wid  = tid >> 5;
    const int lane = tid & 31;
    const int m0 = blockIdx.y * 128;
    const int n0 = blockIdx.x * 128;
    const int wm = (wid & 1) * 64;
    const int wn = (wid >> 1) * 64;

    float acc[4][8][4];
    #pragma unroll
    for (int mt = 0; mt < 4; mt++)
        #pragma unroll
        for (int nt = 0; nt < 8; nt++)
            #pragma unroll
            for (int r = 0; r < 4; r++) acc[mt][nt][r] = 0.f;

    int l_tl[8], l_row[8], l_c[8];
    #pragma unroll
    for (int j = 0; j < 8; j++) {
        int i = tid + j * 128;
        l_tl[j]  = i >> 9;
        l_row[j] = (i & 511) >> 2;
        l_c[j]   = i & 3;
    }

    auto issue_load = [&](int ch, int buf) {
        const int k0 = ch * 32;
        #pragma unroll
        for (int j = 0; j < 8; j++) {
            const __half* g = l_tl[j]
                ? Bh + (size_t)(n0 + l_row[j]) * GK + k0 + l_c[j] * 8
                : Ah + (size_t)(m0 + l_row[j]) * GK + k0 + l_c[j] * 8;
            uint32_t s = sbase + buf * STG + l_tl[j] * TILE_B
                       + l_row[j] * 80 + l_c[j] * 16;
            cp16(s, g);
        }
        cp_commit();
    };

    issue_load(0, 0);
    issue_load(1, 1);

    for (int ch = 0; ch < NCH; ch++) {
        if (ch == NCH - 1) cp_wait0(); else cp_wait1();
        __syncthreads();
        if (ch + 2 < NCH) issue_load(ch + 2, (ch + 2) % 3);

        const uint32_t hbase = sbase + (ch % 3) * STG;
        const uint32_t bbase = hbase + TILE_B;

        #pragma unroll
        for (int ks = 0; ks < 2; ks++) {
            uint32_t b[8][2];
            #pragma unroll
            for (int np = 0; np < 4; np++) {
                uint32_t addr = bbase
                    + (wn + np * 16 + (lane & 7) + ((lane >> 4) & 1) * 8) * 80
                    + ((lane >> 3) & 1) * 16 + ks * 32;
                uint32_t r[4];
                ldm_x4(r, addr);
                b[np * 2][0] = r[0];     b[np * 2][1] = r[1];
                b[np * 2 + 1][0] = r[2]; b[np * 2 + 1][1] = r[3];
            }
            uint32_t a[4][4];
            #pragma unroll
            for (int mt = 0; mt < 4; mt++) {
                uint32_t addr = hbase + (wm + mt * 16 + (lane & 15)) * 80
                              + (lane >> 4) * 16 + ks * 32;
                ldm_x4(a[mt], addr);
            }
            #pragma unroll
            for (int mt = 0; mt < 4; mt++)
                #pragma unroll
                for (int nt = 0; nt < 8; nt++)
                    mma_f16(acc[mt][nt], a[mt], b[nt]);
        }
    }

    // Stage rope table for this m-tile into (now free) smem.
    float2* st = (float2*)dsm;
    if (MODE == 2) {
        __syncthreads();
        for (int i = tid; i < 128 * 32; i += 128)
            st[i] = rtab[(size_t)(m0 + (i >> 5)) * 32 + (i & 31)];
        __syncthreads();
    }

    const int cb_loc = wn + (lane & 3) * 2;
    const int cbase = n0 + cb_loc;
    float bv[8][2];
    #pragma unroll
    for (int nt = 0; nt < 8; nt++) {
        bv[nt][0] = bias[cbase + nt * 8];
        bv[nt][1] = bias[cbase + nt * 8 + 1];
    }

    #pragma unroll
    for (int mt = 0; mt < 4; mt++) {
        int rl0 = wm + mt * 16 + (lane >> 2);
        #pragma unroll
        for (int nt = 0; nt < 8; nt++) {
            int col = cbase + nt * 8;
            float v0 = acc[mt][nt][0] + bv[nt][0];
            float v1 = acc[mt][nt][1] + bv[nt][1];
            float v2 = acc[mt][nt][2] + bv[nt][0];
            float v3 = acc[mt][nt][3] + bv[nt][1];
            if (MODE == 0) {
                *(float2*)&C[(size_t)(m0 + rl0) * GN + col]     = make_float2(v0, v1);
                *(float2*)&C[(size_t)(m0 + rl0 + 8) * GN + col] = make_float2(v2, v3);
            } else if (MODE == 3) {
                ((__half2*)O1)[((size_t)(m0 + rl0) * D_ + col) >> 1]     = __floats2half2_rn(v0, v1);
                ((__half2*)O1)[((size_t)(m0 + rl0 + 8) * D_ + col) >> 1] = __floats2half2_rn(v2, v3);
            } else {
                int j = ((cb_loc + nt * 8) & 63) >> 1;
                float2 cs0 = st[rl0 * 32 + j];
                float2 cs1 = st[(rl0 + 8) * 32 + j];
                float y0 = v0 * cs0.x - v1 * cs0.y;
                float y1 = v1 * cs0.x + v0 * cs0.y;
                float y2 = v2 * cs1.x - v3 * cs1.y;
                float y3 = v3 * cs1.x + v2 * cs1.y;
                ((__half2*)O1)[((size_t)(m0 + rl0) * D_ + col) >> 1]     = __floats2half2_rn(y0, y1);
                ((__half2*)O1)[((size_t)(m0 + rl0 + 8) * D_ + col) >> 1] = __floats2half2_rn(y2, y3);
            }
        }
    }
}

// ---------------------------------------------------------------------------
// HMMA flash attention: S = Q K^T (1-pass), O = P V (1-pass).
// ---------------------------------------------------------------------------
#define ATT_SMEM 27648

__global__ void __launch_bounds__(128)
attn_mma(const __half* __restrict__ Qh,
         const __half* __restrict__ Kr, const __half* __restrict__ Vtr,
         const __nv_bfloat16* __restrict__ E, const float* __restrict__ alpha,
         __half* __restrict__ Yh)
{
    extern __shared__ char sm[];
    uint32_t* sK = (uint32_t*)sm;
    uint32_t* sV = (uint32_t*)(sm + 9216);
    __nv_bfloat16* sE = (__nv_bfloat16*)(sm + 18432);

    const int tid = threadIdx.x;
    const int w = tid >> 5, lane = tid & 31;
    const int c = lane & 3, rg = lane >> 2;
    const int qb = blockIdx.x, fh = blockIdx.y;
    const int f = fh >> 4, h = fh & 15;
    const int tok0 = f * NQ_;
    const int q0 = qb * 64;
    const float alph = alpha[h];
    const int rl = 16 * w + rg;

    // stage Q through sK, extract resident A fragments
    for (int i = tid; i < 512; i += 128) {
        int row = i >> 3, c16 = i & 7;
        size_t go = (size_t)(tok0 + q0 + row) * D_ + h * 64 + c16 * 8;
        *(uint4*)(sK + row * 36 + c16 * 4) = *(const uint4*)(Qh + go);
    }
    __syncthreads();
    uint32_t qhF[4][4];
    #pragma unroll
    for (int s = 0; s < 4; s++) {
        qhF[s][0] = sK[rl * 36 + 8 * s + c];
        qhF[s][1] = sK[(rl + 8) * 36 + 8 * s + c];
        qhF[s][2] = sK[rl * 36 + 8 * s + c + 4];
        qhF[s][3] = sK[(rl + 8) * 36 + 8 * s + c + 4];
    }
    __syncthreads();

    float o[8][4];
    #pragma unroll
    for (int n = 0; n < 8; n++)
        #pragma unroll
        for (int r = 0; r < 4; r++) o[n][r] = 0.f;
    float m0r = -3.0e38f, m1r = -3.0e38f, l0r = 0.f, l1r = 0.f;

    for (int kt = 0; kt < 9; kt++) {
        const int k0 = kt * 64;
        for (int i = tid; i < 512; i += 128) {
            int row = i >> 3, c16 = i & 7;
            size_t go = (size_t)(tok0 + k0 + row) * D_ + h * 64 + c16 * 8;
            *(uint4*)(sK + row * 36 + c16 * 4) = *(const uint4*)(Kr + go);
            size_t vo = (size_t)fh * (64 * NK_) + (size_t)row * NK_ + k0 + c16 * 8;
            *(uint4*)(sV + row * 36 + c16 * 4) = *(const uint4*)(Vtr + vo);
        }
        for (int i = tid; i < 512; i += 128) {
            int row = i >> 3, c8 = i & 7;
            *(uint4*)(sE + row * 72 + c8 * 8) =
                *(const uint4*)(E + (size_t)(tok0 + q0 + row) * NK_ + k0 + c8 * 8);
        }
        __syncthreads();

        // S = Q K^T
        float s[8][4];
        #pragma unroll
        for (int n = 0; n < 8; n++)
            #pragma unroll
            for (int r = 0; r < 4; r++) s[n][r] = 0.f;
        #pragma unroll
        for (int st = 0; st < 4; st++) {
            #pragma unroll
            for (int n = 0; n < 8; n++) {
                int bi = (8 * n + rg) * 36 + 8 * st + c;
                uint32_t bh[2] = { sK[bi], sK[bi + 4] };
                mma_f16(s[n], qhF[st], bh);
            }
        }

        float mn0 = m0r, mn1 = m1r;
        #pragma unroll
        for (int n = 0; n < 8; n++) {
            float2 e0 = __bfloat1622float2(
                *(__nv_bfloat162*)(sE + rl * 72 + 8 * n + 2 * c));
            float2 e1 = __bfloat1622float2(
                *(__nv_bfloat162*)(sE + (rl + 8) * 72 + 8 * n + 2 * c));
            s[n][0] = (e0.x < 0.f) ? NEGBIG : fmaf(s[n][0], 0.125f, alph * e0.x);
            s[n][1] = (e0.y < 0.f) ? NEGBIG : fmaf(s[n][1], 0.125f, alph * e0.y);
            s[n][2] = (e1.x < 0.f) ? NEGBIG : fmaf(s[n][2], 0.125f, alph * e1.x);
            s[n][3] = (e1.y < 0.f) ? NEGBIG : fmaf(s[n][3], 0.125f, alph * e1.y);
            mn0 = fmaxf(mn0, fmaxf(s[n][0], s[n][1]));
            mn1 = fmaxf(mn1, fmaxf(s[n][2], s[n][3]));
        }
        mn0 = fmaxf(mn0, __shfl_xor_sync(0xffffffffu, mn0, 1));
        mn0 = fmaxf(mn0, __shfl_xor_sync(0xffffffffu, mn0, 2));
        mn1 = fmaxf(mn1, __shfl_xor_sync(0xffffffffu, mn1, 1));
        mn1 = fmaxf(mn1, __shfl_xor_sync(0xffffffffu, mn1, 2));
        float f0 = ex2((m0r - mn0) * LOG2E);
        float f1 = ex2((m1r - mn1) * LOG2E);
        m0r = mn0; m1r = mn1;

        float rs0 = 0.f, rs1 = 0.f;
        uint32_t phL[8], phH[8];
        #pragma unroll
        for (int n = 0; n < 8; n++) {
            float p0 = ex2((s[n][0] - mn0) * LOG2E);
            float p1 = ex2((s[n][1] - mn0) * LOG2E);
            float p2 = ex2((s[n][2] - mn1) * LOG2E);
            float p3 = ex2((s[n][3] - mn1) * LOG2E);
            rs0 += p0 + p1;
            rs1 += p2 + p3;
            o[n][0] *= f0; o[n][1] *= f0; o[n][2] *= f1; o[n][3] *= f1;
            __half2 bL = __floats2half2_rn(p0, p1);
            phL[n] = *(uint32_t*)&bL;
            __half2 bH = __floats2half2_rn(p2, p3);
            phH[n] = *(uint32_t*)&bH;
        }
        rs0 += __shfl_xor_sync(0xffffffffu, rs0, 1);
        rs0 += __shfl_xor_sync(0xffffffffu, rs0, 2);
        rs1 += __shfl_xor_sync(0xffffffffu, rs1, 1);
        rs1 += __shfl_xor_sync(0xffffffffu, rs1, 2);
        l0r = l0r * f0 + rs0;
        l1r = l1r * f1 + rs1;

        // O += P V (1-pass)
        #pragma unroll
        for (int st = 0; st < 4; st++) {
            uint32_t ah[4] = { phL[2 * st], phH[2 * st], phL[2 * st + 1], phH[2 * st + 1] };
            #pragma unroll
            for (int n = 0; n < 8; n++) {
                int bi = (8 * n + rg) * 36 + 8 * st + c;
                uint32_t vh[2] = { sV[bi], sV[bi + 4] };
                mma_f16(o[n], ah, vh);
            }
        }
        __syncthreads();
    }

    float i0 = 1.f / l0r, i1 = 1.f / l1r;
    #pragma unroll
    for (int n = 0; n < 8; n++) {
        size_t e0 = ((size_t)(tok0 + q0 + rl) * D_ + h * 64 + 8 * n + 2 * c) >> 1;
        size_t e1 = ((size_t)(tok0 + q0 + rl + 8) * D_ + h * 64 + 8 * n + 2 * c) >> 1;
        ((__half2*)Yh)[e0] = __floats2half2_rn(o[n][0] * i0, o[n][1] * i0);
        ((__half2*)Yh)[e1] = __floats2half2_rn(o[n][2] * i1, o[n][3] * i1);
    }
}

// ---------------------------------------------------------------------------
extern "C" void kernel_launch(void* const* d_in, const int* in_sizes, int n_in,
                              void* d_out, int out_size)
{
    (void)in_sizes; (void)n_in; (void)out_size;

    const float*   q_tokens  = (const float*)d_in[0];
    const float*   kv_tokens = (const float*)d_in[1];
    const float*   coords_q  = (const float*)d_in[2];
    const float*   coords_k  = (const float*)d_in[3];
    const void*    q_pad     = d_in[4];
    const void*    kv_pad    = d_in[5];
    const float*   Wq = (const float*)d_in[6];
    const float*   bq = (const float*)d_in[7];
    const float*   Wk = (const float*)d_in[8];
    const float*   bk = (const float*)d_in[9];
    const float*   Wv = (const float*)d_in[10];
    const float*   bv = (const float*)d_in[11];
    const float*   Wo = (const float*)d_in[12];
    const float*   bo = (const float*)d_in[13];
    const float*   alpha = (const float*)d_in[14];
    const float*   f0 = (const float*)d_in[15];
    const float*   f1 = (const float*)d_in[16];
    const float*   f2 = (const float*)d_in[17];
    float* out = (float*)d_out;

    __nv_bfloat16 *Eb;
    float2 *rtq, *rtk;
    cudaGetSymbolAddress((void**)&Eb, g_E);
    cudaGetSymbolAddress((void**)&rtq, g_rt);
    rtk = rtq + TOK * 32;

    __half *x16q, *x16kv, *yhi, *W16, *V16, *aQh, *aKr, *vtr;
    cudaGetSymbolAddress((void**)&x16q, g_x16);
    x16kv = x16q + TOK * D_;
    cudaGetSymbolAddress((void**)&yhi,  g_yhi);
    cudaGetSymbolAddress((void**)&W16, g_W16);
    cudaGetSymbolAddress((void**)&V16, g_V16);
    cudaGetSymbolAddress((void**)&aQh, g_aQh);
    cudaGetSymbolAddress((void**)&aKr, g_aKr);
    cudaGetSymbolAddress((void**)&vtr, g_vtr);
    __half *Wqh = W16, *Wkh = W16 + D_ * D_, *Wvh = W16 + 2 * D_ * D_,
           *Woh = W16 + 3 * D_ * D_;

    const float** rsrc;
    __half** rdst;
    cudaGetSymbolAddress((void**)&rsrc, g_round_src);
    cudaGetSymbolAddress((void**)&rdst, g_round_dst);

    const int gemm_smem = 3 * STG;  // 61440
    cudaFuncSetAttribute(gemm_mma<0>, cudaFuncAttributeMaxDynamicSharedMemorySize, gemm_smem);
    cudaFuncSetAttribute(gemm_mma<2>, cudaFuncAttributeMaxDynamicSharedMemorySize, gemm_smem);
    cudaFuncSetAttribute(gemm_mma<3>, cudaFuncAttributeMaxDynamicSharedMemorySize, gemm_smem);
    cudaFuncSetAttribute(attn_mma, cudaFuncAttributeMaxDynamicSharedMemorySize, ATT_SMEM);

    // pointers for batched rounding
    setptrs_kernel<<<1, 1>>>(Wq, Wk, Wv, Wo, q_tokens, kv_tokens);

    // masks + fused bias + rope tables
    detect_mask_kernel<<<1, 256>>>((const unsigned*)q_pad, (const unsigned*)kv_pad,
                                   TOK / 4);
    bias_kernel<<<dim3(NQ_ / 8, 8), NK_>>>(coords_q, coords_k, q_pad, kv_pad, Eb);
    ropetab_kernel<<<dim3(TOK, 2), 32>>>(coords_q, coords_k, f0, f1, f2, rtq, rtk);

    // fp16 single roundings (batched: 4 weights at nw4, then 2 acts at ntok4)
    const int ntok4 = TOK * D_ / 4, nw4 = D_ * D_ / 4;
    round_h_batch<<<dim3((nw4 + 255) / 256, 4), 256>>>(rsrc, rdst, nw4);
    round_h_batch<<<dim3((ntok4 + 255) / 256, 2), 256>>>(rsrc + 4, rdst + 4, ntok4);

    dim3 gg(GN / 128, TOK / 128);
    gemm_mma<2><<<gg, 128, gemm_smem>>>(x16q,  Wqh, bq, nullptr, aQh, rtq);
    gemm_mma<2><<<gg, 128, gemm_smem>>>(x16kv, Wkh, bk, nullptr, aKr, rtk);
    gemm_mma<3><<<gg, 128, gemm_smem>>>(x16kv, Wvh, bv, nullptr, V16, nullptr);

    vtsplit_kernel<<<dim3(NK_ / 32, D_ / 32, 8), 256>>>(V16, vtr);

    attn_mma<<<dim3(9, 128), 128, ATT_SMEM>>>(aQh, aKr, vtr, Eb, alpha, yhi);

    gemm_mma<0><<<gg, 128, gemm_smem>>>(yhi, Woh, bo, out, nullptr, nullptr);
}

// round 13
// speedup vs baseline: 1.7807x; 1.0541x over previous
#include <cuda_runtime.h>
#include <cuda_bf16.h>
#include <cuda_fp16.h>
#include <cstdint>
#include <cstddef>
#include <math.h>

// Problem constants
#define B_   2
#define T_   4
#define NQ_  576
#define NK_  576
#define D_   1024
#define H_   16
#define DH_  64
#define TOK  (B_*T_*NQ_)
#define NEGBIG (-1.7014118e38f)
#define LOG2E 1.4426950408889634f

#define GK 1024
#define GN 1024

// Scratch (device globals; no dynamic allocation allowed)
__device__ int   g_mask_mode[2];
__device__ __nv_bfloat16 g_E[8 * NQ_ * NK_];
__device__ float2 g_rt[2][TOK * 32];   // cos/sin tables: [0]=q, [1]=k

// fp16 operands (all single-rounded)
__device__ __half g_x16[2][TOK * D_];  // [0]=q_tokens, [1]=kv_tokens
__device__ __half g_yhi[TOK * D_];
__device__ __half g_W16[4][D_ * D_];   // Wq, Wk, Wv, Wo

// attention operands (fp16): Q (rope'd), K (rope'd), V^T
__device__ __half g_aQh[TOK * D_];
__device__ __half g_aKr[TOK * D_];
__device__ __half g_vtr[128 * 64 * NK_];

__device__ const float* g_round_src[6];
__device__ __half*      g_round_dst[6];

// ---------------------------------------------------------------------------
// Family-portable PTX helpers
// ---------------------------------------------------------------------------
__device__ __forceinline__ uint32_t smem_u32(const void* p) {
    uint32_t a;
    asm("{ .reg .u64 t; cvta.to.shared.u64 t, %1; cvt.u32.u64 %0, t; }"
        : "=r"(a) : "l"(p));
    return a;
}
__device__ __forceinline__ void cp16(uint32_t s, const void* g) {
    asm volatile("cp.async.cg.shared.global [%0], [%1], 16;"
                 :: "r"(s), "l"(g) : "memory");
}
__device__ __forceinline__ void cp_commit() {
    asm volatile("cp.async.commit_group;" ::: "memory");
}
__device__ __forceinline__ void cp_wait1() {
    asm volatile("cp.async.wait_group 1;" ::: "memory");
}
__device__ __forceinline__ void cp_wait0() {
    asm volatile("cp.async.wait_group 0;" ::: "memory");
}
__device__ __forceinline__ void ldm_x4(uint32_t* r, uint32_t addr) {
    asm volatile("ldmatrix.sync.aligned.m8n8.x4.shared.b16 {%0,%1,%2,%3}, [%4];"
                 : "=r"(r[0]), "=r"(r[1]), "=r"(r[2]), "=r"(r[3]) : "r"(addr));
}
__device__ __forceinline__ void mma_f16(float* d, const uint32_t* a, const uint32_t* b) {
    asm volatile(
        "mma.sync.aligned.m16n8k16.row.col.f32.f16.f16.f32 "
        "{%0,%1,%2,%3}, {%4,%5,%6,%7}, {%8,%9}, {%0,%1,%2,%3};"
        : "+f"(d[0]), "+f"(d[1]), "+f"(d[2]), "+f"(d[3])
        : "r"(a[0]), "r"(a[1]), "r"(a[2]), "r"(a[3]), "r"(b[0]), "r"(b[1]));
}
__device__ __forceinline__ float ex2(float x) {
    float y;
    asm("ex2.approx.f32 %0, %1;" : "=f"(y) : "f"(x));
    return y;
}

// batched fp32 -> fp16 rounding: grid.y selects (src,dst) pair
__global__ void round_h_batch(const float* const* __restrict__ srcs,
                              __half* const* __restrict__ dsts, int n4)
{
    int i = blockIdx.x * blockDim.x + threadIdx.x;
    if (i >= n4) return;
    const float* x = srcs[blockIdx.y];
    __half* h = dsts[blockIdx.y];
    float4 v = ((const float4*)x)[i];
    ((__half2*)h)[2*i]   = __floats2half2_rn(v.x, v.y);
    ((__half2*)h)[2*i+1] = __floats2half2_rn(v.z, v.w);
}

// ---------------------------------------------------------------------------
// Mask dtype detection (+ pointer table setup on thread 0)
// ---------------------------------------------------------------------------
__global__ void detect_mask_kernel(const unsigned* __restrict__ qm,
                                   const unsigned* __restrict__ km, int nints,
                                   const float* s0, const float* s1,
                                   const float* s2, const float* s3,
                                   const float* s4, const float* s5)
{
    if (threadIdx.x == 0) {
        g_round_src[0] = s0; g_round_src[1] = s1; g_round_src[2] = s2;
        g_round_src[3] = s3; g_round_src[4] = s4; g_round_src[5] = s5;
        g_round_dst[0] = g_W16[0]; g_round_dst[1] = g_W16[1];
        g_round_dst[2] = g_W16[2]; g_round_dst[3] = g_W16[3];
        g_round_dst[4] = g_x16[0]; g_round_dst[5] = g_x16[1];
    }
    __shared__ int s_i, s_f;
    for (int b = 0; b < 2; b++) {
        if (threadIdx.x == 0) { s_i = 1; s_f = 1; }
        __syncthreads();
        const unsigned* p = b ? km : qm;
        int li = 1, lf = 1;
        for (int i = threadIdx.x; i < nints; i += blockDim.x) {
            unsigned v = p[i];
            if (v > 1u) li = 0;
            if (v != 0u && v != 0x3f800000u) lf = 0;
        }
        if (!li) atomicAnd(&s_i, 0);
        if (!lf) atomicAnd(&s_f, 0);
        __syncthreads();
        if (threadIdx.x == 0)
            g_mask_mode[b] = s_i ? 1 : (s_f ? 2 : 0);
        __syncthreads();
    }
}

__device__ __forceinline__ bool mask_at(const void* p, int i, int mode) {
    if (mode == 1) return ((const int*)p)[i] != 0;
    if (mode == 2) return ((const float*)p)[i] != 0.f;
    return ((const unsigned char*)p)[i] != 0;
}

// ---------------------------------------------------------------------------
// RoPE cos/sin table: 256 threads = 8 tokens/block; grid (TOK/8, 2)
// ---------------------------------------------------------------------------
__global__ void ropetab_kernel(const float* __restrict__ cq,
                               const float* __restrict__ ck,
                               const float* __restrict__ f0,
                               const float* __restrict__ f1,
                               const float* __restrict__ f2,
                               float2* __restrict__ tq,
                               float2* __restrict__ tk)
{
    const int tok = blockIdx.x * 8 + (threadIdx.x >> 5);
    const int tid = threadIdx.x & 31;
    const float* coords = blockIdx.y ? ck : cq;
    float2* tab = blockIdx.y ? tk : tq;
    float coord, fr;
    if (tid < 12)      { coord = coords[tok * 3 + 0]; fr = f0[tid]; }
    else if (tid < 22) { coord = coords[tok * 3 + 1]; fr = f1[tid - 12]; }
    else               { coord = coords[tok * 3 + 2]; fr = f2[tid - 22]; }
    float arg = 1.5707963267948966f * coord * fr;
    float s, c;
    sincosf(arg, &s, &c);
    tab[tok * 32 + tid] = make_float2(c, s);
}

// ---------------------------------------------------------------------------
// Fused bias precompute (raw masks, bf16 output)
// ---------------------------------------------------------------------------
__global__ void __launch_bounds__(576)
bias_kernel(const float* __restrict__ cq, const float* __restrict__ ck,
            const void* __restrict__ qmr, const void* __restrict__ kmr,
            __nv_bfloat16* __restrict__ E)
{
    __shared__ float ky[NK_], kx[NK_];
    __shared__ unsigned char kbad[NK_];
    __shared__ float qy8[8], qx8[8];
    __shared__ unsigned char qbad[8];
    const int f = blockIdx.y, k = threadIdx.x;
    const int ki = f * NK_ + k;
    const int mq = g_mask_mode[0], mk = g_mask_mode[1];
    ky[k]  = ck[ki * 3 + 1];
    kx[k]  = ck[ki * 3 + 2];
    kbad[k] = mask_at(kmr, ki, mk) ? 1 : 0;
    if (threadIdx.x < 8) {
        int q = blockIdx.x * 8 + threadIdx.x;
        int qi = f * NQ_ + q;
        qy8[threadIdx.x] = cq[qi * 3 + 1];
        qx8[threadIdx.x] = cq[qi * 3 + 2];
        qbad[threadIdx.x] = mask_at(qmr, qi, mq) ? 1 : 0;
    }
    __syncthreads();
    #pragma unroll
    for (int r = 0; r < 8; r++) {
        int q = blockIdx.x * 8 + r;
        float dy = qy8[r] - ky[k];
        float dx = qx8[r] - kx[k];
        float dist = sqrtf(dy * dy + dx * dx);
        bool bad = qbad[r] || kbad[k] || (dist > 0.5f);
        E[(size_t)(f * NQ_ + q) * NK_ + k] =
            __float2bfloat16(bad ? -3.0e38f : __expf(-10.f * dist));
    }
}

// ---------------------------------------------------------------------------
// HMMA GEMM, 1-pass fp16: C = rn(A) rn(B)^T + bias, fused epilogues.
// MODE 0: fp32 out (+bias)              [Wo]
// MODE 2: rope + fp16 out               [Q, K]
// MODE 4: fp16 transposed out -> V^T    [V]
// ---------------------------------------------------------------------------
#define TILE_B 10240
#define STG    (2 * TILE_B)
#define NCH    32

template<int MODE>
__global__ void __launch_bounds__(128, 2)
gemm_mma(const __half* __restrict__ Ah, const __half* __restrict__ Bh,
         const float* __restrict__ bias,
         float* __restrict__ C, __half* __restrict__ O1,
         const float2* __restrict__ rtab)
{
    extern __shared__ char dsm[];
    const uint32_t sbase = smem_u32(dsm);

    const int tid  = threadIdx.x;
    const int wid  = tid >> 5;
    const int lane = tid & 31;
    const int m0 = blockIdx.y * 128;
    const int n0 = blockIdx.x * 128;
    const int wm = (wid & 1) * 64;
    const int wn = (wid >> 1) * 64;

    float acc[4][8][4];
    #pragma unroll
    for (int mt = 0; mt < 4; mt++)
        #pragma unroll
        for (int nt = 0; nt < 8; nt++)
            #pragma unroll
            for (int r = 0; r < 4; r++) acc[mt][nt][r] = 0.f;

    int l_tl[8], l_row[8], l_c[8];
    #pragma unroll
    for (int j = 0; j < 8; j++) {
        int i = tid + j * 128;
        l_tl[j]  = i >> 9;
        l_row[j] = (i & 511) >> 2;
        l_c[j]   = i & 3;
    }

    auto issue_load = [&](int ch, int buf) {
        const int k0 = ch * 32;
        #pragma unroll
        for (int j = 0; j < 8; j++) {
            const __half* g = l_tl[j]
                ? Bh + (size_t)(n0 + l_row[j]) * GK + k0 + l_c[j] * 8
                : Ah + (size_t)(m0 + l_row[j]) * GK + k0 + l_c[j] * 8;
            uint32_t s = sbase + buf * STG + l_tl[j] * TILE_B
                       + l_row[j] * 80 + l_c[j] * 16;
            cp16(s, g);
        }
        cp_commit();
    };

    issue_load(0, 0);
    issue_load(1, 1);

    for (int ch = 0; ch < NCH; ch++) {
        if (ch == NCH - 1) cp_wait0(); else cp_wait1();
        __syncthreads();
        if (ch + 2 < NCH) issue_load(ch + 2, (ch + 2) % 3);

        const uint32_t hbase = sbase + (ch % 3) * STG;
        const uint32_t bbase = hbase + TILE_B;

        #pragma unroll
        for (int ks = 0; ks < 2; ks++) {
            uint32_t b[8][2];
            #pragma unroll
            for (int np = 0; np < 4; np++) {
                uint32_t addr = bbase
                    + (wn + np * 16 + (lane & 7) + ((lane >> 4) & 1) * 8) * 80
                    + ((lane >> 3) & 1) * 16 + ks * 32;
                uint32_t r[4];
                ldm_x4(r, addr);
                b[np * 2][0] = r[0];     b[np * 2][1] = r[1];
                b[np * 2 + 1][0] = r[2]; b[np * 2 + 1][1] = r[3];
            }
            uint32_t a[4][4];
            #pragma unroll
            for (int mt = 0; mt < 4; mt++) {
                uint32_t addr = hbase + (wm + mt * 16 + (lane & 15)) * 80
                              + (lane >> 4) * 16 + ks * 32;
                ldm_x4(a[mt], addr);
            }
            #pragma unroll
            for (int mt = 0; mt < 4; mt++)
                #pragma unroll
                for (int nt = 0; nt < 8; nt++)
                    mma_f16(acc[mt][nt], a[mt], b[nt]);
        }
    }

    // Stage rope table for this m-tile into (now free) smem.
    float2* st = (float2*)dsm;
    if (MODE == 2) {
        __syncthreads();
        for (int i = tid; i < 128 * 32; i += 128)
            st[i] = rtab[(size_t)(m0 + (i >> 5)) * 32 + (i & 31)];
        __syncthreads();
    }
    __half* sT = (__half*)dsm;   // MODE 4: 128 x 130 fp16 staging
    if (MODE == 4) __syncthreads();

    const int cb_loc = wn + (lane & 3) * 2;
    const int cbase = n0 + cb_loc;
    float bv[8][2];
    #pragma unroll
    for (int nt = 0; nt < 8; nt++) {
        bv[nt][0] = bias[cbase + nt * 8];
        bv[nt][1] = bias[cbase + nt * 8 + 1];
    }

    #pragma unroll
    for (int mt = 0; mt < 4; mt++) {
        int rl0 = wm + mt * 16 + (lane >> 2);
        #pragma unroll
        for (int nt = 0; nt < 8; nt++) {
            int col = cbase + nt * 8;
            float v0 = acc[mt][nt][0] + bv[nt][0];
            float v1 = acc[mt][nt][1] + bv[nt][1];
            float v2 = acc[mt][nt][2] + bv[nt][0];
            float v3 = acc[mt][nt][3] + bv[nt][1];
            if (MODE == 0) {
                *(float2*)&C[(size_t)(m0 + rl0) * GN + col]     = make_float2(v0, v1);
                *(float2*)&C[(size_t)(m0 + rl0 + 8) * GN + col] = make_float2(v2, v3);
            } else if (MODE == 4) {
                int cl = cb_loc + nt * 8;
                *(__half2*)&sT[rl0 * 130 + cl]       = __floats2half2_rn(v0, v1);
                *(__half2*)&sT[(rl0 + 8) * 130 + cl] = __floats2half2_rn(v2, v3);
            } else {
                int j = ((cb_loc + nt * 8) & 63) >> 1;
                float2 cs0 = st[rl0 * 32 + j];
                float2 cs1 = st[(rl0 + 8) * 32 + j];
                float y0 = v0 * cs0.x - v1 * cs0.y;
                float y1 = v1 * cs0.x + v0 * cs0.y;
                float y2 = v2 * cs1.x - v3 * cs1.y;
                float y3 = v3 * cs1.x + v2 * cs1.y;
                ((__half2*)O1)[((size_t)(m0 + rl0) * D_ + col) >> 1]     = __floats2half2_rn(y0, y1);
                ((__half2*)O1)[((size_t)(m0 + rl0 + 8) * D_ + col) >> 1] = __floats2half2_rn(y2, y3);
            }
        }
    }

    if (MODE == 4) {
        __syncthreads();
        // drain transposed: d-local rows, key pairs along lanes (coalesced)
        for (int idx = tid; idx < 128 * 64; idx += 128) {
            int dl = idx >> 6, kp = idx & 63;
            int tok = m0 + 2 * kp;
            int f = tok / NQ_;
            int key = tok - f * NQ_;
            int gd = n0 + dl;
            int h = gd >> 6, dh = gd & 63;
            __half a = sT[(2 * kp) * 130 + dl];
            __half b = sT[(2 * kp + 1) * 130 + dl];
            size_t oi = (((size_t)(f * 16 + h) * 64 + dh) * NK_ + key) >> 1;
            ((__half2*)O1)[oi] = __halves2half2(a, b);
        }
    }
}

// ---------------------------------------------------------------------------
// HMMA flash attention: S = Q K^T (1-pass), O = P V (1-pass).
// ---------------------------------------------------------------------------
#define ATT_SMEM 27648

__global__ void __launch_bounds__(128)
attn_mma(const __half* __restrict__ Qh,
         const __half* __restrict__ Kr, const __half* __restrict__ Vtr,
         const __nv_bfloat16* __restrict__ E, const float* __restrict__ alpha,
         __half* __restrict__ Yh)
{
    extern __shared__ char sm[];
    uint32_t* sK = (uint32_t*)sm;
    uint32_t* sV = (uint32_t*)(sm + 9216);
    __nv_bfloat16* sE = (__nv_bfloat16*)(sm + 18432);

    const int tid = threadIdx.x;
    const int w = tid >> 5, lane = tid & 31;
    const int c = lane & 3, rg = lane >> 2;
    const int qb = blockIdx.x, fh = blockIdx.y;
    const int f = fh >> 4, h = fh & 15;
    const int tok0 = f * NQ_;
    const int q0 = qb * 64;
    const float alph = alpha[h];
    const int rl = 16 * w + rg;

    for (int i = tid; i < 512; i += 128) {
        int row = i >> 3, c16 = i & 7;
        size_t go = (size_t)(tok0 + q0 + row) * D_ + h * 64 + c16 * 8;
        *(uint4*)(sK + row * 36 + c16 * 4) = *(const uint4*)(Qh + go);
    }
    __syncthreads();
    uint32_t qhF[4][4];
    #pragma unroll
    for (int s = 0; s < 4; s++) {
        qhF[s][0] = sK[rl * 36 + 8 * s + c];
        qhF[s][1] = sK[(rl + 8) * 36 + 8 * s + c];
        qhF[s][2] = sK[rl * 36 + 8 * s + c + 4];
        qhF[s][3] = sK[(rl + 8) * 36 + 8 * s + c + 4];
    }
    __syncthreads();

    float o[8][4];
    #pragma unroll
    for (int n = 0; n < 8; n++)
        #pragma unroll
        for (int r = 0; r < 4; r++) o[n][r] = 0.f;
    float m0r = -3.0e38f, m1r = -3.0e38f, l0r = 0.f, l1r = 0.f;

    for (int kt = 0; kt < 9; kt++) {
        const int k0 = kt * 64;
        for (int i = tid; i < 512; i += 128) {
            int row = i >> 3, c16 = i & 7;
            size_t go = (size_t)(tok0 + k0 + row) * D_ + h * 64 + c16 * 8;
            *(uint4*)(sK + row * 36 + c16 * 4) = *(const uint4*)(Kr + go);
            size_t vo = (size_t)fh * (64 * NK_) + (size_t)row * NK_ + k0 + c16 * 8;
            *(uint4*)(sV + row * 36 + c16 * 4) = *(const uint4*)(Vtr + vo);
        }
        for (int i = tid; i < 512; i += 128) {
            int row = i >> 3, c8 = i & 7;
            *(uint4*)(sE + row * 72 + c8 * 8) =
                *(const uint4*)(E + (size_t)(tok0 + q0 + row) * NK_ + k0 + c8 * 8);
        }
        __syncthreads();

        float s[8][4];
        #pragma unroll
        for (int n = 0; n < 8; n++)
            #pragma unroll
            for (int r = 0; r < 4; r++) s[n][r] = 0.f;
        #pragma unroll
        for (int st = 0; st < 4; st++) {
            #pragma unroll
            for (int n = 0; n < 8; n++) {
                int bi = (8 * n + rg) * 36 + 8 * st + c;
                uint32_t bh[2] = { sK[bi], sK[bi + 4] };
                mma_f16(s[n], qhF[st], bh);
            }
        }

        float mn0 = m0r, mn1 = m1r;
        #pragma unroll
        for (int n = 0; n < 8; n++) {
            float2 e0 = __bfloat1622float2(
                *(__nv_bfloat162*)(sE + rl * 72 + 8 * n + 2 * c));
            float2 e1 = __bfloat1622float2(
                *(__nv_bfloat162*)(sE + (rl + 8) * 72 + 8 * n + 2 * c));
            s[n][0] = (e0.x < 0.f) ? NEGBIG : fmaf(s[n][0], 0.125f, alph * e0.x);
            s[n][1] = (e0.y < 0.f) ? NEGBIG : fmaf(s[n][1], 0.125f, alph * e0.y);
            s[n][2] = (e1.x < 0.f) ? NEGBIG : fmaf(s[n][2], 0.125f, alph * e1.x);
            s[n][3] = (e1.y < 0.f) ? NEGBIG : fmaf(s[n][3], 0.125f, alph * e1.y);
            mn0 = fmaxf(mn0, fmaxf(s[n][0], s[n][1]));
            mn1 = fmaxf(mn1, fmaxf(s[n][2], s[n][3]));
        }
        mn0 = fmaxf(mn0, __shfl_xor_sync(0xffffffffu, mn0, 1));
        mn0 = fmaxf(mn0, __shfl_xor_sync(0xffffffffu, mn0, 2));
        mn1 = fmaxf(mn1, __shfl_xor_sync(0xffffffffu, mn1, 1));
        mn1 = fmaxf(mn1, __shfl_xor_sync(0xffffffffu, mn1, 2));
        float f0 = ex2((m0r - mn0) * LOG2E);
        float f1 = ex2((m1r - mn1) * LOG2E);
        m0r = mn0; m1r = mn1;

        float rs0 = 0.f, rs1 = 0.f;
        uint32_t phL[8], phH[8];
        #pragma unroll
        for (int n = 0; n < 8; n++) {
            float p0 = ex2((s[n][0] - mn0) * LOG2E);
            float p1 = ex2((s[n][1] - mn0) * LOG2E);
            float p2 = ex2((s[n][2] - mn1) * LOG2E);
            float p3 = ex2((s[n][3] - mn1) * LOG2E);
            rs0 += p0 + p1;
            rs1 += p2 + p3;
            o[n][0] *= f0; o[n][1] *= f0; o[n][2] *= f1; o[n][3] *= f1;
            __half2 bL = __floats2half2_rn(p0, p1);
            phL[n] = *(uint32_t*)&bL;
            __half2 bH = __floats2half2_rn(p2, p3);
            phH[n] = *(uint32_t*)&bH;
        }
        rs0 += __shfl_xor_sync(0xffffffffu, rs0, 1);
        rs0 += __shfl_xor_sync(0xffffffffu, rs0, 2);
        rs1 += __shfl_xor_sync(0xffffffffu, rs1, 1);
        rs1 += __shfl_xor_sync(0xffffffffu, rs1, 2);
        l0r = l0r * f0 + rs0;
        l1r = l1r * f1 + rs1;

        #pragma unroll
        for (int st = 0; st < 4; st++) {
            uint32_t ah[4] = { phL[2 * st], phH[2 * st], phL[2 * st + 1], phH[2 * st + 1] };
            #pragma unroll
            for (int n = 0; n < 8; n++) {
                int bi = (8 * n + rg) * 36 + 8 * st + c;
                uint32_t vh[2] = { sV[bi], sV[bi + 4] };
                mma_f16(o[n], ah, vh);
            }
        }
        __syncthreads();
    }

    float i0 = 1.f / l0r, i1 = 1.f / l1r;
    #pragma unroll
    for (int n = 0; n < 8; n++) {
        size_t e0 = ((size_t)(tok0 + q0 + rl) * D_ + h * 64 + 8 * n + 2 * c) >> 1;
        size_t e1 = ((size_t)(tok0 + q0 + rl + 8) * D_ + h * 64 + 8 * n + 2 * c) >> 1;
        ((__half2*)Yh)[e0] = __floats2half2_rn(o[n][0] * i0, o[n][1] * i0);
        ((__half2*)Yh)[e1] = __floats2half2_rn(o[n][2] * i1, o[n][3] * i1);
    }
}

// ---------------------------------------------------------------------------
extern "C" void kernel_launch(void* const* d_in, const int* in_sizes, int n_in,
                              void* d_out, int out_size)
{
    (void)in_sizes; (void)n_in; (void)out_size;

    const float*   q_tokens  = (const float*)d_in[0];
    const float*   kv_tokens = (const float*)d_in[1];
    const float*   coords_q  = (const float*)d_in[2];
    const float*   coords_k  = (const float*)d_in[3];
    const void*    q_pad     = d_in[4];
    const void*    kv_pad    = d_in[5];
    const float*   Wq = (const float*)d_in[6];
    const float*   bq = (const float*)d_in[7];
    const float*   Wk = (const float*)d_in[8];
    const float*   bk = (const float*)d_in[9];
    const float*   Wv = (const float*)d_in[10];
    const float*   bv = (const float*)d_in[11];
    const float*   Wo = (const float*)d_in[12];
    const float*   bo = (const float*)d_in[13];
    const float*   alpha = (const float*)d_in[14];
    const float*   f0 = (const float*)d_in[15];
    const float*   f1 = (const float*)d_in[16];
    const float*   f2 = (const float*)d_in[17];
    float* out = (float*)d_out;

    __nv_bfloat16 *Eb;
    float2 *rtq, *rtk;
    cudaGetSymbolAddress((void**)&Eb, g_E);
    cudaGetSymbolAddress((void**)&rtq, g_rt);
    rtk = rtq + TOK * 32;

    __half *x16q, *x16kv, *yhi, *W16, *aQh, *aKr, *vtr;
    cudaGetSymbolAddress((void**)&x16q, g_x16);
    x16kv = x16q + TOK * D_;
    cudaGetSymbolAddress((void**)&yhi,  g_yhi);
    cudaGetSymbolAddress((void**)&W16, g_W16);
    cudaGetSymbolAddress((void**)&aQh, g_aQh);
    cudaGetSymbolAddress((void**)&aKr, g_aKr);
    cudaGetSymbolAddress((void**)&vtr, g_vtr);
    __half *Wqh = W16, *Wkh = W16 + D_ * D_, *Wvh = W16 + 2 * D_ * D_,
           *Woh = W16 + 3 * D_ * D_;

    const float** rsrc;
    __half** rdst;
    cudaGetSymbolAddress((void**)&rsrc, g_round_src);
    cudaGetSymbolAddress((void**)&rdst, g_round_dst);

    const int gemm_smem = 3 * STG;  // 61440
    cudaFuncSetAttribute(gemm_mma<0>, cudaFuncAttributeMaxDynamicSharedMemorySize, gemm_smem);
    cudaFuncSetAttribute(gemm_mma<2>, cudaFuncAttributeMaxDynamicSharedMemorySize, gemm_smem);
    cudaFuncSetAttribute(gemm_mma<4>, cudaFuncAttributeMaxDynamicSharedMemorySize, gemm_smem);
    cudaFuncSetAttribute(attn_mma, cudaFuncAttributeMaxDynamicSharedMemorySize, ATT_SMEM);

    // masks + pointer tables + fused bias + rope tables
    detect_mask_kernel<<<1, 256>>>((const unsigned*)q_pad, (const unsigned*)kv_pad,
                                   TOK / 4, Wq, Wk, Wv, Wo, q_tokens, kv_tokens);
    bias_kernel<<<dim3(NQ_ / 8, 8), NK_>>>(coords_q, coords_k, q_pad, kv_pad, Eb);
    ropetab_kernel<<<dim3(TOK / 8, 2), 256>>>(coords_q, coords_k, f0, f1, f2, rtq, rtk);

    // fp16 single roundings (batched)
    const int ntok4 = TOK * D_ / 4, nw4 = D_ * D_ / 4;
    round_h_batch<<<dim3((nw4 + 255) / 256, 4), 256>>>(rsrc, rdst, nw4);
    round_h_batch<<<dim3((ntok4 + 255) / 256, 2), 256>>>(rsrc + 4, rdst + 4, ntok4);

    dim3 gg(GN / 128, TOK / 128);
    gemm_mma<2><<<gg, 128, gemm_smem>>>(x16q,  Wqh, bq, nullptr, aQh, rtq);
    gemm_mma<2><<<gg, 128, gemm_smem>>>(x16kv, Wkh, bk, nullptr, aKr, rtk);
    gemm_mma<4><<<gg, 128, gemm_smem>>>(x16kv, Wvh, bv, nullptr, vtr, nullptr);

    attn_mma<<<dim3(9, 128), 128, ATT_SMEM>>>(aQh, aKr, vtr, Eb, alpha, yhi);

    gemm_mma<0><<<gg, 128, gemm_smem>>>(yhi, Woh, bo, out, nullptr, nullptr);
}

// round 14
// speedup vs baseline: 1.8016x; 1.0117x over previous
#include <cuda_runtime.h>
#include <cuda_bf16.h>
#include <cuda_fp16.h>
#include <cstdint>
#include <cstddef>
#include <math.h>

// Problem constants
#define B_   2
#define T_   4
#define NQ_  576
#define NK_  576
#define D_   1024
#define H_   16
#define DH_  64
#define TOK  (B_*T_*NQ_)
#define NEGBIG (-1.7014118e38f)
#define LOG2E 1.4426950408889634f

#define GK 1024
#define GN 1024

// Scratch (device globals; no dynamic allocation allowed)
__device__ int   g_mask_mode[2];
__device__ __nv_bfloat16 g_E[8 * NQ_ * NK_];
__device__ float2 g_rt[2][TOK * 32];   // cos/sin tables: [0]=q, [1]=k

// fp16 operands (all single-rounded)
__device__ __half g_x16[2][TOK * D_];  // [0]=q_tokens, [1]=kv_tokens
__device__ __half g_yhi[TOK * D_];
__device__ __half g_W16[4][D_ * D_];   // Wq, Wk, Wv, Wo

// attention operands (fp16): Q (rope'd), K (rope'd), V^T
__device__ __half g_aQh[TOK * D_];
__device__ __half g_aKr[TOK * D_];
__device__ __half g_vtr[128 * 64 * NK_];

__device__ const float* g_round_src[6];
__device__ __half*      g_round_dst[6];

// ---------------------------------------------------------------------------
// Family-portable PTX helpers
// ---------------------------------------------------------------------------
__device__ __forceinline__ uint32_t smem_u32(const void* p) {
    uint32_t a;
    asm("{ .reg .u64 t; cvta.to.shared.u64 t, %1; cvt.u32.u64 %0, t; }"
        : "=r"(a) : "l"(p));
    return a;
}
__device__ __forceinline__ void cp16(uint32_t s, const void* g) {
    asm volatile("cp.async.cg.shared.global [%0], [%1], 16;"
                 :: "r"(s), "l"(g) : "memory");
}
__device__ __forceinline__ void cp_commit() {
    asm volatile("cp.async.commit_group;" ::: "memory");
}
__device__ __forceinline__ void cp_wait1() {
    asm volatile("cp.async.wait_group 1;" ::: "memory");
}
__device__ __forceinline__ void cp_wait0() {
    asm volatile("cp.async.wait_group 0;" ::: "memory");
}
__device__ __forceinline__ void ldm_x4(uint32_t* r, uint32_t addr) {
    asm volatile("ldmatrix.sync.aligned.m8n8.x4.shared.b16 {%0,%1,%2,%3}, [%4];"
                 : "=r"(r[0]), "=r"(r[1]), "=r"(r[2]), "=r"(r[3]) : "r"(addr));
}
__device__ __forceinline__ void mma_f16(float* d, const uint32_t* a, const uint32_t* b) {
    asm volatile(
        "mma.sync.aligned.m16n8k16.row.col.f32.f16.f16.f32 "
        "{%0,%1,%2,%3}, {%4,%5,%6,%7}, {%8,%9}, {%0,%1,%2,%3};"
        : "+f"(d[0]), "+f"(d[1]), "+f"(d[2]), "+f"(d[3])
        : "r"(a[0]), "r"(a[1]), "r"(a[2]), "r"(a[3]), "r"(b[0]), "r"(b[1]));
}
__device__ __forceinline__ float ex2(float x) {
    float y;
    asm("ex2.approx.f32 %0, %1;" : "=f"(y) : "f"(x));
    return y;
}

// batched fp32 -> fp16 rounding, MLP=4: each thread handles 4 float4 slots
__global__ void round_h_batch(const float* const* __restrict__ srcs,
                              __half* const* __restrict__ dsts, int n4)
{
    const float* x = srcs[blockIdx.y];
    __half* h = dsts[blockIdx.y];
    int base = blockIdx.x * 1024 + threadIdx.x;
    float4 v[4];
    int idx[4];
    #pragma unroll
    for (int j = 0; j < 4; j++) {
        idx[j] = base + j * 256;
        if (idx[j] < n4) v[j] = ((const float4*)x)[idx[j]];
    }
    #pragma unroll
    for (int j = 0; j < 4; j++) {
        if (idx[j] < n4) {
            ((__half2*)h)[2*idx[j]]   = __floats2half2_rn(v[j].x, v[j].y);
            ((__half2*)h)[2*idx[j]+1] = __floats2half2_rn(v[j].z, v[j].w);
        }
    }
}

// ---------------------------------------------------------------------------
// Mask dtype detection (+ pointer table setup on thread 0)
// ---------------------------------------------------------------------------
__global__ void detect_mask_kernel(const unsigned* __restrict__ qm,
                                   const unsigned* __restrict__ km, int nints,
                                   const float* s0, const float* s1,
                                   const float* s2, const float* s3,
                                   const float* s4, const float* s5)
{
    if (threadIdx.x == 0) {
        g_round_src[0] = s0; g_round_src[1] = s1; g_round_src[2] = s2;
        g_round_src[3] = s3; g_round_src[4] = s4; g_round_src[5] = s5;
        g_round_dst[0] = g_W16[0]; g_round_dst[1] = g_W16[1];
        g_round_dst[2] = g_W16[2]; g_round_dst[3] = g_W16[3];
        g_round_dst[4] = g_x16[0]; g_round_dst[5] = g_x16[1];
    }
    __shared__ int s_i, s_f;
    for (int b = 0; b < 2; b++) {
        if (threadIdx.x == 0) { s_i = 1; s_f = 1; }
        __syncthreads();
        const unsigned* p = b ? km : qm;
        int li = 1, lf = 1;
        for (int i = threadIdx.x; i < nints; i += blockDim.x) {
            unsigned v = p[i];
            if (v > 1u) li = 0;
            if (v != 0u && v != 0x3f800000u) lf = 0;
        }
        if (!li) atomicAnd(&s_i, 0);
        if (!lf) atomicAnd(&s_f, 0);
        __syncthreads();
        if (threadIdx.x == 0)
            g_mask_mode[b] = s_i ? 1 : (s_f ? 2 : 0);
        __syncthreads();
    }
}

__device__ __forceinline__ bool mask_at(const void* p, int i, int mode) {
    if (mode == 1) return ((const int*)p)[i] != 0;
    if (mode == 2) return ((const float*)p)[i] != 0.f;
    return ((const unsigned char*)p)[i] != 0;
}

// ---------------------------------------------------------------------------
// RoPE cos/sin table: 256 threads = 8 tokens/block; grid (TOK/8, 2)
// ---------------------------------------------------------------------------
__global__ void ropetab_kernel(const float* __restrict__ cq,
                               const float* __restrict__ ck,
                               const float* __restrict__ f0,
                               const float* __restrict__ f1,
                               const float* __restrict__ f2,
                               float2* __restrict__ tq,
                               float2* __restrict__ tk)
{
    const int tok = blockIdx.x * 8 + (threadIdx.x >> 5);
    const int tid = threadIdx.x & 31;
    const float* coords = blockIdx.y ? ck : cq;
    float2* tab = blockIdx.y ? tk : tq;
    float coord, fr;
    if (tid < 12)      { coord = coords[tok * 3 + 0]; fr = f0[tid]; }
    else if (tid < 22) { coord = coords[tok * 3 + 1]; fr = f1[tid - 12]; }
    else               { coord = coords[tok * 3 + 2]; fr = f2[tid - 22]; }
    float arg = 1.5707963267948966f * coord * fr;
    float s, c;
    sincosf(arg, &s, &c);
    tab[tok * 32 + tid] = make_float2(c, s);
}

// ---------------------------------------------------------------------------
// Fused bias precompute (raw masks, bf16 output)
// ---------------------------------------------------------------------------
__global__ void __launch_bounds__(576)
bias_kernel(const float* __restrict__ cq, const float* __restrict__ ck,
            const void* __restrict__ qmr, const void* __restrict__ kmr,
            __nv_bfloat16* __restrict__ E)
{
    __shared__ float ky[NK_], kx[NK_];
    __shared__ unsigned char kbad[NK_];
    __shared__ float qy8[8], qx8[8];
    __shared__ unsigned char qbad[8];
    const int f = blockIdx.y, k = threadIdx.x;
    const int ki = f * NK_ + k;
    const int mq = g_mask_mode[0], mk = g_mask_mode[1];
    ky[k]  = ck[ki * 3 + 1];
    kx[k]  = ck[ki * 3 + 2];
    kbad[k] = mask_at(kmr, ki, mk) ? 1 : 0;
    if (threadIdx.x < 8) {
        int q = blockIdx.x * 8 + threadIdx.x;
        int qi = f * NQ_ + q;
        qy8[threadIdx.x] = cq[qi * 3 + 1];
        qx8[threadIdx.x] = cq[qi * 3 + 2];
        qbad[threadIdx.x] = mask_at(qmr, qi, mq) ? 1 : 0;
    }
    __syncthreads();
    #pragma unroll
    for (int r = 0; r < 8; r++) {
        int q = blockIdx.x * 8 + r;
        float dy = qy8[r] - ky[k];
        float dx = qx8[r] - kx[k];
        float dist = sqrtf(dy * dy + dx * dx);
        bool bad = qbad[r] || kbad[k] || (dist > 0.5f);
        E[(size_t)(f * NQ_ + q) * NK_ + k] =
            __float2bfloat16(bad ? -3.0e38f : __expf(-10.f * dist));
    }
}

// ---------------------------------------------------------------------------
// Merged Q/K/V HMMA GEMM (grid.z selects operands + epilogue):
//   z=0: aQh = rope(x16q @ Wq^T + bq)      (fp16)
//   z=1: aKr = rope(x16kv @ Wk^T + bk)     (fp16)
//   z=2: vtr = transpose(x16kv @ Wv^T+bv)  (fp16, V^T layout)
// ---------------------------------------------------------------------------
#define TILE_B 10240
#define STG    (2 * TILE_B)
#define NCH    32

__global__ void __launch_bounds__(128, 2)
gemm_qkv(const __half* __restrict__ x16q, const __half* __restrict__ x16kv,
         const __half* __restrict__ Wqh, const __half* __restrict__ Wkh,
         const __half* __restrict__ Wvh,
         const float* __restrict__ bq, const float* __restrict__ bk,
         const float* __restrict__ bv,
         __half* __restrict__ aQh, __half* __restrict__ aKr,
         __half* __restrict__ vtr,
         const float2* __restrict__ rtq, const float2* __restrict__ rtk)
{
    extern __shared__ char dsm[];
    const uint32_t sbase = smem_u32(dsm);

    const int z = blockIdx.z;
    const __half* Ah = (z == 0) ? x16q : x16kv;
    const __half* Bh = (z == 0) ? Wqh : (z == 1) ? Wkh : Wvh;
    const float* bias = (z == 0) ? bq : (z == 1) ? bk : bv;
    __half* O1 = (z == 0) ? aQh : (z == 1) ? aKr : vtr;
    const float2* rtab = (z == 0) ? rtq : rtk;

    const int tid  = threadIdx.x;
    const int wid  = tid >> 5;
    const int lane = tid & 31;
    const int m0 = blockIdx.y * 128;
    const int n0 = blockIdx.x * 128;
    const int wm = (wid & 1) * 64;
    const int wn = (wid >> 1) * 64;

    float acc[4][8][4];
    #pragma unroll
    for (int mt = 0; mt < 4; mt++)
        #pragma unroll
        for (int nt = 0; nt < 8; nt++)
            #pragma unroll
            for (int r = 0; r < 4; r++) acc[mt][nt][r] = 0.f;

    int l_tl[8], l_row[8], l_c[8];
    #pragma unroll
    for (int j = 0; j < 8; j++) {
        int i = tid + j * 128;
        l_tl[j]  = i >> 9;
        l_row[j] = (i & 511) >> 2;
        l_c[j]   = i & 3;
    }

    auto issue_load = [&](int ch, int buf) {
        const int k0 = ch * 32;
        #pragma unroll
        for (int j = 0; j < 8; j++) {
            const __half* g = l_tl[j]
                ? Bh + (size_t)(n0 + l_row[j]) * GK + k0 + l_c[j] * 8
                : Ah + (size_t)(m0 + l_row[j]) * GK + k0 + l_c[j] * 8;
            uint32_t s = sbase + buf * STG + l_tl[j] * TILE_B
                       + l_row[j] * 80 + l_c[j] * 16;
            cp16(s, g);
        }
        cp_commit();
    };

    issue_load(0, 0);
    issue_load(1, 1);

    for (int ch = 0; ch < NCH; ch++) {
        if (ch == NCH - 1) cp_wait0(); else cp_wait1();
        __syncthreads();
        if (ch + 2 < NCH) issue_load(ch + 2, (ch + 2) % 3);

        const uint32_t hbase = sbase + (ch % 3) * STG;
        const uint32_t bbase = hbase + TILE_B;

        #pragma unroll
        for (int ks = 0; ks < 2; ks++) {
            uint32_t b[8][2];
            #pragma unroll
            for (int np = 0; np < 4; np++) {
                uint32_t addr = bbase
                    + (wn + np * 16 + (lane & 7) + ((lane >> 4) & 1) * 8) * 80
                    + ((lane >> 3) & 1) * 16 + ks * 32;
                uint32_t r[4];
                ldm_x4(r, addr);
                b[np * 2][0] = r[0];     b[np * 2][1] = r[1];
                b[np * 2 + 1][0] = r[2]; b[np * 2 + 1][1] = r[3];
            }
            uint32_t a[4][4];
            #pragma unroll
            for (int mt = 0; mt < 4; mt++) {
                uint32_t addr = hbase + (wm + mt * 16 + (lane & 15)) * 80
                              + (lane >> 4) * 16 + ks * 32;
                ldm_x4(a[mt], addr);
            }
            #pragma unroll
            for (int mt = 0; mt < 4; mt++)
                #pragma unroll
                for (int nt = 0; nt < 8; nt++)
                    mma_f16(acc[mt][nt], a[mt], b[nt]);
        }
    }

    const int cb_loc = wn + (lane & 3) * 2;
    const int cbase = n0 + cb_loc;
    float bv_[8][2];
    #pragma unroll
    for (int nt = 0; nt < 8; nt++) {
        bv_[nt][0] = bias[cbase + nt * 8];
        bv_[nt][1] = bias[cbase + nt * 8 + 1];
    }

    if (z < 2) {
        // rope epilogue
        float2* st = (float2*)dsm;
        __syncthreads();
        for (int i = tid; i < 128 * 32; i += 128)
            st[i] = rtab[(size_t)(m0 + (i >> 5)) * 32 + (i & 31)];
        __syncthreads();

        #pragma unroll
        for (int mt = 0; mt < 4; mt++) {
            int rl0 = wm + mt * 16 + (lane >> 2);
            #pragma unroll
            for (int nt = 0; nt < 8; nt++) {
                int col = cbase + nt * 8;
                float v0 = acc[mt][nt][0] + bv_[nt][0];
                float v1 = acc[mt][nt][1] + bv_[nt][1];
                float v2 = acc[mt][nt][2] + bv_[nt][0];
                float v3 = acc[mt][nt][3] + bv_[nt][1];
                int j = ((cb_loc + nt * 8) & 63) >> 1;
                float2 cs0 = st[rl0 * 32 + j];
                float2 cs1 = st[(rl0 + 8) * 32 + j];
                float y0 = v0 * cs0.x - v1 * cs0.y;
                float y1 = v1 * cs0.x + v0 * cs0.y;
                float y2 = v2 * cs1.x - v3 * cs1.y;
                float y3 = v3 * cs1.x + v2 * cs1.y;
                ((__half2*)O1)[((size_t)(m0 + rl0) * D_ + col) >> 1]     = __floats2half2_rn(y0, y1);
                ((__half2*)O1)[((size_t)(m0 + rl0 + 8) * D_ + col) >> 1] = __floats2half2_rn(y2, y3);
            }
        }
    } else {
        // V: transpose epilogue via smem staging
        __half* sT = (__half*)dsm;
        __syncthreads();
        #pragma unroll
        for (int mt = 0; mt < 4; mt++) {
            int rl0 = wm + mt * 16 + (lane >> 2);
            #pragma unroll
            for (int nt = 0; nt < 8; nt++) {
                int cl = cb_loc + nt * 8;
                float v0 = acc[mt][nt][0] + bv_[nt][0];
                float v1 = acc[mt][nt][1] + bv_[nt][1];
                float v2 = acc[mt][nt][2] + bv_[nt][0];
                float v3 = acc[mt][nt][3] + bv_[nt][1];
                *(__half2*)&sT[rl0 * 130 + cl]       = __floats2half2_rn(v0, v1);
                *(__half2*)&sT[(rl0 + 8) * 130 + cl] = __floats2half2_rn(v2, v3);
            }
        }
        __syncthreads();
        for (int idx = tid; idx < 128 * 64; idx += 128) {
            int dl = idx >> 6, kp = idx & 63;
            int tok = m0 + 2 * kp;
            int f = tok / NQ_;
            int key = tok - f * NQ_;
            int gd = n0 + dl;
            int h = gd >> 6, dh = gd & 63;
            __half a = sT[(2 * kp) * 130 + dl];
            __half b = sT[(2 * kp + 1) * 130 + dl];
            size_t oi = (((size_t)(f * 16 + h) * 64 + dh) * NK_ + key) >> 1;
            ((__half2*)O1)[oi] = __halves2half2(a, b);
        }
    }
}

// ---------------------------------------------------------------------------
// Wo GEMM: fp32 out (+bias)
// ---------------------------------------------------------------------------
__global__ void __launch_bounds__(128, 2)
gemm_wo(const __half* __restrict__ Ah, const __half* __restrict__ Bh,
        const float* __restrict__ bias, float* __restrict__ C)
{
    extern __shared__ char dsm[];
    const uint32_t sbase = smem_u32(dsm);

    const int tid  = threadIdx.x;
    const int wid  = tid >> 5;
    const int lane = tid & 31;
    const int m0 = blockIdx.y * 128;
    const int n0 = blockIdx.x * 128;
    const int wm = (wid & 1) * 64;
    const int wn = (wid >> 1) * 64;

    float acc[4][8][4];
    #pragma unroll
    for (int mt = 0; mt < 4; mt++)
        #pragma unroll
        for (int nt = 0; nt < 8; nt++)
            #pragma unroll
            for (int r = 0; r < 4; r++) acc[mt][nt][r] = 0.f;

    int l_tl[8], l_row[8], l_c[8];
    #pragma unroll
    for (int j = 0; j < 8; j++) {
        int i = tid + j * 128;
        l_tl[j]  = i >> 9;
        l_row[j] = (i & 511) >> 2;
        l_c[j]   = i & 3;
    }

    auto issue_load = [&](int ch, int buf) {
        const int k0 = ch * 32;
        #pragma unroll
        for (int j = 0; j < 8; j++) {
            const __half* g = l_tl[j]
                ? Bh + (size_t)(n0 + l_row[j]) * GK + k0 + l_c[j] * 8
                : Ah + (size_t)(m0 + l_row[j]) * GK + k0 + l_c[j] * 8;
            uint32_t s = sbase + buf * STG + l_tl[j] * TILE_B
                       + l_row[j] * 80 + l_c[j] * 16;
            cp16(s, g);
        }
        cp_commit();
    };

    issue_load(0, 0);
    issue_load(1, 1);

    for (int ch = 0; ch < NCH; ch++) {
        if (ch == NCH - 1) cp_wait0(); else cp_wait1();
        __syncthreads();
        if (ch + 2 < NCH) issue_load(ch + 2, (ch + 2) % 3);

        const uint32_t hbase = sbase + (ch % 3) * STG;
        const uint32_t bbase = hbase + TILE_B;

        #pragma unroll
        for (int ks = 0; ks < 2; ks++) {
            uint32_t b[8][2];
            #pragma unroll
            for (int np = 0; np < 4; np++) {
                uint32_t addr = bbase
                    + (wn + np * 16 + (lane & 7) + ((lane >> 4) & 1) * 8) * 80
                    + ((lane >> 3) & 1) * 16 + ks * 32;
                uint32_t r[4];
                ldm_x4(r, addr);
                b[np * 2][0] = r[0];     b[np * 2][1] = r[1];
                b[np * 2 + 1][0] = r[2]; b[np * 2 + 1][1] = r[3];
            }
            uint32_t a[4][4];
            #pragma unroll
            for (int mt = 0; mt < 4; mt++) {
                uint32_t addr = hbase + (wm + mt * 16 + (lane & 15)) * 80
                              + (lane >> 4) * 16 + ks * 32;
                ldm_x4(a[mt], addr);
            }
            #pragma unroll
            for (int mt = 0; mt < 4; mt++)
                #pragma unroll
                for (int nt = 0; nt < 8; nt++)
                    mma_f16(acc[mt][nt], a[mt], b[nt]);
        }
    }

    const int cbase = n0 + wn + (lane & 3) * 2;
    float bv[8][2];
    #pragma unroll
    for (int nt = 0; nt < 8; nt++) {
        bv[nt][0] = bias[cbase + nt * 8];
        bv[nt][1] = bias[cbase + nt * 8 + 1];
    }
    #pragma unroll
    for (int mt = 0; mt < 4; mt++) {
        int r0 = m0 + wm + mt * 16 + (lane >> 2);
        #pragma unroll
        for (int nt = 0; nt < 8; nt++) {
            int c = cbase + nt * 8;
            float2 v0 = { acc[mt][nt][0] + bv[nt][0], acc[mt][nt][1] + bv[nt][1] };
            float2 v1 = { acc[mt][nt][2] + bv[nt][0], acc[mt][nt][3] + bv[nt][1] };
            *(float2*)&C[(size_t)r0 * GN + c]       = v0;
            *(float2*)&C[(size_t)(r0 + 8) * GN + c] = v1;
        }
    }
}

// ---------------------------------------------------------------------------
// HMMA flash attention: S = Q K^T (1-pass), O = P V (1-pass).
// ---------------------------------------------------------------------------
#define ATT_SMEM 27648

__global__ void __launch_bounds__(128)
attn_mma(const __half* __restrict__ Qh,
         const __half* __restrict__ Kr, const __half* __restrict__ Vtr,
         const __nv_bfloat16* __restrict__ E, const float* __restrict__ alpha,
         __half* __restrict__ Yh)
{
    extern __shared__ char sm[];
    uint32_t* sK = (uint32_t*)sm;
    uint32_t* sV = (uint32_t*)(sm + 9216);
    __nv_bfloat16* sE = (__nv_bfloat16*)(sm + 18432);

    const int tid = threadIdx.x;
    const int w = tid >> 5, lane = tid & 31;
    const int c = lane & 3, rg = lane >> 2;
    const int qb = blockIdx.x, fh = blockIdx.y;
    const int f = fh >> 4, h = fh & 15;
    const int tok0 = f * NQ_;
    const int q0 = qb * 64;
    const float alph = alpha[h];
    const int rl = 16 * w + rg;

    for (int i = tid; i < 512; i += 128) {
        int row = i >> 3, c16 = i & 7;
        size_t go = (size_t)(tok0 + q0 + row) * D_ + h * 64 + c16 * 8;
        *(uint4*)(sK + row * 36 + c16 * 4) = *(const uint4*)(Qh + go);
    }
    __syncthreads();
    uint32_t qhF[4][4];
    #pragma unroll
    for (int s = 0; s < 4; s++) {
        qhF[s][0] = sK[rl * 36 + 8 * s + c];
        qhF[s][1] = sK[(rl + 8) * 36 + 8 * s + c];
        qhF[s][2] = sK[rl * 36 + 8 * s + c + 4];
        qhF[s][3] = sK[(rl + 8) * 36 + 8 * s + c + 4];
    }
    __syncthreads();

    float o[8][4];
    #pragma unroll
    for (int n = 0; n < 8; n++)
        #pragma unroll
        for (int r = 0; r < 4; r++) o[n][r] = 0.f;
    float m0r = -3.0e38f, m1r = -3.0e38f, l0r = 0.f, l1r = 0.f;

    for (int kt = 0; kt < 9; kt++) {
        const int k0 = kt * 64;
        for (int i = tid; i < 512; i += 128) {
            int row = i >> 3, c16 = i & 7;
            size_t go = (size_t)(tok0 + k0 + row) * D_ + h * 64 + c16 * 8;
            *(uint4*)(sK + row * 36 + c16 * 4) = *(const uint4*)(Kr + go);
            size_t vo = (size_t)fh * (64 * NK_) + (size_t)row * NK_ + k0 + c16 * 8;
            *(uint4*)(sV + row * 36 + c16 * 4) = *(const uint4*)(Vtr + vo);
        }
        for (int i = tid; i < 512; i += 128) {
            int row = i >> 3, c8 = i & 7;
            *(uint4*)(sE + row * 72 + c8 * 8) =
                *(const uint4*)(E + (size_t)(tok0 + q0 + row) * NK_ + k0 + c8 * 8);
        }
        __syncthreads();

        float s[8][4];
        #pragma unroll
        for (int n = 0; n < 8; n++)
            #pragma unroll
            for (int r = 0; r < 4; r++) s[n][r] = 0.f;
        #pragma unroll
        for (int st = 0; st < 4; st++) {
            #pragma unroll
            for (int n = 0; n < 8; n++) {
                int bi = (8 * n + rg) * 36 + 8 * st + c;
                uint32_t bh[2] = { sK[bi], sK[bi + 4] };
                mma_f16(s[n], qhF[st], bh);
            }
        }

        float mn0 = m0r, mn1 = m1r;
        #pragma unroll
        for (int n = 0; n < 8; n++) {
            float2 e0 = __bfloat1622float2(
                *(__nv_bfloat162*)(sE + rl * 72 + 8 * n + 2 * c));
            float2 e1 = __bfloat1622float2(
                *(__nv_bfloat162*)(sE + (rl + 8) * 72 + 8 * n + 2 * c));
            s[n][0] = (e0.x < 0.f) ? NEGBIG : fmaf(s[n][0], 0.125f, alph * e0.x);
            s[n][1] = (e0.y < 0.f) ? NEGBIG : fmaf(s[n][1], 0.125f, alph * e0.y);
            s[n][2] = (e1.x < 0.f) ? NEGBIG : fmaf(s[n][2], 0.125f, alph * e1.x);
            s[n][3] = (e1.y < 0.f) ? NEGBIG : fmaf(s[n][3], 0.125f, alph * e1.y);
            mn0 = fmaxf(mn0, fmaxf(s[n][0], s[n][1]));
            mn1 = fmaxf(mn1, fmaxf(s[n][2], s[n][3]));
        }
        mn0 = fmaxf(mn0, __shfl_xor_sync(0xffffffffu, mn0, 1));
        mn0 = fmaxf(mn0, __shfl_xor_sync(0xffffffffu, mn0, 2));
        mn1 = fmaxf(mn1, __shfl_xor_sync(0xffffffffu, mn1, 1));
        mn1 = fmaxf(mn1, __shfl_xor_sync(0xffffffffu, mn1, 2));
        float f0 = ex2((m0r - mn0) * LOG2E);
        float f1 = ex2((m1r - mn1) * LOG2E);
        m0r = mn0; m1r = mn1;

        float rs0 = 0.f, rs1 = 0.f;
        uint32_t phL[8], phH[8];
        #pragma unroll
        for (int n = 0; n < 8; n++) {
            float p0 = ex2((s[n][0] - mn0) * LOG2E);
            float p1 = ex2((s[n][1] - mn0) * LOG2E);
            float p2 = ex2((s[n][2] - mn1) * LOG2E);
            float p3 = ex2((s[n][3] - mn1) * LOG2E);
            rs0 += p0 + p1;
            rs1 += p2 + p3;
            o[n][0] *= f0; o[n][1] *= f0; o[n][2] *= f1; o[n][3] *= f1;
            __half2 bL = __floats2half2_rn(p0, p1);
            phL[n] = *(uint32_t*)&bL;
            __half2 bH = __floats2half2_rn(p2, p3);
            phH[n] = *(uint32_t*)&bH;
        }
        rs0 += __shfl_xor_sync(0xffffffffu, rs0, 1);
        rs0 += __shfl_xor_sync(0xffffffffu, rs0, 2);
        rs1 += __shfl_xor_sync(0xffffffffu, rs1, 1);
        rs1 += __shfl_xor_sync(0xffffffffu, rs1, 2);
        l0r = l0r * f0 + rs0;
        l1r = l1r * f1 + rs1;

        #pragma unroll
        for (int st = 0; st < 4; st++) {
            uint32_t ah[4] = { phL[2 * st], phH[2 * st], phL[2 * st + 1], phH[2 * st + 1] };
            #pragma unroll
            for (int n = 0; n < 8; n++) {
                int bi = (8 * n + rg) * 36 + 8 * st + c;
                uint32_t vh[2] = { sV[bi], sV[bi + 4] };
                mma_f16(o[n], ah, vh);
            }
        }
        __syncthreads();
    }

    float i0 = 1.f / l0r, i1 = 1.f / l1r;
    #pragma unroll
    for (int n = 0; n < 8; n++) {
        size_t e0 = ((size_t)(tok0 + q0 + rl) * D_ + h * 64 + 8 * n + 2 * c) >> 1;
        size_t e1 = ((size_t)(tok0 + q0 + rl + 8) * D_ + h * 64 + 8 * n + 2 * c) >> 1;
        ((__half2*)Yh)[e0] = __floats2half2_rn(o[n][0] * i0, o[n][1] * i0);
        ((__half2*)Yh)[e1] = __floats2half2_rn(o[n][2] * i1, o[n][3] * i1);
    }
}

// ---------------------------------------------------------------------------
extern "C" void kernel_launch(void* const* d_in, const int* in_sizes, int n_in,
                              void* d_out, int out_size)
{
    (void)in_sizes; (void)n_in; (void)out_size;

    const float*   q_tokens  = (const float*)d_in[0];
    const float*   kv_tokens = (const float*)d_in[1];
    const float*   coords_q  = (const float*)d_in[2];
    const float*   coords_k  = (const float*)d_in[3];
    const void*    q_pad     = d_in[4];
    const void*    kv_pad    = d_in[5];
    const float*   Wq = (const float*)d_in[6];
    const float*   bq = (const float*)d_in[7];
    const float*   Wk = (const float*)d_in[8];
    const float*   bk = (const float*)d_in[9];
    const float*   Wv = (const float*)d_in[10];
    const float*   bv = (const float*)d_in[11];
    const float*   Wo = (const float*)d_in[12];
    const float*   bo = (const float*)d_in[13];
    const float*   alpha = (const float*)d_in[14];
    const float*   f0 = (const float*)d_in[15];
    const float*   f1 = (const float*)d_in[16];
    const float*   f2 = (const float*)d_in[17];
    float* out = (float*)d_out;

    __nv_bfloat16 *Eb;
    float2 *rtq, *rtk;
    cudaGetSymbolAddress((void**)&Eb, g_E);
    cudaGetSymbolAddress((void**)&rtq, g_rt);
    rtk = rtq + TOK * 32;

    __half *x16q, *x16kv, *yhi, *W16, *aQh, *aKr, *vtr;
    cudaGetSymbolAddress((void**)&x16q, g_x16);
    x16kv = x16q + TOK * D_;
    cudaGetSymbolAddress((void**)&yhi,  g_yhi);
    cudaGetSymbolAddress((void**)&W16, g_W16);
    cudaGetSymbolAddress((void**)&aQh, g_aQh);
    cudaGetSymbolAddress((void**)&aKr, g_aKr);
    cudaGetSymbolAddress((void**)&vtr, g_vtr);
    __half *Wqh = W16, *Wkh = W16 + D_ * D_, *Wvh = W16 + 2 * D_ * D_,
           *Woh = W16 + 3 * D_ * D_;

    const float** rsrc;
    __half** rdst;
    cudaGetSymbolAddress((void**)&rsrc, g_round_src);
    cudaGetSymbolAddress((void**)&rdst, g_round_dst);

    const int gemm_smem = 3 * STG;  // 61440
    cudaFuncSetAttribute(gemm_qkv, cudaFuncAttributeMaxDynamicSharedMemorySize, gemm_smem);
    cudaFuncSetAttribute(gemm_wo,  cudaFuncAttributeMaxDynamicSharedMemorySize, gemm_smem);
    cudaFuncSetAttribute(attn_mma, cudaFuncAttributeMaxDynamicSharedMemorySize, ATT_SMEM);

    // masks + pointer tables + fused bias + rope tables
    detect_mask_kernel<<<1, 256>>>((const unsigned*)q_pad, (const unsigned*)kv_pad,
                                   TOK / 4, Wq, Wk, Wv, Wo, q_tokens, kv_tokens);
    bias_kernel<<<dim3(NQ_ / 8, 8), NK_>>>(coords_q, coords_k, q_pad, kv_pad, Eb);
    ropetab_kernel<<<dim3(TOK / 8, 2), 256>>>(coords_q, coords_k, f0, f1, f2, rtq, rtk);

    // fp16 single roundings (batched, MLP=4: 1024 float4 per block)
    const int ntok4 = TOK * D_ / 4, nw4 = D_ * D_ / 4;
    round_h_batch<<<dim3((nw4 + 1023) / 1024, 4), 256>>>(rsrc, rdst, nw4);
    round_h_batch<<<dim3((ntok4 + 1023) / 1024, 2), 256>>>(rsrc + 4, rdst + 4, ntok4);

    // merged Q/K/V projection (one launch, 864 CTAs)
    gemm_qkv<<<dim3(GN / 128, TOK / 128, 3), 128, gemm_smem>>>(
        x16q, x16kv, Wqh, Wkh, Wvh, bq, bk, bv, aQh, aKr, vtr, rtq, rtk);

    attn_mma<<<dim3(9, 128), 128, ATT_SMEM>>>(aQh, aKr, vtr, Eb, alpha, yhi);

    gemm_wo<<<dim3(GN / 128, TOK / 128), 128, gemm_smem>>>(yhi, Woh, bo, out);
}

// round 15
// speedup vs baseline: 1.8777x; 1.0422x over previous
#include <cuda_runtime.h>
#include <cuda_bf16.h>
#include <cuda_fp16.h>
#include <cstdint>
#include <cstddef>
#include <math.h>

// Problem constants
#define B_   2
#define T_   4
#define NQ_  576
#define NK_  576
#define D_   1024
#define H_   16
#define DH_  64
#define TOK  (B_*T_*NQ_)
#define NEGBIG (-1.7014118e38f)
#define LOG2E 1.4426950408889634f

#define GK 1024
#define GN 1024

// Scratch (device globals; no dynamic allocation allowed)
__device__ int   g_mask_mode[2];
__device__ __nv_bfloat16 g_E[8 * NQ_ * NK_];
__device__ float2 g_rt[2][TOK * 32];   // cos/sin tables: [0]=q, [1]=k

// fp16 operands (all single-rounded)
__device__ __half g_x16[2][TOK * D_];  // [0]=q_tokens, [1]=kv_tokens
__device__ __half g_yhi[TOK * D_];
__device__ __half g_W16[4][D_ * D_];   // Wq, Wk, Wv, Wo

// attention operands (fp16): Q (rope'd), K (rope'd), V^T
__device__ __half g_aQh[TOK * D_];
__device__ __half g_aKr[TOK * D_];
__device__ __half g_vtr[128 * 64 * NK_];

__device__ const float* g_round_src[6];
__device__ __half*      g_round_dst[6];

// ---------------------------------------------------------------------------
// Family-portable PTX helpers
// ---------------------------------------------------------------------------
__device__ __forceinline__ uint32_t smem_u32(const void* p) {
    uint32_t a;
    asm("{ .reg .u64 t; cvta.to.shared.u64 t, %1; cvt.u32.u64 %0, t; }"
        : "=r"(a) : "l"(p));
    return a;
}
__device__ __forceinline__ void cp16(uint32_t s, const void* g) {
    asm volatile("cp.async.cg.shared.global [%0], [%1], 16;"
                 :: "r"(s), "l"(g) : "memory");
}
__device__ __forceinline__ void cp_commit() {
    asm volatile("cp.async.commit_group;" ::: "memory");
}
__device__ __forceinline__ void cp_wait1() {
    asm volatile("cp.async.wait_group 1;" ::: "memory");
}
__device__ __forceinline__ void cp_wait0() {
    asm volatile("cp.async.wait_group 0;" ::: "memory");
}
__device__ __forceinline__ void ldm_x4(uint32_t* r, uint32_t addr) {
    asm volatile("ldmatrix.sync.aligned.m8n8.x4.shared.b16 {%0,%1,%2,%3}, [%4];"
                 : "=r"(r[0]), "=r"(r[1]), "=r"(r[2]), "=r"(r[3]) : "r"(addr));
}
__device__ __forceinline__ void mma_f16(float* d, const uint32_t* a, const uint32_t* b) {
    asm volatile(
        "mma.sync.aligned.m16n8k16.row.col.f32.f16.f16.f32 "
        "{%0,%1,%2,%3}, {%4,%5,%6,%7}, {%8,%9}, {%0,%1,%2,%3};"
        : "+f"(d[0]), "+f"(d[1]), "+f"(d[2]), "+f"(d[3])
        : "r"(a[0]), "r"(a[1]), "r"(a[2]), "r"(a[3]), "r"(b[0]), "r"(b[1]));
}
__device__ __forceinline__ float ex2(float x) {
    float y;
    asm("ex2.approx.f32 %0, %1;" : "=f"(y) : "f"(x));
    return y;
}

// ---------------------------------------------------------------------------
// Mask dtype detection (+ pointer table setup on thread 0)
// ---------------------------------------------------------------------------
__global__ void detect_mask_kernel(const unsigned* __restrict__ qm,
                                   const unsigned* __restrict__ km, int nints,
                                   const float* s0, const float* s1,
                                   const float* s2, const float* s3,
                                   const float* s4, const float* s5)
{
    if (threadIdx.x == 0) {
        g_round_src[0] = s0; g_round_src[1] = s1; g_round_src[2] = s2;
        g_round_src[3] = s3; g_round_src[4] = s4; g_round_src[5] = s5;
        g_round_dst[0] = g_W16[0]; g_round_dst[1] = g_W16[1];
        g_round_dst[2] = g_W16[2]; g_round_dst[3] = g_W16[3];
        g_round_dst[4] = g_x16[0]; g_round_dst[5] = g_x16[1];
    }
    __shared__ int s_i, s_f;
    for (int b = 0; b < 2; b++) {
        if (threadIdx.x == 0) { s_i = 1; s_f = 1; }
        __syncthreads();
        const unsigned* p = b ? km : qm;
        int li = 1, lf = 1;
        for (int i = threadIdx.x; i < nints; i += blockDim.x) {
            unsigned v = p[i];
            if (v > 1u) li = 0;
            if (v != 0u && v != 0x3f800000u) lf = 0;
        }
        if (!li) atomicAnd(&s_i, 0);
        if (!lf) atomicAnd(&s_f, 0);
        __syncthreads();
        if (threadIdx.x == 0)
            g_mask_mode[b] = s_i ? 1 : (s_f ? 2 : 0);
        __syncthreads();
    }
}

__device__ __forceinline__ bool mask_at(const void* p, int i, int mode) {
    if (mode == 1) return ((const int*)p)[i] != 0;
    if (mode == 2) return ((const float*)p)[i] != 0.f;
    return ((const unsigned char*)p)[i] != 0;
}

// ---------------------------------------------------------------------------
// Mega prep kernel (one launch): blockIdx.x ranges select role.
//   [0,1024)        : weight fp16 rounding   (4 matrices x 256 blocks)
//   [1024,3328)     : activation rounding    (2 tensors  x 1152 blocks)
//   [3328,4480)     : rope cos/sin tables    (2 sides    x 576 blocks)
//   [4480,5056)     : fused bias E           (8 frames   x 72 q-blocks)
// ---------------------------------------------------------------------------
#define PREP_BLOCKS 5056

__global__ void __launch_bounds__(256)
prep_kernel(const float* __restrict__ cq, const float* __restrict__ ck,
            const float* __restrict__ f0, const float* __restrict__ f1,
            const float* __restrict__ f2,
            float2* __restrict__ tq, float2* __restrict__ tk,
            const void* __restrict__ qmr, const void* __restrict__ kmr,
            __nv_bfloat16* __restrict__ E)
{
    __shared__ float ky[NK_], kx[NK_];
    __shared__ unsigned char kbad[NK_];
    __shared__ float qy8[8], qx8[8];
    __shared__ unsigned char qbad[8];

    int bid = blockIdx.x;

    if (bid < 1024) {                       // weight rounding (nw4 = 262144)
        int mat = bid >> 8, blk = bid & 255;
        const float* x = g_round_src[mat];
        __half* h = g_round_dst[mat];
        int base = blk * 1024 + threadIdx.x;
        #pragma unroll
        for (int j = 0; j < 4; j++) {
            int idx = base + j * 256;
            float4 v = ((const float4*)x)[idx];
            ((__half2*)h)[2*idx]   = __floats2half2_rn(v.x, v.y);
            ((__half2*)h)[2*idx+1] = __floats2half2_rn(v.z, v.w);
        }
        return;
    }
    bid -= 1024;
    if (bid < 2304) {                       // act rounding (ntok4 = 1179648)
        int which = bid / 1152, blk = bid - which * 1152;
        const float* x = g_round_src[4 + which];
        __half* h = g_round_dst[4 + which];
        int base = blk * 1024 + threadIdx.x;
        #pragma unroll
        for (int j = 0; j < 4; j++) {
            int idx = base + j * 256;
            float4 v = ((const float4*)x)[idx];
            ((__half2*)h)[2*idx]   = __floats2half2_rn(v.x, v.y);
            ((__half2*)h)[2*idx+1] = __floats2half2_rn(v.z, v.w);
        }
        return;
    }
    bid -= 2304;
    if (bid < 1152) {                       // ropetab
        int side = bid / 576, blk = bid - side * 576;
        const float* coords = side ? ck : cq;
        float2* tab = side ? tk : tq;
        int tok = blk * 8 + (threadIdx.x >> 5);
        int tid = threadIdx.x & 31;
        float coord, fr;
        if (tid < 12)      { coord = coords[tok * 3 + 0]; fr = f0[tid]; }
        else if (tid < 22) { coord = coords[tok * 3 + 1]; fr = f1[tid - 12]; }
        else               { coord = coords[tok * 3 + 2]; fr = f2[tid - 22]; }
        float arg = 1.5707963267948966f * coord * fr;
        float s, c;
        sincosf(arg, &s, &c);
        tab[tok * 32 + tid] = make_float2(c, s);
        return;
    }
    bid -= 1152;                            // bias: 576 blocks (f x qb)
    {
        int f = bid / 72, qb = bid - f * 72;
        const int mq = g_mask_mode[0], mk = g_mask_mode[1];
        for (int k = threadIdx.x; k < NK_; k += 256) {
            int ki = f * NK_ + k;
            ky[k]  = ck[ki * 3 + 1];
            kx[k]  = ck[ki * 3 + 2];
            kbad[k] = mask_at(kmr, ki, mk) ? 1 : 0;
        }
        if (threadIdx.x < 8) {
            int q = qb * 8 + threadIdx.x;
            int qi = f * NQ_ + q;
            qy8[threadIdx.x] = cq[qi * 3 + 1];
            qx8[threadIdx.x] = cq[qi * 3 + 2];
            qbad[threadIdx.x] = mask_at(qmr, qi, mq) ? 1 : 0;
        }
        __syncthreads();
        for (int e = threadIdx.x; e < 8 * NK_; e += 256) {
            int r = e / NK_, k = e - r * NK_;
            int q = qb * 8 + r;
            float dy = qy8[r] - ky[k];
            float dx = qx8[r] - kx[k];
            float dist = sqrtf(dy * dy + dx * dx);
            bool bad = qbad[r] || kbad[k] || (dist > 0.5f);
            E[(size_t)(f * NQ_ + q) * NK_ + k] =
                __float2bfloat16(bad ? -3.0e38f : __expf(-10.f * dist));
        }
    }
}

// ---------------------------------------------------------------------------
// Merged Q/K/V HMMA GEMM (grid.z selects operands + epilogue):
//   z=0: aQh = rope(x16q @ Wq^T + bq)      (fp16)
//   z=1: aKr = rope(x16kv @ Wk^T + bk)     (fp16)
//   z=2: vtr = transpose(x16kv @ Wv^T+bv)  (fp16, V^T layout)
// ---------------------------------------------------------------------------
#define TILE_B 10240
#define STG    (2 * TILE_B)
#define NCH    32

__global__ void __launch_bounds__(128, 2)
gemm_qkv(const __half* __restrict__ x16q, const __half* __restrict__ x16kv,
         const __half* __restrict__ Wqh, const __half* __restrict__ Wkh,
         const __half* __restrict__ Wvh,
         const float* __restrict__ bq, const float* __restrict__ bk,
         const float* __restrict__ bv,
         __half* __restrict__ aQh, __half* __restrict__ aKr,
         __half* __restrict__ vtr,
         const float2* __restrict__ rtq, const float2* __restrict__ rtk)
{
    extern __shared__ char dsm[];
    const uint32_t sbase = smem_u32(dsm);

    const int z = blockIdx.z;
    const __half* Ah = (z == 0) ? x16q : x16kv;
    const __half* Bh = (z == 0) ? Wqh : (z == 1) ? Wkh : Wvh;
    const float* bias = (z == 0) ? bq : (z == 1) ? bk : bv;
    __half* O1 = (z == 0) ? aQh : (z == 1) ? aKr : vtr;
    const float2* rtab = (z == 0) ? rtq : rtk;

    const int tid  = threadIdx.x;
    const int wid  = tid >> 5;
    const int lane = tid & 31;
    const int m0 = blockIdx.y * 128;
    const int n0 = blockIdx.x * 128;
    const int wm = (wid & 1) * 64;
    const int wn = (wid >> 1) * 64;

    float acc[4][8][4];
    #pragma unroll
    for (int mt = 0; mt < 4; mt++)
        #pragma unroll
        for (int nt = 0; nt < 8; nt++)
            #pragma unroll
            for (int r = 0; r < 4; r++) acc[mt][nt][r] = 0.f;

    int l_tl[8], l_row[8], l_c[8];
    #pragma unroll
    for (int j = 0; j < 8; j++) {
        int i = tid + j * 128;
        l_tl[j]  = i >> 9;
        l_row[j] = (i & 511) >> 2;
        l_c[j]   = i & 3;
    }

    auto issue_load = [&](int ch, int buf) {
        const int k0 = ch * 32;
        #pragma unroll
        for (int j = 0; j < 8; j++) {
            const __half* g = l_tl[j]
                ? Bh + (size_t)(n0 + l_row[j]) * GK + k0 + l_c[j] * 8
                : Ah + (size_t)(m0 + l_row[j]) * GK + k0 + l_c[j] * 8;
            uint32_t s = sbase + buf * STG + l_tl[j] * TILE_B
                       + l_row[j] * 80 + l_c[j] * 16;
            cp16(s, g);
        }
        cp_commit();
    };

    issue_load(0, 0);
    issue_load(1, 1);

    for (int ch = 0; ch < NCH; ch++) {
        if (ch == NCH - 1) cp_wait0(); else cp_wait1();
        __syncthreads();
        if (ch + 2 < NCH) issue_load(ch + 2, (ch + 2) % 3);

        const uint32_t hbase = sbase + (ch % 3) * STG;
        const uint32_t bbase = hbase + TILE_B;

        #pragma unroll
        for (int ks = 0; ks < 2; ks++) {
            uint32_t b[8][2];
            #pragma unroll
            for (int np = 0; np < 4; np++) {
                uint32_t addr = bbase
                    + (wn + np * 16 + (lane & 7) + ((lane >> 4) & 1) * 8) * 80
                    + ((lane >> 3) & 1) * 16 + ks * 32;
                uint32_t r[4];
                ldm_x4(r, addr);
                b[np * 2][0] = r[0];     b[np * 2][1] = r[1];
                b[np * 2 + 1][0] = r[2]; b[np * 2 + 1][1] = r[3];
            }
            uint32_t a[4][4];
            #pragma unroll
            for (int mt = 0; mt < 4; mt++) {
                uint32_t addr = hbase + (wm + mt * 16 + (lane & 15)) * 80
                              + (lane >> 4) * 16 + ks * 32;
                ldm_x4(a[mt], addr);
            }
            #pragma unroll
            for (int mt = 0; mt < 4; mt++)
                #pragma unroll
                for (int nt = 0; nt < 8; nt++)
                    mma_f16(acc[mt][nt], a[mt], b[nt]);
        }
    }

    const int cb_loc = wn + (lane & 3) * 2;
    const int cbase = n0 + cb_loc;
    float bv_[8][2];
    #pragma unroll
    for (int nt = 0; nt < 8; nt++) {
        bv_[nt][0] = bias[cbase + nt * 8];
        bv_[nt][1] = bias[cbase + nt * 8 + 1];
    }

    if (z < 2) {
        // rope epilogue
        float2* st = (float2*)dsm;
        __syncthreads();
        for (int i = tid; i < 128 * 32; i += 128)
            st[i] = rtab[(size_t)(m0 + (i >> 5)) * 32 + (i & 31)];
        __syncthreads();

        #pragma unroll
        for (int mt = 0; mt < 4; mt++) {
            int rl0 = wm + mt * 16 + (lane >> 2);
            #pragma unroll
            for (int nt = 0; nt < 8; nt++) {
                int col = cbase + nt * 8;
                float v0 = acc[mt][nt][0] + bv_[nt][0];
                float v1 = acc[mt][nt][1] + bv_[nt][1];
                float v2 = acc[mt][nt][2] + bv_[nt][0];
                float v3 = acc[mt][nt][3] + bv_[nt][1];
                int j = ((cb_loc + nt * 8) & 63) >> 1;
                float2 cs0 = st[rl0 * 32 + j];
                float2 cs1 = st[(rl0 + 8) * 32 + j];
                float y0 = v0 * cs0.x - v1 * cs0.y;
                float y1 = v1 * cs0.x + v0 * cs0.y;
                float y2 = v2 * cs1.x - v3 * cs1.y;
                float y3 = v3 * cs1.x + v2 * cs1.y;
                ((__half2*)O1)[((size_t)(m0 + rl0) * D_ + col) >> 1]     = __floats2half2_rn(y0, y1);
                ((__half2*)O1)[((size_t)(m0 + rl0 + 8) * D_ + col) >> 1] = __floats2half2_rn(y2, y3);
            }
        }
    } else {
        // V: transpose epilogue via smem staging
        __half* sT = (__half*)dsm;
        __syncthreads();
        #pragma unroll
        for (int mt = 0; mt < 4; mt++) {
            int rl0 = wm + mt * 16 + (lane >> 2);
            #pragma unroll
            for (int nt = 0; nt < 8; nt++) {
                int cl = cb_loc + nt * 8;
                float v0 = acc[mt][nt][0] + bv_[nt][0];
                float v1 = acc[mt][nt][1] + bv_[nt][1];
                float v2 = acc[mt][nt][2] + bv_[nt][0];
                float v3 = acc[mt][nt][3] + bv_[nt][1];
                *(__half2*)&sT[rl0 * 130 + cl]       = __floats2half2_rn(v0, v1);
                *(__half2*)&sT[(rl0 + 8) * 130 + cl] = __floats2half2_rn(v2, v3);
            }
        }
        __syncthreads();
        for (int idx = tid; idx < 128 * 64; idx += 128) {
            int dl = idx >> 6, kp = idx & 63;
            int tok = m0 + 2 * kp;
            int f = tok / NQ_;
            int key = tok - f * NQ_;
            int gd = n0 + dl;
            int h = gd >> 6, dh = gd & 63;
            __half a = sT[(2 * kp) * 130 + dl];
            __half b = sT[(2 * kp + 1) * 130 + dl];
            size_t oi = (((size_t)(f * 16 + h) * 64 + dh) * NK_ + key) >> 1;
            ((__half2*)O1)[oi] = __halves2half2(a, b);
        }
    }
}

// ---------------------------------------------------------------------------
// Wo GEMM: fp32 out (+bias)
// ---------------------------------------------------------------------------
__global__ void __launch_bounds__(128, 2)
gemm_wo(const __half* __restrict__ Ah, const __half* __restrict__ Bh,
        const float* __restrict__ bias, float* __restrict__ C)
{
    extern __shared__ char dsm[];
    const uint32_t sbase = smem_u32(dsm);

    const int tid  = threadIdx.x;
    const int wid  = tid >> 5;
    const int lane = tid & 31;
    const int m0 = blockIdx.y * 128;
    const int n0 = blockIdx.x * 128;
    const int wm = (wid & 1) * 64;
    const int wn = (wid >> 1) * 64;

    float acc[4][8][4];
    #pragma unroll
    for (int mt = 0; mt < 4; mt++)
        #pragma unroll
        for (int nt = 0; nt < 8; nt++)
            #pragma unroll
            for (int r = 0; r < 4; r++) acc[mt][nt][r] = 0.f;

    int l_tl[8], l_row[8], l_c[8];
    #pragma unroll
    for (int j = 0; j < 8; j++) {
        int i = tid + j * 128;
        l_tl[j]  = i >> 9;
        l_row[j] = (i & 511) >> 2;
        l_c[j]   = i & 3;
    }

    auto issue_load = [&](int ch, int buf) {
        const int k0 = ch * 32;
        #pragma unroll
        for (int j = 0; j < 8; j++) {
            const __half* g = l_tl[j]
                ? Bh + (size_t)(n0 + l_row[j]) * GK + k0 + l_c[j] * 8
                : Ah + (size_t)(m0 + l_row[j]) * GK + k0 + l_c[j] * 8;
            uint32_t s = sbase + buf * STG + l_tl[j] * TILE_B
                       + l_row[j] * 80 + l_c[j] * 16;
            cp16(s, g);
        }
        cp_commit();
    };

    issue_load(0, 0);
    issue_load(1, 1);

    for (int ch = 0; ch < NCH; ch++) {
        if (ch == NCH - 1) cp_wait0(); else cp_wait1();
        __syncthreads();
        if (ch + 2 < NCH) issue_load(ch + 2, (ch + 2) % 3);

        const uint32_t hbase = sbase + (ch % 3) * STG;
        const uint32_t bbase = hbase + TILE_B;

        #pragma unroll
        for (int ks = 0; ks < 2; ks++) {
            uint32_t b[8][2];
            #pragma unroll
            for (int np = 0; np < 4; np++) {
                uint32_t addr = bbase
                    + (wn + np * 16 + (lane & 7) + ((lane >> 4) & 1) * 8) * 80
                    + ((lane >> 3) & 1) * 16 + ks * 32;
                uint32_t r[4];
                ldm_x4(r, addr);
                b[np * 2][0] = r[0];     b[np * 2][1] = r[1];
                b[np * 2 + 1][0] = r[2]; b[np * 2 + 1][1] = r[3];
            }
            uint32_t a[4][4];
            #pragma unroll
            for (int mt = 0; mt < 4; mt++) {
                uint32_t addr = hbase + (wm + mt * 16 + (lane & 15)) * 80
                              + (lane >> 4) * 16 + ks * 32;
                ldm_x4(a[mt], addr);
            }
            #pragma unroll
            for (int mt = 0; mt < 4; mt++)
                #pragma unroll
                for (int nt = 0; nt < 8; nt++)
                    mma_f16(acc[mt][nt], a[mt], b[nt]);
        }
    }

    const int cbase = n0 + wn + (lane & 3) * 2;
    float bv[8][2];
    #pragma unroll
    for (int nt = 0; nt < 8; nt++) {
        bv[nt][0] = bias[cbase + nt * 8];
        bv[nt][1] = bias[cbase + nt * 8 + 1];
    }
    #pragma unroll
    for (int mt = 0; mt < 4; mt++) {
        int r0 = m0 + wm + mt * 16 + (lane >> 2);
        #pragma unroll
        for (int nt = 0; nt < 8; nt++) {
            int c = cbase + nt * 8;
            float2 v0 = { acc[mt][nt][0] + bv[nt][0], acc[mt][nt][1] + bv[nt][1] };
            float2 v1 = { acc[mt][nt][2] + bv[nt][0], acc[mt][nt][3] + bv[nt][1] };
            *(float2*)&C[(size_t)r0 * GN + c]       = v0;
            *(float2*)&C[(size_t)(r0 + 8) * GN + c] = v1;
        }
    }
}

// ---------------------------------------------------------------------------
// HMMA flash attention: S = Q K^T (1-pass), O = P V (1-pass).
// ---------------------------------------------------------------------------
#define ATT_SMEM 27648

__global__ void __launch_bounds__(128)
attn_mma(const __half* __restrict__ Qh,
         const __half* __restrict__ Kr, const __half* __restrict__ Vtr,
         const __nv_bfloat16* __restrict__ E, const float* __restrict__ alpha,
         __half* __restrict__ Yh)
{
    extern __shared__ char sm[];
    uint32_t* sK = (uint32_t*)sm;
    uint32_t* sV = (uint32_t*)(sm + 9216);
    __nv_bfloat16* sE = (__nv_bfloat16*)(sm + 18432);

    const int tid = threadIdx.x;
    const int w = tid >> 5, lane = tid & 31;
    const int c = lane & 3, rg = lane >> 2;
    const int qb = blockIdx.x, fh = blockIdx.y;
    const int f = fh >> 4, h = fh & 15;
    const int tok0 = f * NQ_;
    const int q0 = qb * 64;
    const float alph = alpha[h];
    const int rl = 16 * w + rg;

    for (int i = tid; i < 512; i += 128) {
        int row = i >> 3, c16 = i & 7;
        size_t go = (size_t)(tok0 + q0 + row) * D_ + h * 64 + c16 * 8;
        *(uint4*)(sK + row * 36 + c16 * 4) = *(const uint4*)(Qh + go);
    }
    __syncthreads();
    uint32_t qhF[4][4];
    #pragma unroll
    for (int s = 0; s < 4; s++) {
        qhF[s][0] = sK[rl * 36 + 8 * s + c];
        qhF[s][1] = sK[(rl + 8) * 36 + 8 * s + c];
        qhF[s][2] = sK[rl * 36 + 8 * s + c + 4];
        qhF[s][3] = sK[(rl + 8) * 36 + 8 * s + c + 4];
    }
    __syncthreads();

    float o[8][4];
    #pragma unroll
    for (int n = 0; n < 8; n++)
        #pragma unroll
        for (int r = 0; r < 4; r++) o[n][r] = 0.f;
    float m0r = -3.0e38f, m1r = -3.0e38f, l0r = 0.f, l1r = 0.f;

    for (int kt = 0; kt < 9; kt++) {
        const int k0 = kt * 64;
        for (int i = tid; i < 512; i += 128) {
            int row = i >> 3, c16 = i & 7;
            size_t go = (size_t)(tok0 + k0 + row) * D_ + h * 64 + c16 * 8;
            *(uint4*)(sK + row * 36 + c16 * 4) = *(const uint4*)(Kr + go);
            size_t vo = (size_t)fh * (64 * NK_) + (size_t)row * NK_ + k0 + c16 * 8;
            *(uint4*)(sV + row * 36 + c16 * 4) = *(const uint4*)(Vtr + vo);
        }
        for (int i = tid; i < 512; i += 128) {
            int row = i >> 3, c8 = i & 7;
            *(uint4*)(sE + row * 72 + c8 * 8) =
                *(const uint4*)(E + (size_t)(tok0 + q0 + row) * NK_ + k0 + c8 * 8);
        }
        __syncthreads();

        float s[8][4];
        #pragma unroll
        for (int n = 0; n < 8; n++)
            #pragma unroll
            for (int r = 0; r < 4; r++) s[n][r] = 0.f;
        #pragma unroll
        for (int st = 0; st < 4; st++) {
            #pragma unroll
            for (int n = 0; n < 8; n++) {
                int bi = (8 * n + rg) * 36 + 8 * st + c;
                uint32_t bh[2] = { sK[bi], sK[bi + 4] };
                mma_f16(s[n], qhF[st], bh);
            }
        }

        float mn0 = m0r, mn1 = m1r;
        #pragma unroll
        for (int n = 0; n < 8; n++) {
            float2 e0 = __bfloat1622float2(
                *(__nv_bfloat162*)(sE + rl * 72 + 8 * n + 2 * c));
            float2 e1 = __bfloat1622float2(
                *(__nv_bfloat162*)(sE + (rl + 8) * 72 + 8 * n + 2 * c));
            s[n][0] = (e0.x < 0.f) ? NEGBIG : fmaf(s[n][0], 0.125f, alph * e0.x);
            s[n][1] = (e0.y < 0.f) ? NEGBIG : fmaf(s[n][1], 0.125f, alph * e0.y);
            s[n][2] = (e1.x < 0.f) ? NEGBIG : fmaf(s[n][2], 0.125f, alph * e1.x);
            s[n][3] = (e1.y < 0.f) ? NEGBIG : fmaf(s[n][3], 0.125f, alph * e1.y);
            mn0 = fmaxf(mn0, fmaxf(s[n][0], s[n][1]));
            mn1 = fmaxf(mn1, fmaxf(s[n][2], s[n][3]));
        }
        mn0 = fmaxf(mn0, __shfl_xor_sync(0xffffffffu, mn0, 1));
        mn0 = fmaxf(mn0, __shfl_xor_sync(0xffffffffu, mn0, 2));
        mn1 = fmaxf(mn1, __shfl_xor_sync(0xffffffffu, mn1, 1));
        mn1 = fmaxf(mn1, __shfl_xor_sync(0xffffffffu, mn1, 2));
        float f0 = ex2((m0r - mn0) * LOG2E);
        float f1 = ex2((m1r - mn1) * LOG2E);
        m0r = mn0; m1r = mn1;

        float rs0 = 0.f, rs1 = 0.f;
        uint32_t phL[8], phH[8];
        #pragma unroll
        for (int n = 0; n < 8; n++) {
            float p0 = ex2((s[n][0] - mn0) * LOG2E);
            float p1 = ex2((s[n][1] - mn0) * LOG2E);
            float p2 = ex2((s[n][2] - mn1) * LOG2E);
            float p3 = ex2((s[n][3] - mn1) * LOG2E);
            rs0 += p0 + p1;
            rs1 += p2 + p3;
            o[n][0] *= f0; o[n][1] *= f0; o[n][2] *= f1; o[n][3] *= f1;
            __half2 bL = __floats2half2_rn(p0, p1);
            phL[n] = *(uint32_t*)&bL;
            __half2 bH = __floats2half2_rn(p2, p3);
            phH[n] = *(uint32_t*)&bH;
        }
        rs0 += __shfl_xor_sync(0xffffffffu, rs0, 1);
        rs0 += __shfl_xor_sync(0xffffffffu, rs0, 2);
        rs1 += __shfl_xor_sync(0xffffffffu, rs1, 1);
        rs1 += __shfl_xor_sync(0xffffffffu, rs1, 2);
        l0r = l0r * f0 + rs0;
        l1r = l1r * f1 + rs1;

        #pragma unroll
        for (int st = 0; st < 4; st++) {
            uint32_t ah[4] = { phL[2 * st], phH[2 * st], phL[2 * st + 1], phH[2 * st + 1] };
            #pragma unroll
            for (int n = 0; n < 8; n++) {
                int bi = (8 * n + rg) * 36 + 8 * st + c;
                uint32_t vh[2] = { sV[bi], sV[bi + 4] };
                mma_f16(o[n], ah, vh);
            }
        }
        __syncthreads();
    }

    float i0 = 1.f / l0r, i1 = 1.f / l1r;
    #pragma unroll
    for (int n = 0; n < 8; n++) {
        size_t e0 = ((size_t)(tok0 + q0 + rl) * D_ + h * 64 + 8 * n + 2 * c) >> 1;
        size_t e1 = ((size_t)(tok0 + q0 + rl + 8) * D_ + h * 64 + 8 * n + 2 * c) >> 1;
        ((__half2*)Yh)[e0] = __floats2half2_rn(o[n][0] * i0, o[n][1] * i0);
        ((__half2*)Yh)[e1] = __floats2half2_rn(o[n][2] * i1, o[n][3] * i1);
    }
}

// ---------------------------------------------------------------------------
extern "C" void kernel_launch(void* const* d_in, const int* in_sizes, int n_in,
                              void* d_out, int out_size)
{
    (void)in_sizes; (void)n_in; (void)out_size;

    const float*   q_tokens  = (const float*)d_in[0];
    const float*   kv_tokens = (const float*)d_in[1];
    const float*   coords_q  = (const float*)d_in[2];
    const float*   coords_k  = (const float*)d_in[3];
    const void*    q_pad     = d_in[4];
    const void*    kv_pad    = d_in[5];
    const float*   Wq = (const float*)d_in[6];
    const float*   bq = (const float*)d_in[7];
    const float*   Wk = (const float*)d_in[8];
    const float*   bk = (const float*)d_in[9];
    const float*   Wv = (const float*)d_in[10];
    const float*   bv = (const float*)d_in[11];
    const float*   Wo = (const float*)d_in[12];
    const float*   bo = (const float*)d_in[13];
    const float*   alpha = (const float*)d_in[14];
    const float*   f0 = (const float*)d_in[15];
    const float*   f1 = (const float*)d_in[16];
    const float*   f2 = (const float*)d_in[17];
    float* out = (float*)d_out;

    __nv_bfloat16 *Eb;
    float2 *rtq, *rtk;
    cudaGetSymbolAddress((void**)&Eb, g_E);
    cudaGetSymbolAddress((void**)&rtq, g_rt);
    rtk = rtq + TOK * 32;

    __half *x16q, *x16kv, *yhi, *W16, *aQh, *aKr, *vtr;
    cudaGetSymbolAddress((void**)&x16q, g_x16);
    x16kv = x16q + TOK * D_;
    cudaGetSymbolAddress((void**)&yhi,  g_yhi);
    cudaGetSymbolAddress((void**)&W16, g_W16);
    cudaGetSymbolAddress((void**)&aQh, g_aQh);
    cudaGetSymbolAddress((void**)&aKr, g_aKr);
    cudaGetSymbolAddress((void**)&vtr, g_vtr);
    __half *Wqh = W16, *Wkh = W16 + D_ * D_, *Wvh = W16 + 2 * D_ * D_,
           *Woh = W16 + 3 * D_ * D_;

    const int gemm_smem = 3 * STG;  // 61440
    cudaFuncSetAttribute(gemm_qkv, cudaFuncAttributeMaxDynamicSharedMemorySize, gemm_smem);
    cudaFuncSetAttribute(gemm_wo,  cudaFuncAttributeMaxDynamicSharedMemorySize, gemm_smem);
    cudaFuncSetAttribute(attn_mma, cudaFuncAttributeMaxDynamicSharedMemorySize, ATT_SMEM);

    // masks + pointer tables
    detect_mask_kernel<<<1, 256>>>((const unsigned*)q_pad, (const unsigned*)kv_pad,
                                   TOK / 4, Wq, Wk, Wv, Wo, q_tokens, kv_tokens);

    // mega prep: weight/act rounding + rope tables + bias, one launch
    prep_kernel<<<PREP_BLOCKS, 256>>>(coords_q, coords_k, f0, f1, f2,
                                      rtq, rtk, q_pad, kv_pad, Eb);

    // merged Q/K/V projection (one launch, 864 CTAs)
    gemm_qkv<<<dim3(GN / 128, TOK / 128, 3), 128, gemm_smem>>>(
        x16q, x16kv, Wqh, Wkh, Wvh, bq, bk, bv, aQh, aKr, vtr, rtq, rtk);

    attn_mma<<<dim3(9, 128), 128, ATT_SMEM>>>(aQh, aKr, vtr, Eb, alpha, yhi);

    gemm_wo<<<dim3(GN / 128, TOK / 128), 128, gemm_smem>>>(yhi, Woh, bo, out);
}

// round 16
// speedup vs baseline: 2.0305x; 1.0814x over previous
#include <cuda_runtime.h>
#include <cuda_bf16.h>
#include <cuda_fp16.h>
#include <cstdint>
#include <cstddef>
#include <math.h>

// Problem constants
#define B_   2
#define T_   4
#define NQ_  576
#define NK_  576
#define D_   1024
#define H_   16
#define DH_  64
#define TOK  (B_*T_*NQ_)
#define NEGBIG (-1.7014118e38f)
#define LOG2E 1.4426950408889634f

#define GK 1024
#define GN 1024

// Scratch (device globals; no dynamic allocation allowed)
__device__ int   g_mask_mode[2];
__device__ __nv_bfloat16 g_E[8 * NQ_ * NK_];
__device__ float2 g_rt[2][TOK * 32];   // cos/sin tables: [0]=q, [1]=k

// fp16 operands (all single-rounded)
__device__ __half g_x16[2][TOK * D_];  // [0]=q_tokens, [1]=kv_tokens
__device__ __half g_yhi[TOK * D_];
__device__ __half g_W16[4][D_ * D_];   // Wq, Wk, Wv, Wo

// attention operands (fp16): Q (rope'd), K (rope'd), V^T
__device__ __half g_aQh[TOK * D_];
__device__ __half g_aKr[TOK * D_];
__device__ __half g_vtr[128 * 64 * NK_];

__device__ const float* g_round_src[6];
__device__ __half*      g_round_dst[6];

// ---------------------------------------------------------------------------
// Family-portable PTX helpers
// ---------------------------------------------------------------------------
__device__ __forceinline__ uint32_t smem_u32(const void* p) {
    uint32_t a;
    asm("{ .reg .u64 t; cvta.to.shared.u64 t, %1; cvt.u32.u64 %0, t; }"
        : "=r"(a) : "l"(p));
    return a;
}
__device__ __forceinline__ void cp16(uint32_t s, const void* g) {
    asm volatile("cp.async.cg.shared.global [%0], [%1], 16;"
                 :: "r"(s), "l"(g) : "memory");
}
__device__ __forceinline__ void cp_commit() {
    asm volatile("cp.async.commit_group;" ::: "memory");
}
__device__ __forceinline__ void cp_wait1() {
    asm volatile("cp.async.wait_group 1;" ::: "memory");
}
__device__ __forceinline__ void cp_wait0() {
    asm volatile("cp.async.wait_group 0;" ::: "memory");
}
__device__ __forceinline__ void ldm_x4(uint32_t* r, uint32_t addr) {
    asm volatile("ldmatrix.sync.aligned.m8n8.x4.shared.b16 {%0,%1,%2,%3}, [%4];"
                 : "=r"(r[0]), "=r"(r[1]), "=r"(r[2]), "=r"(r[3]) : "r"(addr));
}
__device__ __forceinline__ void mma_f16(float* d, const uint32_t* a, const uint32_t* b) {
    asm volatile(
        "mma.sync.aligned.m16n8k16.row.col.f32.f16.f16.f32 "
        "{%0,%1,%2,%3}, {%4,%5,%6,%7}, {%8,%9}, {%0,%1,%2,%3};"
        : "+f"(d[0]), "+f"(d[1]), "+f"(d[2]), "+f"(d[3])
        : "r"(a[0]), "r"(a[1]), "r"(a[2]), "r"(a[3]), "r"(b[0]), "r"(b[1]));
}
__device__ __forceinline__ float ex2(float x) {
    float y;
    asm("ex2.approx.f32 %0, %1;" : "=f"(y) : "f"(x));
    return y;
}

// ---------------------------------------------------------------------------
// Mask dtype detection (+ pointer table setup on thread 0)
// ---------------------------------------------------------------------------
__global__ void detect_mask_kernel(const unsigned* __restrict__ qm,
                                   const unsigned* __restrict__ km, int nints,
                                   const float* s0, const float* s1,
                                   const float* s2, const float* s3,
                                   const float* s4, const float* s5)
{
    if (threadIdx.x == 0) {
        g_round_src[0] = s0; g_round_src[1] = s1; g_round_src[2] = s2;
        g_round_src[3] = s3; g_round_src[4] = s4; g_round_src[5] = s5;
        g_round_dst[0] = g_W16[0]; g_round_dst[1] = g_W16[1];
        g_round_dst[2] = g_W16[2]; g_round_dst[3] = g_W16[3];
        g_round_dst[4] = g_x16[0]; g_round_dst[5] = g_x16[1];
    }
    __shared__ int s_i, s_f;
    for (int b = 0; b < 2; b++) {
        if (threadIdx.x == 0) { s_i = 1; s_f = 1; }
        __syncthreads();
        const unsigned* p = b ? km : qm;
        int li = 1, lf = 1;
        for (int i = threadIdx.x; i < nints; i += blockDim.x) {
            unsigned v = p[i];
            if (v > 1u) li = 0;
            if (v != 0u && v != 0x3f800000u) lf = 0;
        }
        if (!li) atomicAnd(&s_i, 0);
        if (!lf) atomicAnd(&s_f, 0);
        __syncthreads();
        if (threadIdx.x == 0)
            g_mask_mode[b] = s_i ? 1 : (s_f ? 2 : 0);
        __syncthreads();
    }
}

__device__ __forceinline__ bool mask_at(const void* p, int i, int mode) {
    if (mode == 1) return ((const int*)p)[i] != 0;
    if (mode == 2) return ((const float*)p)[i] != 0.f;
    return ((const unsigned char*)p)[i] != 0;
}

// ---------------------------------------------------------------------------
// Mega prep kernel (one launch): blockIdx.x ranges select role.
// ---------------------------------------------------------------------------
#define PREP_BLOCKS 5056

__global__ void __launch_bounds__(256)
prep_kernel(const float* __restrict__ cq, const float* __restrict__ ck,
            const float* __restrict__ f0, const float* __restrict__ f1,
            const float* __restrict__ f2,
            float2* __restrict__ tq, float2* __restrict__ tk,
            const void* __restrict__ qmr, const void* __restrict__ kmr,
            __nv_bfloat16* __restrict__ E)
{
    __shared__ float ky[NK_], kx[NK_];
    __shared__ unsigned char kbad[NK_];
    __shared__ float qy8[8], qx8[8];
    __shared__ unsigned char qbad[8];

    int bid = blockIdx.x;

    if (bid < 1024) {                       // weight rounding
        int mat = bid >> 8, blk = bid & 255;
        const float* x = g_round_src[mat];
        __half* h = g_round_dst[mat];
        int base = blk * 1024 + threadIdx.x;
        #pragma unroll
        for (int j = 0; j < 4; j++) {
            int idx = base + j * 256;
            float4 v = ((const float4*)x)[idx];
            ((__half2*)h)[2*idx]   = __floats2half2_rn(v.x, v.y);
            ((__half2*)h)[2*idx+1] = __floats2half2_rn(v.z, v.w);
        }
        return;
    }
    bid -= 1024;
    if (bid < 2304) {                       // act rounding
        int which = bid / 1152, blk = bid - which * 1152;
        const float* x = g_round_src[4 + which];
        __half* h = g_round_dst[4 + which];
        int base = blk * 1024 + threadIdx.x;
        #pragma unroll
        for (int j = 0; j < 4; j++) {
            int idx = base + j * 256;
            float4 v = ((const float4*)x)[idx];
            ((__half2*)h)[2*idx]   = __floats2half2_rn(v.x, v.y);
            ((__half2*)h)[2*idx+1] = __floats2half2_rn(v.z, v.w);
        }
        return;
    }
    bid -= 2304;
    if (bid < 1152) {                       // ropetab
        int side = bid / 576, blk = bid - side * 576;
        const float* coords = side ? ck : cq;
        float2* tab = side ? tk : tq;
        int tok = blk * 8 + (threadIdx.x >> 5);
        int tid = threadIdx.x & 31;
        float coord, fr;
        if (tid < 12)      { coord = coords[tok * 3 + 0]; fr = f0[tid]; }
        else if (tid < 22) { coord = coords[tok * 3 + 1]; fr = f1[tid - 12]; }
        else               { coord = coords[tok * 3 + 2]; fr = f2[tid - 22]; }
        float arg = 1.5707963267948966f * coord * fr;
        float s, c;
        sincosf(arg, &s, &c);
        tab[tok * 32 + tid] = make_float2(c, s);
        return;
    }
    bid -= 1152;                            // bias
    {
        int f = bid / 72, qb = bid - f * 72;
        const int mq = g_mask_mode[0], mk = g_mask_mode[1];
        for (int k = threadIdx.x; k < NK_; k += 256) {
            int ki = f * NK_ + k;
            ky[k]  = ck[ki * 3 + 1];
            kx[k]  = ck[ki * 3 + 2];
            kbad[k] = mask_at(kmr, ki, mk) ? 1 : 0;
        }
        if (threadIdx.x < 8) {
            int q = qb * 8 + threadIdx.x;
            int qi = f * NQ_ + q;
            qy8[threadIdx.x] = cq[qi * 3 + 1];
            qx8[threadIdx.x] = cq[qi * 3 + 2];
            qbad[threadIdx.x] = mask_at(qmr, qi, mq) ? 1 : 0;
        }
        __syncthreads();
        for (int e = threadIdx.x; e < 8 * NK_; e += 256) {
            int r = e / NK_, k = e - r * NK_;
            int q = qb * 8 + r;
            float dy = qy8[r] - ky[k];
            float dx = qx8[r] - kx[k];
            float dist = sqrtf(dy * dy + dx * dx);
            bool bad = qbad[r] || kbad[k] || (dist > 0.5f);
            E[(size_t)(f * NQ_ + q) * NK_ + k] =
                __float2bfloat16(bad ? -3.0e38f : __expf(-10.f * dist));
        }
    }
}

// ---------------------------------------------------------------------------
// Merged Q/K/V HMMA GEMM (grid.z selects operands + epilogue)
// ---------------------------------------------------------------------------
#define TILE_B 10240
#define STG    (2 * TILE_B)
#define NCH    32

__global__ void __launch_bounds__(128, 2)
gemm_qkv(const __half* __restrict__ x16q, const __half* __restrict__ x16kv,
         const __half* __restrict__ Wqh, const __half* __restrict__ Wkh,
         const __half* __restrict__ Wvh,
         const float* __restrict__ bq, const float* __restrict__ bk,
         const float* __restrict__ bv,
         __half* __restrict__ aQh, __half* __restrict__ aKr,
         __half* __restrict__ vtr,
         const float2* __restrict__ rtq, const float2* __restrict__ rtk)
{
    extern __shared__ char dsm[];
    const uint32_t sbase = smem_u32(dsm);

    const int z = blockIdx.z;
    const __half* Ah = (z == 0) ? x16q : x16kv;
    const __half* Bh = (z == 0) ? Wqh : (z == 1) ? Wkh : Wvh;
    const float* bias = (z == 0) ? bq : (z == 1) ? bk : bv;
    __half* O1 = (z == 0) ? aQh : (z == 1) ? aKr : vtr;
    const float2* rtab = (z == 0) ? rtq : rtk;

    const int tid  = threadIdx.x;
    const int wid  = tid >> 5;
    const int lane = tid & 31;
    const int m0 = blockIdx.y * 128;
    const int n0 = blockIdx.x * 128;
    const int wm = (wid & 1) * 64;
    const int wn = (wid >> 1) * 64;

    float acc[4][8][4];
    #pragma unroll
    for (int mt = 0; mt < 4; mt++)
        #pragma unroll
        for (int nt = 0; nt < 8; nt++)
            #pragma unroll
            for (int r = 0; r < 4; r++) acc[mt][nt][r] = 0.f;

    int l_tl[8], l_row[8], l_c[8];
    #pragma unroll
    for (int j = 0; j < 8; j++) {
        int i = tid + j * 128;
        l_tl[j]  = i >> 9;
        l_row[j] = (i & 511) >> 2;
        l_c[j]   = i & 3;
    }

    auto issue_load = [&](int ch, int buf) {
        const int k0 = ch * 32;
        #pragma unroll
        for (int j = 0; j < 8; j++) {
            const __half* g = l_tl[j]
                ? Bh + (size_t)(n0 + l_row[j]) * GK + k0 + l_c[j] * 8
                : Ah + (size_t)(m0 + l_row[j]) * GK + k0 + l_c[j] * 8;
            uint32_t s = sbase + buf * STG + l_tl[j] * TILE_B
                       + l_row[j] * 80 + l_c[j] * 16;
            cp16(s, g);
        }
        cp_commit();
    };

    issue_load(0, 0);
    issue_load(1, 1);

    for (int ch = 0; ch < NCH; ch++) {
        if (ch == NCH - 1) cp_wait0(); else cp_wait1();
        __syncthreads();
        if (ch + 2 < NCH) issue_load(ch + 2, (ch + 2) % 3);

        const uint32_t hbase = sbase + (ch % 3) * STG;
        const uint32_t bbase = hbase + TILE_B;

        #pragma unroll
        for (int ks = 0; ks < 2; ks++) {
            uint32_t b[8][2];
            #pragma unroll
            for (int np = 0; np < 4; np++) {
                uint32_t addr = bbase
                    + (wn + np * 16 + (lane & 7) + ((lane >> 4) & 1) * 8) * 80
                    + ((lane >> 3) & 1) * 16 + ks * 32;
                uint32_t r[4];
                ldm_x4(r, addr);
                b[np * 2][0] = r[0];     b[np * 2][1] = r[1];
                b[np * 2 + 1][0] = r[2]; b[np * 2 + 1][1] = r[3];
            }
            uint32_t a[4][4];
            #pragma unroll
            for (int mt = 0; mt < 4; mt++) {
                uint32_t addr = hbase + (wm + mt * 16 + (lane & 15)) * 80
                              + (lane >> 4) * 16 + ks * 32;
                ldm_x4(a[mt], addr);
            }
            #pragma unroll
            for (int mt = 0; mt < 4; mt++)
                #pragma unroll
                for (int nt = 0; nt < 8; nt++)
                    mma_f16(acc[mt][nt], a[mt], b[nt]);
        }
    }

    const int cb_loc = wn + (lane & 3) * 2;
    const int cbase = n0 + cb_loc;
    float bv_[8][2];
    #pragma unroll
    for (int nt = 0; nt < 8; nt++) {
        bv_[nt][0] = bias[cbase + nt * 8];
        bv_[nt][1] = bias[cbase + nt * 8 + 1];
    }

    if (z < 2) {
        float2* st = (float2*)dsm;
        __syncthreads();
        for (int i = tid; i < 128 * 32; i += 128)
            st[i] = rtab[(size_t)(m0 + (i >> 5)) * 32 + (i & 31)];
        __syncthreads();

        #pragma unroll
        for (int mt = 0; mt < 4; mt++) {
            int rl0 = wm + mt * 16 + (lane >> 2);
            #pragma unroll
            for (int nt = 0; nt < 8; nt++) {
                int col = cbase + nt * 8;
                float v0 = acc[mt][nt][0] + bv_[nt][0];
                float v1 = acc[mt][nt][1] + bv_[nt][1];
                float v2 = acc[mt][nt][2] + bv_[nt][0];
                float v3 = acc[mt][nt][3] + bv_[nt][1];
                int j = ((cb_loc + nt * 8) & 63) >> 1;
                float2 cs0 = st[rl0 * 32 + j];
                float2 cs1 = st[(rl0 + 8) * 32 + j];
                float y0 = v0 * cs0.x - v1 * cs0.y;
                float y1 = v1 * cs0.x + v0 * cs0.y;
                float y2 = v2 * cs1.x - v3 * cs1.y;
                float y3 = v3 * cs1.x + v2 * cs1.y;
                ((__half2*)O1)[((size_t)(m0 + rl0) * D_ + col) >> 1]     = __floats2half2_rn(y0, y1);
                ((__half2*)O1)[((size_t)(m0 + rl0 + 8) * D_ + col) >> 1] = __floats2half2_rn(y2, y3);
            }
        }
    } else {
        __half* sT = (__half*)dsm;
        __syncthreads();
        #pragma unroll
        for (int mt = 0; mt < 4; mt++) {
            int rl0 = wm + mt * 16 + (lane >> 2);
            #pragma unroll
            for (int nt = 0; nt < 8; nt++) {
                int cl = cb_loc + nt * 8;
                float v0 = acc[mt][nt][0] + bv_[nt][0];
                float v1 = acc[mt][nt][1] + bv_[nt][1];
                float v2 = acc[mt][nt][2] + bv_[nt][0];
                float v3 = acc[mt][nt][3] + bv_[nt][1];
                *(__half2*)&sT[rl0 * 130 + cl]       = __floats2half2_rn(v0, v1);
                *(__half2*)&sT[(rl0 + 8) * 130 + cl] = __floats2half2_rn(v2, v3);
            }
        }
        __syncthreads();
        for (int idx = tid; idx < 128 * 64; idx += 128) {
            int dl = idx >> 6, kp = idx & 63;
            int tok = m0 + 2 * kp;
            int f = tok / NQ_;
            int key = tok - f * NQ_;
            int gd = n0 + dl;
            int h = gd >> 6, dh = gd & 63;
            __half a = sT[(2 * kp) * 130 + dl];
            __half b = sT[(2 * kp + 1) * 130 + dl];
            size_t oi = (((size_t)(f * 16 + h) * 64 + dh) * NK_ + key) >> 1;
            ((__half2*)O1)[oi] = __halves2half2(a, b);
        }
    }
}

// ---------------------------------------------------------------------------
// Wo GEMM: fp32 out (+bias)
// ---------------------------------------------------------------------------
__global__ void __launch_bounds__(128, 2)
gemm_wo(const __half* __restrict__ Ah, const __half* __restrict__ Bh,
        const float* __restrict__ bias, float* __restrict__ C)
{
    extern __shared__ char dsm[];
    const uint32_t sbase = smem_u32(dsm);

    const int tid  = threadIdx.x;
    const int wid  = tid >> 5;
    const int lane = tid & 31;
    const int m0 = blockIdx.y * 128;
    const int n0 = blockIdx.x * 128;
    const int wm = (wid & 1) * 64;
    const int wn = (wid >> 1) * 64;

    float acc[4][8][4];
    #pragma unroll
    for (int mt = 0; mt < 4; mt++)
        #pragma unroll
        for (int nt = 0; nt < 8; nt++)
            #pragma unroll
            for (int r = 0; r < 4; r++) acc[mt][nt][r] = 0.f;

    int l_tl[8], l_row[8], l_c[8];
    #pragma unroll
    for (int j = 0; j < 8; j++) {
        int i = tid + j * 128;
        l_tl[j]  = i >> 9;
        l_row[j] = (i & 511) >> 2;
        l_c[j]   = i & 3;
    }

    auto issue_load = [&](int ch, int buf) {
        const int k0 = ch * 32;
        #pragma unroll
        for (int j = 0; j < 8; j++) {
            const __half* g = l_tl[j]
                ? Bh + (size_t)(n0 + l_row[j]) * GK + k0 + l_c[j] * 8
                : Ah + (size_t)(m0 + l_row[j]) * GK + k0 + l_c[j] * 8;
            uint32_t s = sbase + buf * STG + l_tl[j] * TILE_B
                       + l_row[j] * 80 + l_c[j] * 16;
            cp16(s, g);
        }
        cp_commit();
    };

    issue_load(0, 0);
    issue_load(1, 1);

    for (int ch = 0; ch < NCH; ch++) {
        if (ch == NCH - 1) cp_wait0(); else cp_wait1();
        __syncthreads();
        if (ch + 2 < NCH) issue_load(ch + 2, (ch + 2) % 3);

        const uint32_t hbase = sbase + (ch % 3) * STG;
        const uint32_t bbase = hbase + TILE_B;

        #pragma unroll
        for (int ks = 0; ks < 2; ks++) {
            uint32_t b[8][2];
            #pragma unroll
            for (int np = 0; np < 4; np++) {
                uint32_t addr = bbase
                    + (wn + np * 16 + (lane & 7) + ((lane >> 4) & 1) * 8) * 80
                    + ((lane >> 3) & 1) * 16 + ks * 32;
                uint32_t r[4];
                ldm_x4(r, addr);
                b[np * 2][0] = r[0];     b[np * 2][1] = r[1];
                b[np * 2 + 1][0] = r[2]; b[np * 2 + 1][1] = r[3];
            }
            uint32_t a[4][4];
            #pragma unroll
            for (int mt = 0; mt < 4; mt++) {
                uint32_t addr = hbase + (wm + mt * 16 + (lane & 15)) * 80
                              + (lane >> 4) * 16 + ks * 32;
                ldm_x4(a[mt], addr);
            }
            #pragma unroll
            for (int mt = 0; mt < 4; mt++)
                #pragma unroll
                for (int nt = 0; nt < 8; nt++)
                    mma_f16(acc[mt][nt], a[mt], b[nt]);
        }
    }

    const int cbase = n0 + wn + (lane & 3) * 2;
    float bv[8][2];
    #pragma unroll
    for (int nt = 0; nt < 8; nt++) {
        bv[nt][0] = bias[cbase + nt * 8];
        bv[nt][1] = bias[cbase + nt * 8 + 1];
    }
    #pragma unroll
    for (int mt = 0; mt < 4; mt++) {
        int r0 = m0 + wm + mt * 16 + (lane >> 2);
        #pragma unroll
        for (int nt = 0; nt < 8; nt++) {
            int c = cbase + nt * 8;
            float2 v0 = { acc[mt][nt][0] + bv[nt][0], acc[mt][nt][1] + bv[nt][1] };
            float2 v1 = { acc[mt][nt][2] + bv[nt][0], acc[mt][nt][3] + bv[nt][1] };
            *(float2*)&C[(size_t)r0 * GN + c]       = v0;
            *(float2*)&C[(size_t)(r0 + 8) * GN + c] = v1;
        }
    }
}

// ---------------------------------------------------------------------------
// HMMA flash attention, cp.async double-buffered K/V/E tiles.
// smem: 2 stages x (K 9216 + V 9216 + E 9216) = 55296 B.
// ---------------------------------------------------------------------------
#define ASTG 27648
#define ATT_SMEM (2 * ASTG)

__global__ void __launch_bounds__(128)
attn_mma(const __half* __restrict__ Qh,
         const __half* __restrict__ Kr, const __half* __restrict__ Vtr,
         const __nv_bfloat16* __restrict__ E, const float* __restrict__ alpha,
         __half* __restrict__ Yh)
{
    extern __shared__ char sm[];
    const uint32_t sbase = smem_u32(sm);

    const int tid = threadIdx.x;
    const int w = tid >> 5, lane = tid & 31;
    const int c = lane & 3, rg = lane >> 2;
    const int qb = blockIdx.x, fh = blockIdx.y;
    const int f = fh >> 4, h = fh & 15;
    const int tok0 = f * NQ_;
    const int q0 = qb * 64;
    const float alph = alpha[h];
    const int rl = 16 * w + rg;

    // stage Q through stage-0 K region, extract resident A fragments
    uint32_t* sQ = (uint32_t*)sm;
    for (int i = tid; i < 512; i += 128) {
        int row = i >> 3, c16 = i & 7;
        size_t go = (size_t)(tok0 + q0 + row) * D_ + h * 64 + c16 * 8;
        *(uint4*)(sQ + row * 36 + c16 * 4) = *(const uint4*)(Qh + go);
    }
    __syncthreads();
    uint32_t qhF[4][4];
    #pragma unroll
    for (int s = 0; s < 4; s++) {
        qhF[s][0] = sQ[rl * 36 + 8 * s + c];
        qhF[s][1] = sQ[(rl + 8) * 36 + 8 * s + c];
        qhF[s][2] = sQ[rl * 36 + 8 * s + c + 4];
        qhF[s][3] = sQ[(rl + 8) * 36 + 8 * s + c + 4];
    }
    __syncthreads();

    // async tile loader: K, V, E into stage buf (1536 cp16 per tile)
    auto issue_tile = [&](int kt, int buf) {
        const int k0 = kt * 64;
        uint32_t kb = sbase + buf * ASTG;
        uint32_t vb = kb + 9216;
        uint32_t eb = kb + 18432;
        for (int i = tid; i < 512; i += 128) {
            int row = i >> 3, c16 = i & 7;
            cp16(kb + row * 144 + c16 * 16,
                 Kr + (size_t)(tok0 + k0 + row) * D_ + h * 64 + c16 * 8);
            cp16(vb + row * 144 + c16 * 16,
                 Vtr + (size_t)fh * (64 * NK_) + (size_t)row * NK_ + k0 + c16 * 8);
            cp16(eb + row * 144 + c16 * 16,
                 E + (size_t)(tok0 + q0 + row) * NK_ + k0 + c16 * 8);
        }
        cp_commit();
    };

    float o[8][4];
    #pragma unroll
    for (int n = 0; n < 8; n++)
        #pragma unroll
        for (int r = 0; r < 4; r++) o[n][r] = 0.f;
    float m0r = -3.0e38f, m1r = -3.0e38f, l0r = 0.f, l1r = 0.f;

    issue_tile(0, 0);

    for (int kt = 0; kt < 9; kt++) {
        if (kt + 1 < 9) issue_tile(kt + 1, (kt + 1) & 1);
        if (kt == 8) cp_wait0(); else cp_wait1();
        __syncthreads();

        const int buf = kt & 1;
        uint32_t* sK = (uint32_t*)(sm + buf * ASTG);
        uint32_t* sV = (uint32_t*)(sm + buf * ASTG + 9216);
        __nv_bfloat16* sE = (__nv_bfloat16*)(sm + buf * ASTG + 18432);

        // S = Q K^T
        float s[8][4];
        #pragma unroll
        for (int n = 0; n < 8; n++)
            #pragma unroll
            for (int r = 0; r < 4; r++) s[n][r] = 0.f;
        #pragma unroll
        for (int st = 0; st < 4; st++) {
            #pragma unroll
            for (int n = 0; n < 8; n++) {
                int bi = (8 * n + rg) * 36 + 8 * st + c;
                uint32_t bh[2] = { sK[bi], sK[bi + 4] };
                mma_f16(s[n], qhF[st], bh);
            }
        }

        float mn0 = m0r, mn1 = m1r;
        #pragma unroll
        for (int n = 0; n < 8; n++) {
            float2 e0 = __bfloat1622float2(
                *(__nv_bfloat162*)(sE + rl * 72 + 8 * n + 2 * c));
            float2 e1 = __bfloat1622float2(
                *(__nv_bfloat162*)(sE + (rl + 8) * 72 + 8 * n + 2 * c));
            s[n][0] = (e0.x < 0.f) ? NEGBIG : fmaf(s[n][0], 0.125f, alph * e0.x);
            s[n][1] = (e0.y < 0.f) ? NEGBIG : fmaf(s[n][1], 0.125f, alph * e0.y);
            s[n][2] = (e1.x < 0.f) ? NEGBIG : fmaf(s[n][2], 0.125f, alph * e1.x);
            s[n][3] = (e1.y < 0.f) ? NEGBIG : fmaf(s[n][3], 0.125f, alph * e1.y);
            mn0 = fmaxf(mn0, fmaxf(s[n][0], s[n][1]));
            mn1 = fmaxf(mn1, fmaxf(s[n][2], s[n][3]));
        }
        mn0 = fmaxf(mn0, __shfl_xor_sync(0xffffffffu, mn0, 1));
        mn0 = fmaxf(mn0, __shfl_xor_sync(0xffffffffu, mn0, 2));
        mn1 = fmaxf(mn1, __shfl_xor_sync(0xffffffffu, mn1, 1));
        mn1 = fmaxf(mn1, __shfl_xor_sync(0xffffffffu, mn1, 2));
        float f0 = ex2((m0r - mn0) * LOG2E);
        float f1 = ex2((m1r - mn1) * LOG2E);
        m0r = mn0; m1r = mn1;

        float rs0 = 0.f, rs1 = 0.f;
        uint32_t phL[8], phH[8];
        #pragma unroll
        for (int n = 0; n < 8; n++) {
            float p0 = ex2((s[n][0] - mn0) * LOG2E);
            float p1 = ex2((s[n][1] - mn0) * LOG2E);
            float p2 = ex2((s[n][2] - mn1) * LOG2E);
            float p3 = ex2((s[n][3] - mn1) * LOG2E);
            rs0 += p0 + p1;
            rs1 += p2 + p3;
            o[n][0] *= f0; o[n][1] *= f0; o[n][2] *= f1; o[n][3] *= f1;
            __half2 bL = __floats2half2_rn(p0, p1);
            phL[n] = *(uint32_t*)&bL;
            __half2 bH = __floats2half2_rn(p2, p3);
            phH[n] = *(uint32_t*)&bH;
        }
        rs0 += __shfl_xor_sync(0xffffffffu, rs0, 1);
        rs0 += __shfl_xor_sync(0xffffffffu, rs0, 2);
        rs1 += __shfl_xor_sync(0xffffffffu, rs1, 1);
        rs1 += __shfl_xor_sync(0xffffffffu, rs1, 2);
        l0r = l0r * f0 + rs0;
        l1r = l1r * f1 + rs1;

        // O += P V
        #pragma unroll
        for (int st = 0; st < 4; st++) {
            uint32_t ah[4] = { phL[2 * st], phH[2 * st], phL[2 * st + 1], phH[2 * st + 1] };
            #pragma unroll
            for (int n = 0; n < 8; n++) {
                int bi = (8 * n + rg) * 36 + 8 * st + c;
                uint32_t vh[2] = { sV[bi], sV[bi + 4] };
                mma_f16(o[n], ah, vh);
            }
        }
        __syncthreads();
    }

    float i0 = 1.f / l0r, i1 = 1.f / l1r;
    #pragma unroll
    for (int n = 0; n < 8; n++) {
        size_t e0 = ((size_t)(tok0 + q0 + rl) * D_ + h * 64 + 8 * n + 2 * c) >> 1;
        size_t e1 = ((size_t)(tok0 + q0 + rl + 8) * D_ + h * 64 + 8 * n + 2 * c) >> 1;
        ((__half2*)Yh)[e0] = __floats2half2_rn(o[n][0] * i0, o[n][1] * i0);
        ((__half2*)Yh)[e1] = __floats2half2_rn(o[n][2] * i1, o[n][3] * i1);
    }
}

// ---------------------------------------------------------------------------
extern "C" void kernel_launch(void* const* d_in, const int* in_sizes, int n_in,
                              void* d_out, int out_size)
{
    (void)in_sizes; (void)n_in; (void)out_size;

    const float*   q_tokens  = (const float*)d_in[0];
    const float*   kv_tokens = (const float*)d_in[1];
    const float*   coords_q  = (const float*)d_in[2];
    const float*   coords_k  = (const float*)d_in[3];
    const void*    q_pad     = d_in[4];
    const void*    kv_pad    = d_in[5];
    const float*   Wq = (const float*)d_in[6];
    const float*   bq = (const float*)d_in[7];
    const float*   Wk = (const float*)d_in[8];
    const float*   bk = (const float*)d_in[9];
    const float*   Wv = (const float*)d_in[10];
    const float*   bv = (const float*)d_in[11];
    const float*   Wo = (const float*)d_in[12];
    const float*   bo = (const float*)d_in[13];
    const float*   alpha = (const float*)d_in[14];
    const float*   f0 = (const float*)d_in[15];
    const float*   f1 = (const float*)d_in[16];
    const float*   f2 = (const float*)d_in[17];
    float* out = (float*)d_out;

    __nv_bfloat16 *Eb;
    float2 *rtq, *rtk;
    cudaGetSymbolAddress((void**)&Eb, g_E);
    cudaGetSymbolAddress((void**)&rtq, g_rt);
    rtk = rtq + TOK * 32;

    __half *x16q, *x16kv, *yhi, *W16, *aQh, *aKr, *vtr;
    cudaGetSymbolAddress((void**)&x16q, g_x16);
    x16kv = x16q + TOK * D_;
    cudaGetSymbolAddress((void**)&yhi,  g_yhi);
    cudaGetSymbolAddress((void**)&W16, g_W16);
    cudaGetSymbolAddress((void**)&aQh, g_aQh);
    cudaGetSymbolAddress((void**)&aKr, g_aKr);
    cudaGetSymbolAddress((void**)&vtr, g_vtr);
    __half *Wqh = W16, *Wkh = W16 + D_ * D_, *Wvh = W16 + 2 * D_ * D_,
           *Woh = W16 + 3 * D_ * D_;

    const int gemm_smem = 3 * STG;  // 61440
    cudaFuncSetAttribute(gemm_qkv, cudaFuncAttributeMaxDynamicSharedMemorySize, gemm_smem);
    cudaFuncSetAttribute(gemm_wo,  cudaFuncAttributeMaxDynamicSharedMemorySize, gemm_smem);
    cudaFuncSetAttribute(attn_mma, cudaFuncAttributeMaxDynamicSharedMemorySize, ATT_SMEM);

    // masks + pointer tables
    detect_mask_kernel<<<1, 256>>>((const unsigned*)q_pad, (const unsigned*)kv_pad,
                                   TOK / 4, Wq, Wk, Wv, Wo, q_tokens, kv_tokens);

    // mega prep: weight/act rounding + rope tables + bias, one launch
    prep_kernel<<<PREP_BLOCKS, 256>>>(coords_q, coords_k, f0, f1, f2,
                                      rtq, rtk, q_pad, kv_pad, Eb);

    // merged Q/K/V projection (one launch, 864 CTAs)
    gemm_qkv<<<dim3(GN / 128, TOK / 128, 3), 128, gemm_smem>>>(
        x16q, x16kv, Wqh, Wkh, Wvh, bq, bk, bv, aQh, aKr, vtr, rtq, rtk);

    attn_mma<<<dim3(9, 128), 128, ATT_SMEM>>>(aQh, aKr, vtr, Eb, alpha, yhi);

    gemm_wo<<<dim3(GN / 128, TOK / 128), 128, gemm_smem>>>(yhi, Woh, bo, out);
}

// round 17
// speedup vs baseline: 2.1041x; 1.0362x over previous
#include <cuda_runtime.h>
#include <cuda_bf16.h>
#include <cuda_fp16.h>
#include <cstdint>
#include <cstddef>
#include <math.h>

// Problem constants
#define B_   2
#define T_   4
#define NQ_  576
#define NK_  576
#define D_   1024
#define H_   16
#define DH_  64
#define TOK  (B_*T_*NQ_)
#define NEGBIG (-1.7014118e38f)
#define LOG2E 1.4426950408889634f
#define QSCL 0.18033688011112042f   // 0.125 * log2(e)

#define GK 1024
#define GN 1024

// Scratch (device globals; no dynamic allocation allowed)
__device__ int   g_mask_mode[2];
__device__ __nv_bfloat16 g_E[8 * NQ_ * NK_];
__device__ float2 g_rt[2][TOK * 32];   // cos/sin tables: [0]=q, [1]=k

// fp16 operands (all single-rounded)
__device__ __half g_x16[2][TOK * D_];  // [0]=q_tokens, [1]=kv_tokens
__device__ __half g_yhi[TOK * D_];
__device__ __half g_W16[4][D_ * D_];   // Wq, Wk, Wv, Wo

// attention operands (fp16): Q (rope'd, pre-scaled), K (rope'd), V^T
__device__ __half g_aQh[TOK * D_];
__device__ __half g_aKr[TOK * D_];
__device__ __half g_vtr[128 * 64 * NK_];

__device__ const float* g_round_src[6];
__device__ __half*      g_round_dst[6];

// ---------------------------------------------------------------------------
// Family-portable PTX helpers
// ---------------------------------------------------------------------------
__device__ __forceinline__ uint32_t smem_u32(const void* p) {
    uint32_t a;
    asm("{ .reg .u64 t; cvta.to.shared.u64 t, %1; cvt.u32.u64 %0, t; }"
        : "=r"(a) : "l"(p));
    return a;
}
__device__ __forceinline__ void cp16(uint32_t s, const void* g) {
    asm volatile("cp.async.cg.shared.global [%0], [%1], 16;"
                 :: "r"(s), "l"(g) : "memory");
}
__device__ __forceinline__ void cp_commit() {
    asm volatile("cp.async.commit_group;" ::: "memory");
}
__device__ __forceinline__ void cp_wait1() {
    asm volatile("cp.async.wait_group 1;" ::: "memory");
}
__device__ __forceinline__ void cp_wait0() {
    asm volatile("cp.async.wait_group 0;" ::: "memory");
}
__device__ __forceinline__ void ldm_x4(uint32_t* r, uint32_t addr) {
    asm volatile("ldmatrix.sync.aligned.m8n8.x4.shared.b16 {%0,%1,%2,%3}, [%4];"
                 : "=r"(r[0]), "=r"(r[1]), "=r"(r[2]), "=r"(r[3]) : "r"(addr));
}
__device__ __forceinline__ void mma_f16(float* d, const uint32_t* a, const uint32_t* b) {
    asm volatile(
        "mma.sync.aligned.m16n8k16.row.col.f32.f16.f16.f32 "
        "{%0,%1,%2,%3}, {%4,%5,%6,%7}, {%8,%9}, {%0,%1,%2,%3};"
        : "+f"(d[0]), "+f"(d[1]), "+f"(d[2]), "+f"(d[3])
        : "r"(a[0]), "r"(a[1]), "r"(a[2]), "r"(a[3]), "r"(b[0]), "r"(b[1]));
}
__device__ __forceinline__ float ex2(float x) {
    float y;
    asm("ex2.approx.f32 %0, %1;" : "=f"(y) : "f"(x));
    return y;
}

// ---------------------------------------------------------------------------
// Mask dtype detection (+ pointer table setup on thread 0)
// ---------------------------------------------------------------------------
__global__ void detect_mask_kernel(const unsigned* __restrict__ qm,
                                   const unsigned* __restrict__ km, int nints,
                                   const float* s0, const float* s1,
                                   const float* s2, const float* s3,
                                   const float* s4, const float* s5)
{
    if (threadIdx.x == 0) {
        g_round_src[0] = s0; g_round_src[1] = s1; g_round_src[2] = s2;
        g_round_src[3] = s3; g_round_src[4] = s4; g_round_src[5] = s5;
        g_round_dst[0] = g_W16[0]; g_round_dst[1] = g_W16[1];
        g_round_dst[2] = g_W16[2]; g_round_dst[3] = g_W16[3];
        g_round_dst[4] = g_x16[0]; g_round_dst[5] = g_x16[1];
    }
    __shared__ int s_i, s_f;
    for (int b = 0; b < 2; b++) {
        if (threadIdx.x == 0) { s_i = 1; s_f = 1; }
        __syncthreads();
        const unsigned* p = b ? km : qm;
        int li = 1, lf = 1;
        for (int i = threadIdx.x; i < nints; i += blockDim.x) {
            unsigned v = p[i];
            if (v > 1u) li = 0;
            if (v != 0u && v != 0x3f800000u) lf = 0;
        }
        if (!li) atomicAnd(&s_i, 0);
        if (!lf) atomicAnd(&s_f, 0);
        __syncthreads();
        if (threadIdx.x == 0)
            g_mask_mode[b] = s_i ? 1 : (s_f ? 2 : 0);
        __syncthreads();
    }
}

__device__ __forceinline__ bool mask_at(const void* p, int i, int mode) {
    if (mode == 1) return ((const int*)p)[i] != 0;
    if (mode == 2) return ((const float*)p)[i] != 0.f;
    return ((const unsigned char*)p)[i] != 0;
}

// ---------------------------------------------------------------------------
// Mega prep kernel (one launch): blockIdx.x ranges select role.
// ---------------------------------------------------------------------------
#define PREP_BLOCKS 5056

__global__ void __launch_bounds__(256)
prep_kernel(const float* __restrict__ cq, const float* __restrict__ ck,
            const float* __restrict__ f0, const float* __restrict__ f1,
            const float* __restrict__ f2,
            float2* __restrict__ tq, float2* __restrict__ tk,
            const void* __restrict__ qmr, const void* __restrict__ kmr,
            __nv_bfloat16* __restrict__ E)
{
    __shared__ float ky[NK_], kx[NK_];
    __shared__ unsigned char kbad[NK_];
    __shared__ float qy8[8], qx8[8];
    __shared__ unsigned char qbad[8];

    int bid = blockIdx.x;

    if (bid < 1024) {                       // weight rounding
        int mat = bid >> 8, blk = bid & 255;
        const float* x = g_round_src[mat];
        __half* h = g_round_dst[mat];
        int base = blk * 1024 + threadIdx.x;
        #pragma unroll
        for (int j = 0; j < 4; j++) {
            int idx = base + j * 256;
            float4 v = ((const float4*)x)[idx];
            ((__half2*)h)[2*idx]   = __floats2half2_rn(v.x, v.y);
            ((__half2*)h)[2*idx+1] = __floats2half2_rn(v.z, v.w);
        }
        return;
    }
    bid -= 1024;
    if (bid < 2304) {                       // act rounding
        int which = bid / 1152, blk = bid - which * 1152;
        const float* x = g_round_src[4 + which];
        __half* h = g_round_dst[4 + which];
        int base = blk * 1024 + threadIdx.x;
        #pragma unroll
        for (int j = 0; j < 4; j++) {
            int idx = base + j * 256;
            float4 v = ((const float4*)x)[idx];
            ((__half2*)h)[2*idx]   = __floats2half2_rn(v.x, v.y);
            ((__half2*)h)[2*idx+1] = __floats2half2_rn(v.z, v.w);
        }
        return;
    }
    bid -= 2304;
    if (bid < 1152) {                       // ropetab
        int side = bid / 576, blk = bid - side * 576;
        const float* coords = side ? ck : cq;
        float2* tab = side ? tk : tq;
        int tok = blk * 8 + (threadIdx.x >> 5);
        int tid = threadIdx.x & 31;
        float coord, fr;
        if (tid < 12)      { coord = coords[tok * 3 + 0]; fr = f0[tid]; }
        else if (tid < 22) { coord = coords[tok * 3 + 1]; fr = f1[tid - 12]; }
        else               { coord = coords[tok * 3 + 2]; fr = f2[tid - 22]; }
        float arg = 1.5707963267948966f * coord * fr;
        float s, c;
        sincosf(arg, &s, &c);
        tab[tok * 32 + tid] = make_float2(c, s);
        return;
    }
    bid -= 1152;                            // bias
    {
        int f = bid / 72, qb = bid - f * 72;
        const int mq = g_mask_mode[0], mk = g_mask_mode[1];
        for (int k = threadIdx.x; k < NK_; k += 256) {
            int ki = f * NK_ + k;
            ky[k]  = ck[ki * 3 + 1];
            kx[k]  = ck[ki * 3 + 2];
            kbad[k] = mask_at(kmr, ki, mk) ? 1 : 0;
        }
        if (threadIdx.x < 8) {
            int q = qb * 8 + threadIdx.x;
            int qi = f * NQ_ + q;
            qy8[threadIdx.x] = cq[qi * 3 + 1];
            qx8[threadIdx.x] = cq[qi * 3 + 2];
            qbad[threadIdx.x] = mask_at(qmr, qi, mq) ? 1 : 0;
        }
        __syncthreads();
        for (int e = threadIdx.x; e < 8 * NK_; e += 256) {
            int r = e / NK_, k = e - r * NK_;
            int q = qb * 8 + r;
            float dy = qy8[r] - ky[k];
            float dx = qx8[r] - kx[k];
            float dist = sqrtf(dy * dy + dx * dx);
            bool bad = qbad[r] || kbad[k] || (dist > 0.5f);
            E[(size_t)(f * NQ_ + q) * NK_ + k] =
                __float2bfloat16(bad ? -3.0e38f : __expf(-10.f * dist));
        }
    }
}

// ---------------------------------------------------------------------------
// Merged Q/K/V HMMA GEMM (grid.z selects operands + epilogue):
//   z=0: aQh = rope(...) * QSCL  (pre-scaled for log2-domain softmax)
//   z=1: aKr = rope(...)
//   z=2: vtr = transpose(...)
// ---------------------------------------------------------------------------
#define TILE_B 10240
#define STG    (2 * TILE_B)
#define NCH    32

__global__ void __launch_bounds__(128, 2)
gemm_qkv(const __half* __restrict__ x16q, const __half* __restrict__ x16kv,
         const __half* __restrict__ Wqh, const __half* __restrict__ Wkh,
         const __half* __restrict__ Wvh,
         const float* __restrict__ bq, const float* __restrict__ bk,
         const float* __restrict__ bv,
         __half* __restrict__ aQh, __half* __restrict__ aKr,
         __half* __restrict__ vtr,
         const float2* __restrict__ rtq, const float2* __restrict__ rtk)
{
    extern __shared__ char dsm[];
    const uint32_t sbase = smem_u32(dsm);

    const int z = blockIdx.z;
    const __half* Ah = (z == 0) ? x16q : x16kv;
    const __half* Bh = (z == 0) ? Wqh : (z == 1) ? Wkh : Wvh;
    const float* bias = (z == 0) ? bq : (z == 1) ? bk : bv;
    __half* O1 = (z == 0) ? aQh : (z == 1) ? aKr : vtr;
    const float2* rtab = (z == 0) ? rtq : rtk;

    const int tid  = threadIdx.x;
    const int wid  = tid >> 5;
    const int lane = tid & 31;
    const int m0 = blockIdx.y * 128;
    const int n0 = blockIdx.x * 128;
    const int wm = (wid & 1) * 64;
    const int wn = (wid >> 1) * 64;

    float acc[4][8][4];
    #pragma unroll
    for (int mt = 0; mt < 4; mt++)
        #pragma unroll
        for (int nt = 0; nt < 8; nt++)
            #pragma unroll
            for (int r = 0; r < 4; r++) acc[mt][nt][r] = 0.f;

    int l_tl[8], l_row[8], l_c[8];
    #pragma unroll
    for (int j = 0; j < 8; j++) {
        int i = tid + j * 128;
        l_tl[j]  = i >> 9;
        l_row[j] = (i & 511) >> 2;
        l_c[j]   = i & 3;
    }

    auto issue_load = [&](int ch, int buf) {
        const int k0 = ch * 32;
        #pragma unroll
        for (int j = 0; j < 8; j++) {
            const __half* g = l_tl[j]
                ? Bh + (size_t)(n0 + l_row[j]) * GK + k0 + l_c[j] * 8
                : Ah + (size_t)(m0 + l_row[j]) * GK + k0 + l_c[j] * 8;
            uint32_t s = sbase + buf * STG + l_tl[j] * TILE_B
                       + l_row[j] * 80 + l_c[j] * 16;
            cp16(s, g);
        }
        cp_commit();
    };

    issue_load(0, 0);
    issue_load(1, 1);

    for (int ch = 0; ch < NCH; ch++) {
        if (ch == NCH - 1) cp_wait0(); else cp_wait1();
        __syncthreads();
        if (ch + 2 < NCH) issue_load(ch + 2, (ch + 2) % 3);

        const uint32_t hbase = sbase + (ch % 3) * STG;
        const uint32_t bbase = hbase + TILE_B;

        #pragma unroll
        for (int ks = 0; ks < 2; ks++) {
            uint32_t b[8][2];
            #pragma unroll
            for (int np = 0; np < 4; np++) {
                uint32_t addr = bbase
                    + (wn + np * 16 + (lane & 7) + ((lane >> 4) & 1) * 8) * 80
                    + ((lane >> 3) & 1) * 16 + ks * 32;
                uint32_t r[4];
                ldm_x4(r, addr);
                b[np * 2][0] = r[0];     b[np * 2][1] = r[1];
                b[np * 2 + 1][0] = r[2]; b[np * 2 + 1][1] = r[3];
            }
            uint32_t a[4][4];
            #pragma unroll
            for (int mt = 0; mt < 4; mt++) {
                uint32_t addr = hbase + (wm + mt * 16 + (lane & 15)) * 80
                              + (lane >> 4) * 16 + ks * 32;
                ldm_x4(a[mt], addr);
            }
            #pragma unroll
            for (int mt = 0; mt < 4; mt++)
                #pragma unroll
                for (int nt = 0; nt < 8; nt++)
                    mma_f16(acc[mt][nt], a[mt], b[nt]);
        }
    }

    const int cb_loc = wn + (lane & 3) * 2;
    const int cbase = n0 + cb_loc;
    float bv_[8][2];
    #pragma unroll
    for (int nt = 0; nt < 8; nt++) {
        bv_[nt][0] = bias[cbase + nt * 8];
        bv_[nt][1] = bias[cbase + nt * 8 + 1];
    }

    if (z < 2) {
        float2* st = (float2*)dsm;
        __syncthreads();
        for (int i = tid; i < 128 * 32; i += 128)
            st[i] = rtab[(size_t)(m0 + (i >> 5)) * 32 + (i & 31)];
        __syncthreads();

        const float scl = (z == 0) ? QSCL : 1.0f;
        #pragma unroll
        for (int mt = 0; mt < 4; mt++) {
            int rl0 = wm + mt * 16 + (lane >> 2);
            #pragma unroll
            for (int nt = 0; nt < 8; nt++) {
                int col = cbase + nt * 8;
                float v0 = acc[mt][nt][0] + bv_[nt][0];
                float v1 = acc[mt][nt][1] + bv_[nt][1];
                float v2 = acc[mt][nt][2] + bv_[nt][0];
                float v3 = acc[mt][nt][3] + bv_[nt][1];
                int j = ((cb_loc + nt * 8) & 63) >> 1;
                float2 cs0 = st[rl0 * 32 + j];
                float2 cs1 = st[(rl0 + 8) * 32 + j];
                float y0 = (v0 * cs0.x - v1 * cs0.y) * scl;
                float y1 = (v1 * cs0.x + v0 * cs0.y) * scl;
                float y2 = (v2 * cs1.x - v3 * cs1.y) * scl;
                float y3 = (v3 * cs1.x + v2 * cs1.y) * scl;
                ((__half2*)O1)[((size_t)(m0 + rl0) * D_ + col) >> 1]     = __floats2half2_rn(y0, y1);
                ((__half2*)O1)[((size_t)(m0 + rl0 + 8) * D_ + col) >> 1] = __floats2half2_rn(y2, y3);
            }
        }
    } else {
        __half* sT = (__half*)dsm;
        __syncthreads();
        #pragma unroll
        for (int mt = 0; mt < 4; mt++) {
            int rl0 = wm + mt * 16 + (lane >> 2);
            #pragma unroll
            for (int nt = 0; nt < 8; nt++) {
                int cl = cb_loc + nt * 8;
                float v0 = acc[mt][nt][0] + bv_[nt][0];
                float v1 = acc[mt][nt][1] + bv_[nt][1];
                float v2 = acc[mt][nt][2] + bv_[nt][0];
                float v3 = acc[mt][nt][3] + bv_[nt][1];
                *(__half2*)&sT[rl0 * 130 + cl]       = __floats2half2_rn(v0, v1);
                *(__half2*)&sT[(rl0 + 8) * 130 + cl] = __floats2half2_rn(v2, v3);
            }
        }
        __syncthreads();
        for (int idx = tid; idx < 128 * 64; idx += 128) {
            int dl = idx >> 6, kp = idx & 63;
            int tok = m0 + 2 * kp;
            int f = tok / NQ_;
            int key = tok - f * NQ_;
            int gd = n0 + dl;
            int h = gd >> 6, dh = gd & 63;
            __half a = sT[(2 * kp) * 130 + dl];
            __half b = sT[(2 * kp + 1) * 130 + dl];
            size_t oi = (((size_t)(f * 16 + h) * 64 + dh) * NK_ + key) >> 1;
            ((__half2*)O1)[oi] = __halves2half2(a, b);
        }
    }
}

// ---------------------------------------------------------------------------
// Wo GEMM: fp32 out (+bias)
// ---------------------------------------------------------------------------
__global__ void __launch_bounds__(128, 2)
gemm_wo(const __half* __restrict__ Ah, const __half* __restrict__ Bh,
        const float* __restrict__ bias, float* __restrict__ C)
{
    extern __shared__ char dsm[];
    const uint32_t sbase = smem_u32(dsm);

    const int tid  = threadIdx.x;
    const int wid  = tid >> 5;
    const int lane = tid & 31;
    const int m0 = blockIdx.y * 128;
    const int n0 = blockIdx.x * 128;
    const int wm = (wid & 1) * 64;
    const int wn = (wid >> 1) * 64;

    float acc[4][8][4];
    #pragma unroll
    for (int mt = 0; mt < 4; mt++)
        #pragma unroll
        for (int nt = 0; nt < 8; nt++)
            #pragma unroll
            for (int r = 0; r < 4; r++) acc[mt][nt][r] = 0.f;

    int l_tl[8], l_row[8], l_c[8];
    #pragma unroll
    for (int j = 0; j < 8; j++) {
        int i = tid + j * 128;
        l_tl[j]  = i >> 9;
        l_row[j] = (i & 511) >> 2;
        l_c[j]   = i & 3;
    }

    auto issue_load = [&](int ch, int buf) {
        const int k0 = ch * 32;
        #pragma unroll
        for (int j = 0; j < 8; j++) {
            const __half* g = l_tl[j]
                ? Bh + (size_t)(n0 + l_row[j]) * GK + k0 + l_c[j] * 8
                : Ah + (size_t)(m0 + l_row[j]) * GK + k0 + l_c[j] * 8;
            uint32_t s = sbase + buf * STG + l_tl[j] * TILE_B
                       + l_row[j] * 80 + l_c[j] * 16;
            cp16(s, g);
        }
        cp_commit();
    };

    issue_load(0, 0);
    issue_load(1, 1);

    for (int ch = 0; ch < NCH; ch++) {
        if (ch == NCH - 1) cp_wait0(); else cp_wait1();
        __syncthreads();
        if (ch + 2 < NCH) issue_load(ch + 2, (ch + 2) % 3);

        const uint32_t hbase = sbase + (ch % 3) * STG;
        const uint32_t bbase = hbase + TILE_B;

        #pragma unroll
        for (int ks = 0; ks < 2; ks++) {
            uint32_t b[8][2];
            #pragma unroll
            for (int np = 0; np < 4; np++) {
                uint32_t addr = bbase
                    + (wn + np * 16 + (lane & 7) + ((lane >> 4) & 1) * 8) * 80
                    + ((lane >> 3) & 1) * 16 + ks * 32;
                uint32_t r[4];
                ldm_x4(r, addr);
                b[np * 2][0] = r[0];     b[np * 2][1] = r[1];
                b[np * 2 + 1][0] = r[2]; b[np * 2 + 1][1] = r[3];
            }
            uint32_t a[4][4];
            #pragma unroll
            for (int mt = 0; mt < 4; mt++) {
                uint32_t addr = hbase + (wm + mt * 16 + (lane & 15)) * 80
                              + (lane >> 4) * 16 + ks * 32;
                ldm_x4(a[mt], addr);
            }
            #pragma unroll
            for (int mt = 0; mt < 4; mt++)
                #pragma unroll
                for (int nt = 0; nt < 8; nt++)
                    mma_f16(acc[mt][nt], a[mt], b[nt]);
        }
    }

    const int cbase = n0 + wn + (lane & 3) * 2;
    float bv[8][2];
    #pragma unroll
    for (int nt = 0; nt < 8; nt++) {
        bv[nt][0] = bias[cbase + nt * 8];
        bv[nt][1] = bias[cbase + nt * 8 + 1];
    }
    #pragma unroll
    for (int mt = 0; mt < 4; mt++) {
        int r0 = m0 + wm + mt * 16 + (lane >> 2);
        #pragma unroll
        for (int nt = 0; nt < 8; nt++) {
            int c = cbase + nt * 8;
            float2 v0 = { acc[mt][nt][0] + bv[nt][0], acc[mt][nt][1] + bv[nt][1] };
            float2 v1 = { acc[mt][nt][2] + bv[nt][0], acc[mt][nt][3] + bv[nt][1] };
            *(float2*)&C[(size_t)r0 * GN + c]       = v0;
            *(float2*)&C[(size_t)(r0 + 8) * GN + c] = v1;
        }
    }
}

// ---------------------------------------------------------------------------
// HMMA flash attention, cp.async double-buffered, log2-domain softmax,
// ldmatrix B-fragments. smem: 2 x 27648 B.
// ---------------------------------------------------------------------------
#define ASTG 27648
#define ATT_SMEM (2 * ASTG)

__global__ void __launch_bounds__(128)
attn_mma(const __half* __restrict__ Qh,
         const __half* __restrict__ Kr, const __half* __restrict__ Vtr,
         const __nv_bfloat16* __restrict__ E, const float* __restrict__ alpha,
         __half* __restrict__ Yh)
{
    extern __shared__ char sm[];
    const uint32_t sbase = smem_u32(sm);

    const int tid = threadIdx.x;
    const int w = tid >> 5, lane = tid & 31;
    const int c = lane & 3, rg = lane >> 2;
    const int qb = blockIdx.x, fh = blockIdx.y;
    const int f = fh >> 4, h = fh & 15;
    const int tok0 = f * NQ_;
    const int q0 = qb * 64;
    const float alphL = alpha[h] * LOG2E;
    const int rl = 16 * w + rg;

    // stage Q through stage-0 K region, extract resident A fragments
    uint32_t* sQ = (uint32_t*)sm;
    for (int i = tid; i < 512; i += 128) {
        int row = i >> 3, c16 = i & 7;
        size_t go = (size_t)(tok0 + q0 + row) * D_ + h * 64 + c16 * 8;
        *(uint4*)(sQ + row * 36 + c16 * 4) = *(const uint4*)(Qh + go);
    }
    __syncthreads();
    uint32_t qhF[4][4];
    #pragma unroll
    for (int s = 0; s < 4; s++) {
        qhF[s][0] = sQ[rl * 36 + 8 * s + c];
        qhF[s][1] = sQ[(rl + 8) * 36 + 8 * s + c];
        qhF[s][2] = sQ[rl * 36 + 8 * s + c + 4];
        qhF[s][3] = sQ[(rl + 8) * 36 + 8 * s + c + 4];
    }
    __syncthreads();

    // async tile loader: K, V, E into stage buf
    auto issue_tile = [&](int kt, int buf) {
        const int k0 = kt * 64;
        uint32_t kb = sbase + buf * ASTG;
        uint32_t vb = kb + 9216;
        uint32_t eb = kb + 18432;
        for (int i = tid; i < 512; i += 128) {
            int row = i >> 3, c16 = i & 7;
            cp16(kb + row * 144 + c16 * 16,
                 Kr + (size_t)(tok0 + k0 + row) * D_ + h * 64 + c16 * 8);
            cp16(vb + row * 144 + c16 * 16,
                 Vtr + (size_t)fh * (64 * NK_) + (size_t)row * NK_ + k0 + c16 * 8);
            cp16(eb + row * 144 + c16 * 16,
                 E + (size_t)(tok0 + q0 + row) * NK_ + k0 + c16 * 8);
        }
        cp_commit();
    };

    float o[8][4];
    #pragma unroll
    for (int n = 0; n < 8; n++)
        #pragma unroll
        for (int r = 0; r < 4; r++) o[n][r] = 0.f;
    float m0r = -3.0e38f, m1r = -3.0e38f, l0r = 0.f, l1r = 0.f;

    issue_tile(0, 0);

    for (int kt = 0; kt < 9; kt++) {
        if (kt + 1 < 9) issue_tile(kt + 1, (kt + 1) & 1);
        if (kt == 8) cp_wait0(); else cp_wait1();
        __syncthreads();

        const int buf = kt & 1;
        const uint32_t kb = sbase + buf * ASTG;
        const uint32_t vb = kb + 9216;
        __nv_bfloat16* sE = (__nv_bfloat16*)(sm + buf * ASTG + 18432);

        // S = Q K^T (scores already in log2 domain via pre-scaled Q)
        float s[8][4];
        #pragma unroll
        for (int n = 0; n < 8; n++)
            #pragma unroll
            for (int r = 0; r < 4; r++) s[n][r] = 0.f;
        #pragma unroll
        for (int st = 0; st < 4; st++) {
            uint32_t b[8][2];
            #pragma unroll
            for (int np = 0; np < 4; np++) {
                uint32_t addr = kb
                    + (np * 16 + (lane & 7) + ((lane >> 4) & 1) * 8) * 144
                    + ((lane >> 3) & 1) * 16 + st * 32;
                uint32_t r[4];
                ldm_x4(r, addr);
                b[np * 2][0] = r[0];     b[np * 2][1] = r[1];
                b[np * 2 + 1][0] = r[2]; b[np * 2 + 1][1] = r[3];
            }
            #pragma unroll
            for (int n = 0; n < 8; n++)
                mma_f16(s[n], qhF[st], b[n]);
        }

        float mn0 = m0r, mn1 = m1r;
        #pragma unroll
        for (int n = 0; n < 8; n++) {
            float2 e0 = __bfloat1622float2(
                *(__nv_bfloat162*)(sE + rl * 72 + 8 * n + 2 * c));
            float2 e1 = __bfloat1622float2(
                *(__nv_bfloat162*)(sE + (rl + 8) * 72 + 8 * n + 2 * c));
            s[n][0] = (e0.x < 0.f) ? NEGBIG : fmaf(alphL, e0.x, s[n][0]);
            s[n][1] = (e0.y < 0.f) ? NEGBIG : fmaf(alphL, e0.y, s[n][1]);
            s[n][2] = (e1.x < 0.f) ? NEGBIG : fmaf(alphL, e1.x, s[n][2]);
            s[n][3] = (e1.y < 0.f) ? NEGBIG : fmaf(alphL, e1.y, s[n][3]);
            mn0 = fmaxf(mn0, fmaxf(s[n][0], s[n][1]));
            mn1 = fmaxf(mn1, fmaxf(s[n][2], s[n][3]));
        }
        mn0 = fmaxf(mn0, __shfl_xor_sync(0xffffffffu, mn0, 1));
        mn0 = fmaxf(mn0, __shfl_xor_sync(0xffffffffu, mn0, 2));
        mn1 = fmaxf(mn1, __shfl_xor_sync(0xffffffffu, mn1, 1));
        mn1 = fmaxf(mn1, __shfl_xor_sync(0xffffffffu, mn1, 2));
        float f0 = ex2(m0r - mn0);
        float f1 = ex2(m1r - mn1);
        m0r = mn0; m1r = mn1;

        float rs0 = 0.f, rs1 = 0.f;
        uint32_t phL[8], phH[8];
        #pragma unroll
        for (int n = 0; n < 8; n++) {
            float p0 = ex2(s[n][0] - mn0);
            float p1 = ex2(s[n][1] - mn0);
            float p2 = ex2(s[n][2] - mn1);
            float p3 = ex2(s[n][3] - mn1);
            rs0 += p0 + p1;
            rs1 += p2 + p3;
            o[n][0] *= f0; o[n][1] *= f0; o[n][2] *= f1; o[n][3] *= f1;
            __half2 bL = __floats2half2_rn(p0, p1);
            phL[n] = *(uint32_t*)&bL;
            __half2 bH = __floats2half2_rn(p2, p3);
            phH[n] = *(uint32_t*)&bH;
        }
        rs0 += __shfl_xor_sync(0xffffffffu, rs0, 1);
        rs0 += __shfl_xor_sync(0xffffffffu, rs0, 2);
        rs1 += __shfl_xor_sync(0xffffffffu, rs1, 1);
        rs1 += __shfl_xor_sync(0xffffffffu, rs1, 2);
        l0r = l0r * f0 + rs0;
        l1r = l1r * f1 + rs1;

        // O += P V
        #pragma unroll
        for (int st = 0; st < 4; st++) {
            uint32_t ah[4] = { phL[2 * st], phH[2 * st], phL[2 * st + 1], phH[2 * st + 1] };
            uint32_t b[8][2];
            #pragma unroll
            for (int np = 0; np < 4; np++) {
                uint32_t addr = vb
                    + (np * 16 + (lane & 7) + ((lane >> 4) & 1) * 8) * 144
                    + ((lane >> 3) & 1) * 16 + st * 32;
                uint32_t r[4];
                ldm_x4(r, addr);
                b[np * 2][0] = r[0];     b[np * 2][1] = r[1];
                b[np * 2 + 1][0] = r[2]; b[np * 2 + 1][1] = r[3];
            }
            #pragma unroll
            for (int n = 0; n < 8; n++)
                mma_f16(o[n], ah, b[n]);
        }
        __syncthreads();
    }

    float i0 = 1.f / l0r, i1 = 1.f / l1r;
    #pragma unroll
    for (int n = 0; n < 8; n++) {
        size_t e0 = ((size_t)(tok0 + q0 + rl) * D_ + h * 64 + 8 * n + 2 * c) >> 1;
        size_t e1 = ((size_t)(tok0 + q0 + rl + 8) * D_ + h * 64 + 8 * n + 2 * c) >> 1;
        ((__half2*)Yh)[e0] = __floats2half2_rn(o[n][0] * i0, o[n][1] * i0);
        ((__half2*)Yh)[e1] = __floats2half2_rn(o[n][2] * i1, o[n][3] * i1);
    }
}

// ---------------------------------------------------------------------------
extern "C" void kernel_launch(void* const* d_in, const int* in_sizes, int n_in,
                              void* d_out, int out_size)
{
    (void)in_sizes; (void)n_in; (void)out_size;

    const float*   q_tokens  = (const float*)d_in[0];
    const float*   kv_tokens = (const float*)d_in[1];
    const float*   coords_q  = (const float*)d_in[2];
    const float*   coords_k  = (const float*)d_in[3];
    const void*    q_pad     = d_in[4];
    const void*    kv_pad    = d_in[5];
    const float*   Wq = (const float*)d_in[6];
    const float*   bq = (const float*)d_in[7];
    const float*   Wk = (const float*)d_in[8];
    const float*   bk = (const float*)d_in[9];
    const float*   Wv = (const float*)d_in[10];
    const float*   bv = (const float*)d_in[11];
    const float*   Wo = (const float*)d_in[12];
    const float*   bo = (const float*)d_in[13];
    const float*   alpha = (const float*)d_in[14];
    const float*   f0 = (const float*)d_in[15];
    const float*   f1 = (const float*)d_in[16];
    const float*   f2 = (const float*)d_in[17];
    float* out = (float*)d_out;

    __nv_bfloat16 *Eb;
    float2 *rtq, *rtk;
    cudaGetSymbolAddress((void**)&Eb, g_E);
    cudaGetSymbolAddress((void**)&rtq, g_rt);
    rtk = rtq + TOK * 32;

    __half *x16q, *x16kv, *yhi, *W16, *aQh, *aKr, *vtr;
    cudaGetSymbolAddress((void**)&x16q, g_x16);
    x16kv = x16q + TOK * D_;
    cudaGetSymbolAddress((void**)&yhi,  g_yhi);
    cudaGetSymbolAddress((void**)&W16, g_W16);
    cudaGetSymbolAddress((void**)&aQh, g_aQh);
    cudaGetSymbolAddress((void**)&aKr, g_aKr);
    cudaGetSymbolAddress((void**)&vtr, g_vtr);
    __half *Wqh = W16, *Wkh = W16 + D_ * D_, *Wvh = W16 + 2 * D_ * D_,
           *Woh = W16 + 3 * D_ * D_;

    const int gemm_smem = 3 * STG;  // 61440
    cudaFuncSetAttribute(gemm_qkv, cudaFuncAttributeMaxDynamicSharedMemorySize, gemm_smem);
    cudaFuncSetAttribute(gemm_wo,  cudaFuncAttributeMaxDynamicSharedMemorySize, gemm_smem);
    cudaFuncSetAttribute(attn_mma, cudaFuncAttributeMaxDynamicSharedMemorySize, ATT_SMEM);

    // masks + pointer tables
    detect_mask_kernel<<<1, 256>>>((const unsigned*)q_pad, (const unsigned*)kv_pad,
                                   TOK / 4, Wq, Wk, Wv, Wo, q_tokens, kv_tokens);

    // mega prep: weight/act rounding + rope tables + bias, one launch
    prep_kernel<<<PREP_BLOCKS, 256>>>(coords_q, coords_k, f0, f1, f2,
                                      rtq, rtk, q_pad, kv_pad, Eb);

    // merged Q/K/V projection (one launch, 864 CTAs)
    gemm_qkv<<<dim3(GN / 128, TOK / 128, 3), 128, gemm_smem>>>(
        x16q, x16kv, Wqh, Wkh, Wvh, bq, bk, bv, aQh, aKr, vtr, rtq, rtk);

    attn_mma<<<dim3(9, 128), 128, ATT_SMEM>>>(aQh, aKr, vtr, Eb, alpha, yhi);

    gemm_wo<<<dim3(GN / 128, TOK / 128), 128, gemm_smem>>>(yhi, Woh, bo, out);
}